// round 1
// baseline (speedup 1.0000x reference)
#include <cuda_runtime.h>

#define N_NODES 500000
#define N_EDGES 1000000
#define EMB 64
#define FDIM 128
#define LDIM 8
#define OPC 5000
#define IN_DIM (3*EMB + LDIM)   // 200

// ---- scratch (no allocations allowed) ----
__device__ float  g_z  [(size_t)N_NODES * FDIM];   // 256 MB
__device__ float  g_agg[(size_t)N_NODES * FDIM];   // 256 MB
__device__ double g_kl_sum;
__device__ double g_lat_sum;

// ----------------------------------------------------------------------------
// Kernel 0: zero agg scratch, output buffer head, scalar accumulators
// ----------------------------------------------------------------------------
__global__ void zero_kernel(float* __restrict__ out)
{
    size_t i = (size_t)blockIdx.x * blockDim.x + threadIdx.x;
    const size_t tot4 = (size_t)N_NODES * FDIM / 4;   // 16,000,000 float4
    if (i < tot4) ((float4*)g_agg)[i] = make_float4(0.f, 0.f, 0.f, 0.f);
    if (i < (size_t)(1 + 2*OPC)) out[i] = 0.f;
    if (i == 0) { g_kl_sum = 0.0; g_lat_sum = 0.0; }
}

// ----------------------------------------------------------------------------
// Kernel 1: encoder. One warp per node. Lane owns 4 consecutive columns.
// feats(200) -> relu GEMM1(200x128) -> GEMM2(128x256) -> z, KL partials.
// ----------------------------------------------------------------------------
__global__ void enc_kernel(const int*   __restrict__ op_id,
                           const int*   __restrict__ sv_id,
                           const int*   __restrict__ st_id,
                           const float* __restrict__ lat,
                           const float* __restrict__ eps,
                           const float* __restrict__ opE,
                           const float* __restrict__ svE,
                           const float* __restrict__ stE,
                           const float* __restrict__ W1,
                           const float* __restrict__ b1,
                           const float* __restrict__ W2,
                           const float* __restrict__ b2)
{
    const int w    = threadIdx.x >> 5;
    const int lane = threadIdx.x & 31;
    const int n    = blockIdx.x * 8 + w;

    __shared__ __align__(16) float sfeat[8][IN_DIM];
    __shared__ __align__(16) float sh[8][FDIM];
    __shared__ float sKL[8];

    float klw = 0.f;

    if (n < N_NODES) {
        const int op = op_id[n], sv = sv_id[n], st = st_id[n];

        // gather feats = [opE | svE | stE | latency]
        for (int i = lane; i < EMB; i += 32) {
            sfeat[w][i]         = __ldg(opE + (size_t)op * EMB + i);
            sfeat[w][EMB + i]   = __ldg(svE + (size_t)sv * EMB + i);
            sfeat[w][2*EMB + i] = __ldg(stE + (size_t)st * EMB + i);
        }
        if (lane < LDIM) sfeat[w][3*EMB + lane] = __ldg(lat + (size_t)n * LDIM + lane);
        __syncwarp();

        // GEMM1: h = relu(feats @ W1 + b1), lane -> cols [4*lane, 4*lane+3]
        float4 acc = *(const float4*)(b1 + 4*lane);
        #pragma unroll 4
        for (int i = 0; i < IN_DIM; i++) {
            const float f  = sfeat[w][i];
            const float4 wv = __ldg((const float4*)(W1 + (size_t)i * FDIM + 4*lane));
            acc.x += f * wv.x; acc.y += f * wv.y; acc.z += f * wv.z; acc.w += f * wv.w;
        }
        acc.x = fmaxf(acc.x, 0.f); acc.y = fmaxf(acc.y, 0.f);
        acc.z = fmaxf(acc.z, 0.f); acc.w = fmaxf(acc.w, 0.f);
        *(float4*)&sh[w][4*lane] = acc;
        __syncwarp();

        // GEMM2: y = h @ W2 + b2 ; lane's mu cols = lv cols = [4*lane..4*lane+3]
        float4 am = *(const float4*)(b2 + 4*lane);
        float4 al = *(const float4*)(b2 + FDIM + 4*lane);
        #pragma unroll 4
        for (int i = 0; i < FDIM; i++) {
            const float h = sh[w][i];
            const float4 wm = __ldg((const float4*)(W2 + (size_t)i * 2*FDIM + 4*lane));
            const float4 wl = __ldg((const float4*)(W2 + (size_t)i * 2*FDIM + FDIM + 4*lane));
            am.x += h * wm.x; am.y += h * wm.y; am.z += h * wm.z; am.w += h * wm.w;
            al.x += h * wl.x; al.y += h * wl.y; al.z += h * wl.z; al.w += h * wl.w;
        }
        al.x = tanhf(al.x); al.y = tanhf(al.y); al.z = tanhf(al.z); al.w = tanhf(al.w);

        const float4 e4 = __ldg((const float4*)(eps + (size_t)n * FDIM + 4*lane));
        float4 z;
        z.x = am.x + expf(0.5f * al.x) * e4.x;
        z.y = am.y + expf(0.5f * al.y) * e4.y;
        z.z = am.z + expf(0.5f * al.z) * e4.z;
        z.w = am.w + expf(0.5f * al.w) * e4.w;
        ((float4*)g_z)[(size_t)n * 32 + lane] = z;

        // KL term: z_lv + 1 - exp(z_lv) - z_mu^2
        klw  = (al.x + 1.f - expf(al.x) - am.x * am.x);
        klw += (al.y + 1.f - expf(al.y) - am.y * am.y);
        klw += (al.z + 1.f - expf(al.z) - am.z * am.z);
        klw += (al.w + 1.f - expf(al.w) - am.w * am.w);
    }

    #pragma unroll
    for (int o = 16; o; o >>= 1) klw += __shfl_xor_sync(0xffffffffu, klw, o);
    if (lane == 0) sKL[w] = klw;
    __syncthreads();
    if (threadIdx.x == 0) {
        double s = 0.0;
        #pragma unroll
        for (int i = 0; i < 8; i++) s += (double)sKL[i];
        atomicAdd(&g_kl_sum, s);
    }
}

// ----------------------------------------------------------------------------
// Kernel 2: edge scatter-add. One warp per edge, one v4 reduction per lane.
// ----------------------------------------------------------------------------
__global__ void scatter_kernel(const int* __restrict__ esrc,
                               const int* __restrict__ edst)
{
    const int e    = (blockIdx.x * blockDim.x + threadIdx.x) >> 5;
    const int lane = threadIdx.x & 31;
    if (e >= N_EDGES) return;
    const int s = __ldg(esrc + e);
    const int d = __ldg(edst + e);
    const float4 v = ((const float4*)g_z)[(size_t)s * 32 + lane];
    float* p = &g_agg[(size_t)d * FDIM + 4*lane];
    asm volatile("red.global.add.v4.f32 [%0], {%1, %2, %3, %4};"
                 :: "l"(p), "f"(v.x), "f"(v.y), "f"(v.z), "f"(v.w) : "memory");
}

// ----------------------------------------------------------------------------
// Kernel 3: decoder + heads + per-op einsum + loss + segment sums.
// One warp per node.
// ----------------------------------------------------------------------------
__global__ void dec_kernel(const int*   __restrict__ op_id,
                           const float* __restrict__ lat,
                           const float* __restrict__ Wself,
                           const float* __restrict__ Wagg,
                           const float* __restrict__ muW,
                           const float* __restrict__ mub,
                           const float* __restrict__ lvW,
                           const float* __restrict__ lvb,
                           const float* __restrict__ opw,
                           float* __restrict__ op_loss,
                           float* __restrict__ op_cnt)
{
    const int w    = threadIdx.x >> 5;
    const int lane = threadIdx.x & 31;
    const int n    = blockIdx.x * 8 + w;

    __shared__ __align__(16) float zb[8][FDIM];
    __shared__ __align__(16) float ab[8][FDIM];
    __shared__ float sL[8];

    float lossn = 0.f;

    if (n < N_NODES) {
        *(float4*)&zb[w][4*lane] = ((const float4*)g_z)  [(size_t)n * 32 + lane];
        *(float4*)&ab[w][4*lane] = ((const float4*)g_agg)[(size_t)n * 32 + lane];
        __syncwarp();

        // yd = relu(z@Wself + agg@Wagg); lane owns yd[4*lane .. 4*lane+3]
        float4 acc = make_float4(0.f, 0.f, 0.f, 0.f);
        #pragma unroll 4
        for (int i = 0; i < FDIM; i++) {
            const float zi = zb[w][i];
            const float ai = ab[w][i];
            const float4 ws = __ldg((const float4*)(Wself + (size_t)i * FDIM + 4*lane));
            const float4 wa = __ldg((const float4*)(Wagg  + (size_t)i * FDIM + 4*lane));
            acc.x += zi * ws.x + ai * wa.x;
            acc.y += zi * ws.y + ai * wa.y;
            acc.z += zi * ws.z + ai * wa.z;
            acc.w += zi * ws.w + ai * wa.w;
        }
        float yd[4];
        yd[0] = fmaxf(acc.x, 0.f); yd[1] = fmaxf(acc.y, 0.f);
        yd[2] = fmaxf(acc.z, 0.f); yd[3] = fmaxf(acc.w, 0.f);

        // heads: mu[l] = sum_i yd[i]*muW[i,l] (+bias). Per-lane partial over its 4 rows.
        float mu[LDIM], lv[LDIM];
        #pragma unroll
        for (int l = 0; l < LDIM; l++) { mu[l] = 0.f; lv[l] = 0.f; }
        #pragma unroll
        for (int c = 0; c < 4; c++) {
            const float* mr = muW + (size_t)(4*lane + c) * LDIM;
            const float* lr = lvW + (size_t)(4*lane + c) * LDIM;
            #pragma unroll
            for (int l = 0; l < LDIM; l++) {
                mu[l] += yd[c] * __ldg(mr + l);
                lv[l] += yd[c] * __ldg(lr + l);
            }
        }
        #pragma unroll
        for (int l = 0; l < LDIM; l++) {
            #pragma unroll
            for (int o = 16; o; o >>= 1) {
                mu[l] += __shfl_xor_sync(0xffffffffu, mu[l], o);
                lv[l] += __shfl_xor_sync(0xffffffffu, lv[l], o);
            }
            mu[l] += __ldg(mub + l);
            lv[l] += __ldg(lvb + l);
        }

        // per-op einsum + Gaussian NLL; lanes 0..7 handle k = lane
        const int op = __ldg(op_id + n);
        float lk = 0.f;
        if (lane < LDIM) {
            const float* wrow = opw + (size_t)op * (2 * LDIM * LDIM);
            float mp = 0.f, lp = 0.f;
            #pragma unroll
            for (int l = 0; l < LDIM; l++) {
                mp += mu[l] * __ldg(wrow + l * 2 * LDIM + lane);
                lp += lv[l] * __ldg(wrow + l * 2 * LDIM + LDIM + lane);
            }
            const float label = __ldg(lat + (size_t)n * LDIM + lane);
            const float d = mp - label;
            lk = d * d / (2.f * expf(lp) + 1e-7f) + 0.5f * lp;
        }
        #pragma unroll
        for (int o = 16; o; o >>= 1) lk += __shfl_xor_sync(0xffffffffu, lk, o);
        lossn = lk * (1.f / LDIM);

        if (lane == 0) {
            atomicAdd(op_loss + op, lossn);
            atomicAdd(op_cnt  + op, 1.f);
        }
    }

    if (lane == 0) sL[w] = (n < N_NODES) ? lossn : 0.f;
    __syncthreads();
    if (threadIdx.x == 0) {
        double s = 0.0;
        #pragma unroll
        for (int i = 0; i < 8; i++) s += (double)sL[i];
        atomicAdd(&g_lat_sum, s);
    }
}

// ----------------------------------------------------------------------------
// Kernel 4: finalize scalar output
// ----------------------------------------------------------------------------
__global__ void fin_kernel(float* __restrict__ out)
{
    if (threadIdx.x == 0) {
        const double lat_loss = g_lat_sum / (double)N_NODES;
        const double kl = -0.5 * (g_kl_sum / ((double)N_NODES * (double)FDIM));
        out[0] = (float)(lat_loss + kl);
    }
}

// ----------------------------------------------------------------------------
extern "C" void kernel_launch(void* const* d_in, const int* in_sizes, int n_in,
                              void* d_out, int out_size)
{
    const int*   op_id = (const int*)  d_in[0];
    const int*   sv_id = (const int*)  d_in[1];
    const int*   st_id = (const int*)  d_in[2];
    const float* lat   = (const float*)d_in[3];
    const int*   esrc  = (const int*)  d_in[4];
    const int*   edst  = (const int*)  d_in[5];
    const float* eps   = (const float*)d_in[6];
    const float* opE   = (const float*)d_in[7];
    const float* svE   = (const float*)d_in[8];
    const float* stE   = (const float*)d_in[9];
    const float* W1    = (const float*)d_in[10];
    const float* b1    = (const float*)d_in[11];
    const float* W2    = (const float*)d_in[12];
    const float* b2    = (const float*)d_in[13];
    const float* Wself = (const float*)d_in[14];
    const float* Wagg  = (const float*)d_in[15];
    const float* muW   = (const float*)d_in[16];
    const float* mub   = (const float*)d_in[17];
    const float* lvW   = (const float*)d_in[18];
    const float* lvb   = (const float*)d_in[19];
    const float* opw   = (const float*)d_in[20];

    float* out     = (float*)d_out;
    float* op_loss = out + 1;
    float* op_cnt  = out + 1 + OPC;

    // 16M float4 zeroing -> exactly 62500 blocks of 256
    zero_kernel<<<62500, 256>>>(out);

    enc_kernel<<<(N_NODES + 7) / 8, 256>>>(op_id, sv_id, st_id, lat, eps,
                                           opE, svE, stE, W1, b1, W2, b2);

    scatter_kernel<<<(N_EDGES + 7) / 8, 256>>>(esrc, edst);

    dec_kernel<<<(N_NODES + 7) / 8, 256>>>(op_id, lat, Wself, Wagg,
                                           muW, mub, lvW, lvb, opw,
                                           op_loss, op_cnt);

    fin_kernel<<<1, 32>>>(out);
}

// round 2
// speedup vs baseline: 2.6735x; 2.6735x over previous
#include <cuda_runtime.h>

#define N_NODES 500000
#define N_EDGES 1000000
#define EMB 64
#define FDIM 128
#define LDIM 8
#define OPC 5000
#define IN_DIM (3*EMB + LDIM)   // 200

#define TILE 64                  // nodes per block
#define SF   68                  // padded row stride (floats) for transposed smem
#define YDS  132                 // padded row stride for yd row-major

// ---- scratch (no allocations allowed) ----
__device__ float  g_z  [(size_t)N_NODES * FDIM];   // 256 MB
__device__ float  g_agg[(size_t)N_NODES * FDIM];   // 256 MB
__device__ double g_kl_sum;
__device__ double g_lat_sum;

// ---- packed f32x2 helpers (sm_103a FFMA2) ----
__device__ __forceinline__ unsigned long long pk2(float a, float b) {
    unsigned long long r;
    asm("mov.b64 %0, {%1, %2};" : "=l"(r) : "f"(a), "f"(b));
    return r;
}
__device__ __forceinline__ float2 up2(unsigned long long v) {
    float2 r;
    asm("mov.b64 {%0, %1}, %2;" : "=f"(r.x), "=f"(r.y) : "l"(v));
    return r;
}
__device__ __forceinline__ void fma2(unsigned long long& d,
                                     unsigned long long a,
                                     unsigned long long b) {
    asm("fma.rn.f32x2 %0, %1, %2, %0;" : "+l"(d) : "l"(a), "l"(b));
}

// ----------------------------------------------------------------------------
// Kernel 0: zero agg scratch, output head, scalar accumulators
// ----------------------------------------------------------------------------
__global__ void zero_kernel(float* __restrict__ out)
{
    size_t i = (size_t)blockIdx.x * blockDim.x + threadIdx.x;
    const size_t tot4 = (size_t)N_NODES * FDIM / 4;
    if (i < tot4) ((float4*)g_agg)[i] = make_float4(0.f, 0.f, 0.f, 0.f);
    if (i < (size_t)(1 + 2*OPC)) out[i] = 0.f;
    if (i == 0) { g_kl_sum = 0.0; g_lat_sum = 0.0; }
}

// ----------------------------------------------------------------------------
// Kernel 1: encoder, 64-node tile per block, 256 threads.
//   sfeatT[k][r] (k=0..199), hT[k][r] (k=0..127) in dynamic smem.
//   Thread (ty=warp, tx=lane): rows ty*8..ty*8+7 (as 4 row-pairs), cols 4tx..4tx+3.
// ----------------------------------------------------------------------------
extern "C" __global__ void __launch_bounds__(256, 2)
enc_kernel(const int*   __restrict__ op_id,
           const int*   __restrict__ sv_id,
           const int*   __restrict__ st_id,
           const float* __restrict__ lat,
           const float* __restrict__ eps,
           const float* __restrict__ opE,
           const float* __restrict__ svE,
           const float* __restrict__ stE,
           const float* __restrict__ W1,
           const float* __restrict__ b1,
           const float* __restrict__ W2,
           const float* __restrict__ b2)
{
    extern __shared__ float sm[];
    float* sfeatT = sm;               // [200][SF]
    float* hT     = sm + 200 * SF;    // [128][SF]
    __shared__ float skl[8];

    const int tid  = threadIdx.x;
    const int lane = tid & 31;
    const int wid  = tid >> 5;
    const int base = blockIdx.x * TILE;

    // ---- gather feats transposed: sfeatT[k][r] ----
    #pragma unroll
    for (int i = 0; i < 8; i++) {
        const int r = wid * 8 + i;
        const int n = base + r;
        if (n < N_NODES) {
            const int op = op_id[n], sv = sv_id[n], st = st_id[n];
            sfeatT[(lane      ) * SF + r] = __ldg(opE + (size_t)op * EMB + lane);
            sfeatT[(lane +  32) * SF + r] = __ldg(opE + (size_t)op * EMB + 32 + lane);
            sfeatT[(lane +  64) * SF + r] = __ldg(svE + (size_t)sv * EMB + lane);
            sfeatT[(lane +  96) * SF + r] = __ldg(svE + (size_t)sv * EMB + 32 + lane);
            sfeatT[(lane + 128) * SF + r] = __ldg(stE + (size_t)st * EMB + lane);
            sfeatT[(lane + 160) * SF + r] = __ldg(stE + (size_t)st * EMB + 32 + lane);
            if (lane < LDIM)
                sfeatT[(lane + 192) * SF + r] = __ldg(lat + (size_t)n * LDIM + lane);
        }
    }
    __syncthreads();

    const int tx = lane, ty = wid;

    // ---- GEMM1: h = relu(feats @ W1 + b1) ----
    {
        unsigned long long acc[4][4];
        const float4 bb = __ldg((const float4*)(b1 + 4*tx));
        #pragma unroll
        for (int p = 0; p < 4; p++) {
            acc[p][0] = pk2(bb.x, bb.x); acc[p][1] = pk2(bb.y, bb.y);
            acc[p][2] = pk2(bb.z, bb.z); acc[p][3] = pk2(bb.w, bb.w);
        }
        #pragma unroll 4
        for (int k = 0; k < IN_DIM; k++) {
            const float4 w = __ldg((const float4*)(W1 + (size_t)k * FDIM + 4*tx));
            const unsigned long long w0 = pk2(w.x, w.x), w1 = pk2(w.y, w.y),
                                     w2 = pk2(w.z, w.z), w3 = pk2(w.w, w.w);
            const ulonglong2* fp = (const ulonglong2*)(sfeatT + k * SF + ty * 8);
            const ulonglong2 fA = fp[0], fB = fp[1];
            fma2(acc[0][0], fA.x, w0); fma2(acc[0][1], fA.x, w1);
            fma2(acc[0][2], fA.x, w2); fma2(acc[0][3], fA.x, w3);
            fma2(acc[1][0], fA.y, w0); fma2(acc[1][1], fA.y, w1);
            fma2(acc[1][2], fA.y, w2); fma2(acc[1][3], fA.y, w3);
            fma2(acc[2][0], fB.x, w0); fma2(acc[2][1], fB.x, w1);
            fma2(acc[2][2], fB.x, w2); fma2(acc[2][3], fB.x, w3);
            fma2(acc[3][0], fB.y, w0); fma2(acc[3][1], fB.y, w1);
            fma2(acc[3][2], fB.y, w2); fma2(acc[3][3], fB.y, w3);
        }
        // relu + store transposed into hT[c][r]
        #pragma unroll
        for (int j = 0; j < 4; j++) {
            const float2 a0 = up2(acc[0][j]), a1 = up2(acc[1][j]);
            const float2 a2 = up2(acc[2][j]), a3 = up2(acc[3][j]);
            float4 o0 = make_float4(fmaxf(a0.x,0.f), fmaxf(a0.y,0.f),
                                    fmaxf(a1.x,0.f), fmaxf(a1.y,0.f));
            float4 o1 = make_float4(fmaxf(a2.x,0.f), fmaxf(a2.y,0.f),
                                    fmaxf(a3.x,0.f), fmaxf(a3.y,0.f));
            *(float4*)(hT + (4*tx + j) * SF + ty*8)     = o0;
            *(float4*)(hT + (4*tx + j) * SF + ty*8 + 4) = o1;
        }
    }
    __syncthreads();

    // ---- GEMM2: y = h @ W2 + b2 ; mu cols 4tx.., lv cols 128+4tx.. ----
    unsigned long long accm[4][4], accl[4][4];
    {
        const float4 bm = __ldg((const float4*)(b2 + 4*tx));
        const float4 bl = __ldg((const float4*)(b2 + FDIM + 4*tx));
        #pragma unroll
        for (int p = 0; p < 4; p++) {
            accm[p][0] = pk2(bm.x, bm.x); accm[p][1] = pk2(bm.y, bm.y);
            accm[p][2] = pk2(bm.z, bm.z); accm[p][3] = pk2(bm.w, bm.w);
            accl[p][0] = pk2(bl.x, bl.x); accl[p][1] = pk2(bl.y, bl.y);
            accl[p][2] = pk2(bl.z, bl.z); accl[p][3] = pk2(bl.w, bl.w);
        }
        #pragma unroll 2
        for (int k = 0; k < FDIM; k++) {
            const float4 wm = __ldg((const float4*)(W2 + (size_t)k * 2*FDIM + 4*tx));
            const float4 wl = __ldg((const float4*)(W2 + (size_t)k * 2*FDIM + FDIM + 4*tx));
            const unsigned long long m0 = pk2(wm.x, wm.x), m1 = pk2(wm.y, wm.y),
                                     m2 = pk2(wm.z, wm.z), m3 = pk2(wm.w, wm.w);
            const unsigned long long l0 = pk2(wl.x, wl.x), l1 = pk2(wl.y, wl.y),
                                     l2 = pk2(wl.z, wl.z), l3 = pk2(wl.w, wl.w);
            const ulonglong2* fp = (const ulonglong2*)(hT + k * SF + ty * 8);
            const ulonglong2 fA = fp[0], fB = fp[1];
            fma2(accm[0][0], fA.x, m0); fma2(accm[0][1], fA.x, m1);
            fma2(accm[0][2], fA.x, m2); fma2(accm[0][3], fA.x, m3);
            fma2(accl[0][0], fA.x, l0); fma2(accl[0][1], fA.x, l1);
            fma2(accl[0][2], fA.x, l2); fma2(accl[0][3], fA.x, l3);
            fma2(accm[1][0], fA.y, m0); fma2(accm[1][1], fA.y, m1);
            fma2(accm[1][2], fA.y, m2); fma2(accm[1][3], fA.y, m3);
            fma2(accl[1][0], fA.y, l0); fma2(accl[1][1], fA.y, l1);
            fma2(accl[1][2], fA.y, l2); fma2(accl[1][3], fA.y, l3);
            fma2(accm[2][0], fB.x, m0); fma2(accm[2][1], fB.x, m1);
            fma2(accm[2][2], fB.x, m2); fma2(accm[2][3], fB.x, m3);
            fma2(accl[2][0], fB.x, l0); fma2(accl[2][1], fB.x, l1);
            fma2(accl[2][2], fB.x, l2); fma2(accl[2][3], fB.x, l3);
            fma2(accm[3][0], fB.y, m0); fma2(accm[3][1], fB.y, m1);
            fma2(accm[3][2], fB.y, m2); fma2(accm[3][3], fB.y, m3);
            fma2(accl[3][0], fB.y, l0); fma2(accl[3][1], fB.y, l1);
            fma2(accl[3][2], fB.y, l2); fma2(accl[3][3], fB.y, l3);
        }
    }

    // ---- epilogue: z = mu + exp(0.5*tanh(lv))*eps, KL partials ----
    float klw = 0.f;
    #pragma unroll
    for (int p = 0; p < 4; p++) {
        const float2 m0 = up2(accm[p][0]), m1 = up2(accm[p][1]),
                     m2 = up2(accm[p][2]), m3 = up2(accm[p][3]);
        const float2 l0 = up2(accl[p][0]), l1 = up2(accl[p][1]),
                     l2 = up2(accl[p][2]), l3 = up2(accl[p][3]);
        #pragma unroll
        for (int s = 0; s < 2; s++) {
            const int r = ty*8 + 2*p + s;
            const int n = base + r;
            if (n >= N_NODES) continue;
            float4 mu4 = s ? make_float4(m0.y, m1.y, m2.y, m3.y)
                           : make_float4(m0.x, m1.x, m2.x, m3.x);
            float4 lv4 = s ? make_float4(l0.y, l1.y, l2.y, l3.y)
                           : make_float4(l0.x, l1.x, l2.x, l3.x);
            lv4.x = tanhf(lv4.x); lv4.y = tanhf(lv4.y);
            lv4.z = tanhf(lv4.z); lv4.w = tanhf(lv4.w);
            const float4 e = __ldg((const float4*)(eps + (size_t)n * FDIM + 4*tx));
            float4 z;
            z.x = mu4.x + expf(0.5f*lv4.x) * e.x;
            z.y = mu4.y + expf(0.5f*lv4.y) * e.y;
            z.z = mu4.z + expf(0.5f*lv4.z) * e.z;
            z.w = mu4.w + expf(0.5f*lv4.w) * e.w;
            ((float4*)g_z)[(size_t)n * 32 + tx] = z;
            klw += (lv4.x + 1.f - expf(lv4.x) - mu4.x*mu4.x);
            klw += (lv4.y + 1.f - expf(lv4.y) - mu4.y*mu4.y);
            klw += (lv4.z + 1.f - expf(lv4.z) - mu4.z*mu4.z);
            klw += (lv4.w + 1.f - expf(lv4.w) - mu4.w*mu4.w);
        }
    }
    #pragma unroll
    for (int o = 16; o; o >>= 1) klw += __shfl_xor_sync(0xffffffffu, klw, o);
    if (lane == 0) skl[wid] = klw;
    __syncthreads();
    if (tid == 0) {
        double s = 0.0;
        #pragma unroll
        for (int i = 0; i < 8; i++) s += (double)skl[i];
        atomicAdd(&g_kl_sum, s);
    }
}

// ----------------------------------------------------------------------------
// Kernel 2: edge scatter-add (unchanged: warp/edge, v4 global reduction)
// ----------------------------------------------------------------------------
__global__ void scatter_kernel(const int* __restrict__ esrc,
                               const int* __restrict__ edst)
{
    const int e    = (blockIdx.x * blockDim.x + threadIdx.x) >> 5;
    const int lane = threadIdx.x & 31;
    if (e >= N_EDGES) return;
    const int s = __ldg(esrc + e);
    const int d = __ldg(edst + e);
    const float4 v = ((const float4*)g_z)[(size_t)s * 32 + lane];
    float* p = &g_agg[(size_t)d * FDIM + 4*lane];
    asm volatile("red.global.add.v4.f32 [%0], {%1, %2, %3, %4};"
                 :: "l"(p), "f"(v.x), "f"(v.y), "f"(v.z), "f"(v.w) : "memory");
}

// ----------------------------------------------------------------------------
// Kernel 3: decoder tile GEMM + heads + per-op einsum + loss
// ----------------------------------------------------------------------------
extern "C" __global__ void __launch_bounds__(256, 2)
dec_kernel(const int*   __restrict__ op_id,
           const float* __restrict__ lat,
           const float* __restrict__ Wself,
           const float* __restrict__ Wagg,
           const float* __restrict__ muW,
           const float* __restrict__ mub,
           const float* __restrict__ lvW,
           const float* __restrict__ lvb,
           const float* __restrict__ opw,
           float* __restrict__ op_loss,
           float* __restrict__ op_cnt)
{
    extern __shared__ float sm[];
    float* sdecT = sm;                // [256][SF] : k<128 = z, k>=128 = agg
    float* ydrow = sm + 256 * SF;     // [64][YDS]
    __shared__ float sL[8];

    const int tid  = threadIdx.x;
    const int lane = tid & 31;
    const int wid  = tid >> 5;
    const int base = blockIdx.x * TILE;

    // ---- gather z/agg transposed ----
    #pragma unroll
    for (int i = 0; i < 8; i++) {
        const int r = wid * 8 + i;
        const int n = base + r;
        if (n < N_NODES) {
            const float* zp = g_z   + (size_t)n * FDIM;
            const float* ap = g_agg + (size_t)n * FDIM;
            #pragma unroll
            for (int q = 0; q < 4; q++) {
                const int k = lane + 32*q;
                sdecT[ k        * SF + r] = __ldg(zp + k);
                sdecT[(k + 128) * SF + r] = __ldg(ap + k);
            }
        }
    }
    __syncthreads();

    const int tx = lane, ty = wid;

    // ---- GEMM: yd = relu(z@Wself + agg@Wagg) ----
    {
        unsigned long long acc[4][4];
        #pragma unroll
        for (int p = 0; p < 4; p++)
            #pragma unroll
            for (int j = 0; j < 4; j++) acc[p][j] = 0ull;

        #pragma unroll 4
        for (int k = 0; k < FDIM; k++) {
            const float4 w = __ldg((const float4*)(Wself + (size_t)k * FDIM + 4*tx));
            const unsigned long long w0 = pk2(w.x, w.x), w1 = pk2(w.y, w.y),
                                     w2 = pk2(w.z, w.z), w3 = pk2(w.w, w.w);
            const ulonglong2* fp = (const ulonglong2*)(sdecT + k * SF + ty * 8);
            const ulonglong2 fA = fp[0], fB = fp[1];
            fma2(acc[0][0], fA.x, w0); fma2(acc[0][1], fA.x, w1);
            fma2(acc[0][2], fA.x, w2); fma2(acc[0][3], fA.x, w3);
            fma2(acc[1][0], fA.y, w0); fma2(acc[1][1], fA.y, w1);
            fma2(acc[1][2], fA.y, w2); fma2(acc[1][3], fA.y, w3);
            fma2(acc[2][0], fB.x, w0); fma2(acc[2][1], fB.x, w1);
            fma2(acc[2][2], fB.x, w2); fma2(acc[2][3], fB.x, w3);
            fma2(acc[3][0], fB.y, w0); fma2(acc[3][1], fB.y, w1);
            fma2(acc[3][2], fB.y, w2); fma2(acc[3][3], fB.y, w3);
        }
        #pragma unroll 4
        for (int k = 0; k < FDIM; k++) {
            const float4 w = __ldg((const float4*)(Wagg + (size_t)k * FDIM + 4*tx));
            const unsigned long long w0 = pk2(w.x, w.x), w1 = pk2(w.y, w.y),
                                     w2 = pk2(w.z, w.z), w3 = pk2(w.w, w.w);
            const ulonglong2* fp = (const ulonglong2*)(sdecT + (k + 128) * SF + ty * 8);
            const ulonglong2 fA = fp[0], fB = fp[1];
            fma2(acc[0][0], fA.x, w0); fma2(acc[0][1], fA.x, w1);
            fma2(acc[0][2], fA.x, w2); fma2(acc[0][3], fA.x, w3);
            fma2(acc[1][0], fA.y, w0); fma2(acc[1][1], fA.y, w1);
            fma2(acc[1][2], fA.y, w2); fma2(acc[1][3], fA.y, w3);
            fma2(acc[2][0], fB.x, w0); fma2(acc[2][1], fB.x, w1);
            fma2(acc[2][2], fB.x, w2); fma2(acc[2][3], fB.x, w3);
            fma2(acc[3][0], fB.y, w0); fma2(acc[3][1], fB.y, w1);
            fma2(acc[3][2], fB.y, w2); fma2(acc[3][3], fB.y, w3);
        }
        // relu + store row-major yd
        #pragma unroll
        for (int p = 0; p < 4; p++) {
            const float2 a0 = up2(acc[p][0]), a1 = up2(acc[p][1]);
            const float2 a2 = up2(acc[p][2]), a3 = up2(acc[p][3]);
            const int r0 = ty*8 + 2*p;
            *(float4*)(ydrow + (size_t)r0     * YDS + 4*tx) =
                make_float4(fmaxf(a0.x,0.f), fmaxf(a1.x,0.f), fmaxf(a2.x,0.f), fmaxf(a3.x,0.f));
            *(float4*)(ydrow + (size_t)(r0+1) * YDS + 4*tx) =
                make_float4(fmaxf(a0.y,0.f), fmaxf(a1.y,0.f), fmaxf(a2.y,0.f), fmaxf(a3.y,0.f));
        }
    }
    __syncthreads();

    // ---- heads + per-op einsum + loss, warp per node ----
    float latw = 0.f;
    #pragma unroll 1
    for (int i = 0; i < 8; i++) {
        const int r = wid * 8 + i;
        const int n = base + r;
        if (n >= N_NODES) break;

        const float4 yd4 = *(const float4*)(ydrow + (size_t)r * YDS + 4*lane);
        float mu[LDIM], lv[LDIM];
        #pragma unroll
        for (int l = 0; l < LDIM; l++) { mu[l] = 0.f; lv[l] = 0.f; }
        const float yc[4] = { yd4.x, yd4.y, yd4.z, yd4.w };
        #pragma unroll
        for (int c = 0; c < 4; c++) {
            const int row = 4*lane + c;
            const float4 ma = __ldg((const float4*)(muW + (size_t)row * LDIM));
            const float4 mb = __ldg((const float4*)(muW + (size_t)row * LDIM + 4));
            const float4 la = __ldg((const float4*)(lvW + (size_t)row * LDIM));
            const float4 lb = __ldg((const float4*)(lvW + (size_t)row * LDIM + 4));
            const float y = yc[c];
            mu[0] += y*ma.x; mu[1] += y*ma.y; mu[2] += y*ma.z; mu[3] += y*ma.w;
            mu[4] += y*mb.x; mu[5] += y*mb.y; mu[6] += y*mb.z; mu[7] += y*mb.w;
            lv[0] += y*la.x; lv[1] += y*la.y; lv[2] += y*la.z; lv[3] += y*la.w;
            lv[4] += y*lb.x; lv[5] += y*lb.y; lv[6] += y*lb.z; lv[7] += y*lb.w;
        }
        #pragma unroll
        for (int l = 0; l < LDIM; l++) {
            #pragma unroll
            for (int o = 16; o; o >>= 1) {
                mu[l] += __shfl_xor_sync(0xffffffffu, mu[l], o);
                lv[l] += __shfl_xor_sync(0xffffffffu, lv[l], o);
            }
            mu[l] += __ldg(mub + l);
            lv[l] += __ldg(lvb + l);
        }

        const int op = __ldg(op_id + n);
        float lk = 0.f;
        if (lane < LDIM) {
            const float* wrow = opw + (size_t)op * (2 * LDIM * LDIM);
            float mp = 0.f, lp = 0.f;
            #pragma unroll
            for (int l = 0; l < LDIM; l++) {
                mp += mu[l] * __ldg(wrow + l * 2 * LDIM + lane);
                lp += lv[l] * __ldg(wrow + l * 2 * LDIM + LDIM + lane);
            }
            const float label = __ldg(lat + (size_t)n * LDIM + lane);
            const float d = mp - label;
            lk = d * d / (2.f * expf(lp) + 1e-7f) + 0.5f * lp;
        }
        #pragma unroll
        for (int o = 16; o; o >>= 1) lk += __shfl_xor_sync(0xffffffffu, lk, o);
        const float lossn = lk * (1.f / LDIM);
        if (lane == 0) {
            atomicAdd(op_loss + op, lossn);
            atomicAdd(op_cnt  + op, 1.f);
            latw += lossn;
        }
    }
    if (lane == 0) sL[wid] = latw;
    __syncthreads();
    if (tid == 0) {
        double s = 0.0;
        #pragma unroll
        for (int i = 0; i < 8; i++) s += (double)sL[i];
        atomicAdd(&g_lat_sum, s);
    }
}

// ----------------------------------------------------------------------------
// Kernel 4: finalize scalar output
// ----------------------------------------------------------------------------
__global__ void fin_kernel(float* __restrict__ out)
{
    if (threadIdx.x == 0) {
        const double lat_loss = g_lat_sum / (double)N_NODES;
        const double kl = -0.5 * (g_kl_sum / ((double)N_NODES * (double)FDIM));
        out[0] = (float)(lat_loss + kl);
    }
}

// ----------------------------------------------------------------------------
extern "C" void kernel_launch(void* const* d_in, const int* in_sizes, int n_in,
                              void* d_out, int out_size)
{
    const int*   op_id = (const int*)  d_in[0];
    const int*   sv_id = (const int*)  d_in[1];
    const int*   st_id = (const int*)  d_in[2];
    const float* lat   = (const float*)d_in[3];
    const int*   esrc  = (const int*)  d_in[4];
    const int*   edst  = (const int*)  d_in[5];
    const float* eps   = (const float*)d_in[6];
    const float* opE   = (const float*)d_in[7];
    const float* svE   = (const float*)d_in[8];
    const float* stE   = (const float*)d_in[9];
    const float* W1    = (const float*)d_in[10];
    const float* b1    = (const float*)d_in[11];
    const float* W2    = (const float*)d_in[12];
    const float* b2    = (const float*)d_in[13];
    const float* Wself = (const float*)d_in[14];
    const float* Wagg  = (const float*)d_in[15];
    const float* muW   = (const float*)d_in[16];
    const float* mub   = (const float*)d_in[17];
    const float* lvW   = (const float*)d_in[18];
    const float* lvb   = (const float*)d_in[19];
    const float* opw   = (const float*)d_in[20];

    float* out     = (float*)d_out;
    float* op_loss = out + 1;
    float* op_cnt  = out + 1 + OPC;

    const int ENC_SMEM = (200 + 128) * SF * sizeof(float);   // 89216 B
    const int DEC_SMEM = 256 * SF * sizeof(float) + 64 * YDS * sizeof(float); // 103424 B
    static bool attr_done = false;
    if (!attr_done) {
        cudaFuncSetAttribute(enc_kernel, cudaFuncAttributeMaxDynamicSharedMemorySize, ENC_SMEM);
        cudaFuncSetAttribute(dec_kernel, cudaFuncAttributeMaxDynamicSharedMemorySize, DEC_SMEM);
        attr_done = true;
    }

    const int n_tiles = (N_NODES + TILE - 1) / TILE;   // 7813

    zero_kernel<<<62500, 256>>>(out);

    enc_kernel<<<n_tiles, 256, ENC_SMEM>>>(op_id, sv_id, st_id, lat, eps,
                                           opE, svE, stE, W1, b1, W2, b2);

    scatter_kernel<<<(N_EDGES + 7) / 8, 256>>>(esrc, edst);

    dec_kernel<<<n_tiles, 256, DEC_SMEM>>>(op_id, lat, Wself, Wagg,
                                           muW, mub, lvW, lvb, opw,
                                           op_loss, op_cnt);

    fin_kernel<<<1, 32>>>(out);
}

// round 3
// speedup vs baseline: 3.9472x; 1.4764x over previous
#include <cuda_runtime.h>
#include <cstdint>

#define N_NODES 500000
#define N_EDGES 1000000
#define EMB 64
#define FDIM 128
#define LDIM 8
#define OPC 5000

#define TILE 64
#define LDX1 204      // enc feats row stride (200 + pad)
#define LDH  132      // enc hidden row stride
#define LDW1 136      // staged W row stride (128 + pad)
#define LDW2 264      // staged W2 row stride (256 + pad)
#define LDXD 260      // dec [z|agg] row stride (256 + pad)

// ---- scratch (no allocations allowed) ----
__device__ float  g_z  [(size_t)N_NODES * FDIM];
__device__ float  g_agg[(size_t)N_NODES * FDIM];
__device__ double g_kl_sum;
__device__ double g_lat_sum;

// ---- helpers ----
__device__ __forceinline__ uint32_t smem_u32(const void* p) {
    uint32_t a;
    asm("{ .reg .u64 t; cvta.to.shared.u64 t, %1; cvt.u32.u64 %0, t; }"
        : "=r"(a) : "l"(p));
    return a;
}
__device__ __forceinline__ void ldsm_x4(uint32_t& r0, uint32_t& r1,
                                        uint32_t& r2, uint32_t& r3,
                                        uint32_t addr) {
    asm volatile("ldmatrix.sync.aligned.m8n8.x4.shared.b16 {%0,%1,%2,%3}, [%4];"
                 : "=r"(r0), "=r"(r1), "=r"(r2), "=r"(r3) : "r"(addr));
}
__device__ __forceinline__ void mma_tf32(float* d, const uint32_t* a,
                                         uint32_t b0, uint32_t b1) {
    asm volatile("mma.sync.aligned.m16n8k8.row.col.f32.tf32.tf32.f32 "
                 "{%0,%1,%2,%3}, {%4,%5,%6,%7}, {%8,%9}, {%0,%1,%2,%3};"
                 : "+f"(d[0]), "+f"(d[1]), "+f"(d[2]), "+f"(d[3])
                 : "r"(a[0]), "r"(a[1]), "r"(a[2]), "r"(a[3]),
                   "r"(b0), "r"(b1));
}

// ----------------------------------------------------------------------------
// Kernel 0: zero agg scratch, output head, scalar accumulators
// ----------------------------------------------------------------------------
__global__ void zero_kernel(float* __restrict__ out)
{
    size_t i = (size_t)blockIdx.x * blockDim.x + threadIdx.x;
    const size_t tot4 = (size_t)N_NODES * FDIM / 4;
    if (i < tot4) ((float4*)g_agg)[i] = make_float4(0.f, 0.f, 0.f, 0.f);
    if (i < (size_t)(1 + 2*OPC)) out[i] = 0.f;
    if (i == 0) { g_kl_sum = 0.0; g_lat_sum = 0.0; }
}

// ----------------------------------------------------------------------------
// Kernel 1: encoder (tf32 tensor cores), 64-node tile, 256 threads
// ----------------------------------------------------------------------------
extern "C" __global__ void __launch_bounds__(256, 2)
enc_kernel(const int*   __restrict__ op_id,
           const int*   __restrict__ sv_id,
           const int*   __restrict__ st_id,
           const float* __restrict__ lat,
           const float* __restrict__ eps,
           const float* __restrict__ opE,
           const float* __restrict__ svE,
           const float* __restrict__ stE,
           const float* __restrict__ W1,
           const float* __restrict__ b1,
           const float* __restrict__ W2,
           const float* __restrict__ b2)
{
    extern __shared__ float sm[];
    float* X1  = sm;                 // [64][204]  (52224 B)
    float* Wc  = sm + 13056;         // [40][136]  (GEMM1 chunk)
    float* Hs  = sm + 18496;         // [64][132]
    float* W2c = sm;                 // [64][264]  (GEMM2 chunk, aliases X1)
    float* Y   = sm;                 // [64][264]  (post-GEMM2, aliases W2c)
    __shared__ float skl[8];

    const int tid  = threadIdx.x;
    const int lane = tid & 31;
    const int w    = tid >> 5;
    const int base = blockIdx.x * TILE;
    const int mp   = w & 1;          // m-pair: rows mp*32 .. mp*32+31
    const int nq   = w >> 1;         // n-quarter
    const int g    = lane >> 2;      // groupID
    const int t    = lane & 3;       // threadID in group

    const uint32_t x1b = smem_u32(X1);
    const uint32_t hsb = smem_u32(Hs);

    // ---- gather feats: X1[r][0:200] = [opE|svE|stE|lat] ----
    {
        const int r = tid >> 2, q = tid & 3;
        const int n = base + r;
        float* row = X1 + r * LDX1;
        if (n < N_NODES) {
            const int op = op_id[n], sv = sv_id[n], st = st_id[n];
            #pragma unroll
            for (int j = 0; j < 4; j++) {
                *(float4*)(row + q*16 + 4*j)       = __ldg((const float4*)(opE + (size_t)op*EMB + q*16 + 4*j));
                *(float4*)(row + 64 + q*16 + 4*j)  = __ldg((const float4*)(svE + (size_t)sv*EMB + q*16 + 4*j));
                *(float4*)(row + 128 + q*16 + 4*j) = __ldg((const float4*)(stE + (size_t)st*EMB + q*16 + 4*j));
            }
            if (q == 0) {
                *(float4*)(row + 192) = __ldg((const float4*)(lat + (size_t)n*LDIM));
                *(float4*)(row + 196) = __ldg((const float4*)(lat + (size_t)n*LDIM + 4));
            }
        } else {
            const float4 z4 = make_float4(0.f,0.f,0.f,0.f);
            #pragma unroll
            for (int j = 0; j < 4; j++) {
                *(float4*)(row + q*16 + 4*j) = z4;
                *(float4*)(row + 64 + q*16 + 4*j) = z4;
                *(float4*)(row + 128 + q*16 + 4*j) = z4;
            }
            if (q == 0) { *(float4*)(row + 192) = z4; *(float4*)(row + 196) = z4; }
        }
    }
    __syncthreads();

    // ---- GEMM1: h = relu(X1 @ W1 + b1), K=200 (5 chunks x 40) ----
    float acc1[2][4][4];
    #pragma unroll
    for (int i = 0; i < 2; i++)
        #pragma unroll
        for (int nt = 0; nt < 4; nt++)
            #pragma unroll
            for (int j = 0; j < 4; j++) acc1[i][nt][j] = 0.f;

    for (int ch = 0; ch < 5; ch++) {
        #pragma unroll
        for (int i = 0; i < 5; i++) {
            const int idx = tid + i*256;           // < 1280
            const int row = idx >> 5, c4 = (idx & 31) << 2;
            *(float4*)(Wc + row*LDW1 + c4) =
                __ldg((const float4*)(W1 + (size_t)(ch*40 + row)*FDIM + c4));
        }
        __syncthreads();
        #pragma unroll
        for (int ks = 0; ks < 5; ks++) {
            const int kk = ks * 8;
            const int kcol = ch*40 + kk + ((lane >> 4) << 2);
            uint32_t a[2][4];
            #pragma unroll
            for (int i = 0; i < 2; i++) {
                const uint32_t addr = x1b +
                    (((mp*32 + i*16 + (lane & 15)) * LDX1 + kcol) << 2);
                ldsm_x4(a[i][0], a[i][1], a[i][2], a[i][3], addr);
            }
            #pragma unroll
            for (int nt = 0; nt < 4; nt++) {
                const int ncol = nq*32 + nt*8 + g;
                const uint32_t b0 = __float_as_uint(Wc[(kk + t)*LDW1 + ncol]);
                const uint32_t b1r = __float_as_uint(Wc[(kk + t + 4)*LDW1 + ncol]);
                mma_tf32(acc1[0][nt], a[0], b0, b1r);
                mma_tf32(acc1[1][nt], a[1], b0, b1r);
            }
        }
        __syncthreads();
    }

    // ---- write h = relu(y1 + b1) ----
    #pragma unroll
    for (int i = 0; i < 2; i++)
        #pragma unroll
        for (int nt = 0; nt < 4; nt++) {
            const int r = mp*32 + i*16 + g;
            const int c = nq*32 + nt*8 + 2*t;
            const float bA = __ldg(b1 + c), bB = __ldg(b1 + c + 1);
            Hs[r*LDH + c]       = fmaxf(acc1[i][nt][0] + bA, 0.f);
            Hs[r*LDH + c + 1]   = fmaxf(acc1[i][nt][1] + bB, 0.f);
            Hs[(r+8)*LDH + c]   = fmaxf(acc1[i][nt][2] + bA, 0.f);
            Hs[(r+8)*LDH + c+1] = fmaxf(acc1[i][nt][3] + bB, 0.f);
        }
    __syncthreads();

    // ---- GEMM2: y = h @ W2, K=128 (2 chunks x 64), N=256 ----
    float acc2[2][8][4];
    #pragma unroll
    for (int i = 0; i < 2; i++)
        #pragma unroll
        for (int nt = 0; nt < 8; nt++)
            #pragma unroll
            for (int j = 0; j < 4; j++) acc2[i][nt][j] = 0.f;

    for (int ch = 0; ch < 2; ch++) {
        #pragma unroll
        for (int i = 0; i < 16; i++) {
            const int idx = tid + i*256;           // < 4096
            const int row = idx >> 6, c4 = (idx & 63) << 2;
            *(float4*)(W2c + row*LDW2 + c4) =
                __ldg((const float4*)(W2 + (size_t)(ch*64 + row)*(2*FDIM) + c4));
        }
        __syncthreads();
        #pragma unroll
        for (int ks = 0; ks < 8; ks++) {
            const int kk = ks * 8;
            const int kcol = ch*64 + kk + ((lane >> 4) << 2);
            uint32_t a[2][4];
            #pragma unroll
            for (int i = 0; i < 2; i++) {
                const uint32_t addr = hsb +
                    (((mp*32 + i*16 + (lane & 15)) * LDH + kcol) << 2);
                ldsm_x4(a[i][0], a[i][1], a[i][2], a[i][3], addr);
            }
            #pragma unroll
            for (int nt = 0; nt < 8; nt++) {
                const int ncol = nq*64 + nt*8 + g;
                const uint32_t b0 = __float_as_uint(W2c[(kk + t)*LDW2 + ncol]);
                const uint32_t b1r = __float_as_uint(W2c[(kk + t + 4)*LDW2 + ncol]);
                mma_tf32(acc2[0][nt], a[0], b0, b1r);
                mma_tf32(acc2[1][nt], a[1], b0, b1r);
            }
        }
        __syncthreads();
    }

    // ---- y frags -> smem ----
    #pragma unroll
    for (int i = 0; i < 2; i++)
        #pragma unroll
        for (int nt = 0; nt < 8; nt++) {
            const int r = mp*32 + i*16 + g;
            const int c = nq*64 + nt*8 + 2*t;
            *(float2*)(Y + r*LDW2 + c)     = make_float2(acc2[i][nt][0], acc2[i][nt][1]);
            *(float2*)(Y + (r+8)*LDW2 + c) = make_float2(acc2[i][nt][2], acc2[i][nt][3]);
        }
    __syncthreads();

    // ---- epilogue: z = (mu+b) + exp(0.5*tanh(lv+b))*eps, KL ----
    float klw = 0.f;
    #pragma unroll
    for (int it = 0; it < 8; it++) {
        const int idx = tid + it*256;              // 2048 = 64*32
        const int r = idx >> 5, c4 = (idx & 31) << 2;
        const int n = base + r;
        if (n >= N_NODES) continue;
        float4 mu4 = *(float4*)(Y + r*LDW2 + c4);
        float4 lv4 = *(float4*)(Y + r*LDW2 + FDIM + c4);
        const float4 bm = __ldg((const float4*)(b2 + c4));
        const float4 bl = __ldg((const float4*)(b2 + FDIM + c4));
        mu4.x += bm.x; mu4.y += bm.y; mu4.z += bm.z; mu4.w += bm.w;
        lv4.x = tanhf(lv4.x + bl.x); lv4.y = tanhf(lv4.y + bl.y);
        lv4.z = tanhf(lv4.z + bl.z); lv4.w = tanhf(lv4.w + bl.w);
        const float4 e = __ldg((const float4*)(eps + (size_t)n*FDIM + c4));
        float4 z;
        z.x = mu4.x + expf(0.5f*lv4.x) * e.x;
        z.y = mu4.y + expf(0.5f*lv4.y) * e.y;
        z.z = mu4.z + expf(0.5f*lv4.z) * e.z;
        z.w = mu4.w + expf(0.5f*lv4.w) * e.w;
        *(float4*)(g_z + (size_t)n*FDIM + c4) = z;
        klw += (lv4.x + 1.f - expf(lv4.x) - mu4.x*mu4.x);
        klw += (lv4.y + 1.f - expf(lv4.y) - mu4.y*mu4.y);
        klw += (lv4.z + 1.f - expf(lv4.z) - mu4.z*mu4.z);
        klw += (lv4.w + 1.f - expf(lv4.w) - mu4.w*mu4.w);
    }
    #pragma unroll
    for (int o = 16; o; o >>= 1) klw += __shfl_xor_sync(0xffffffffu, klw, o);
    if (lane == 0) skl[w] = klw;
    __syncthreads();
    if (tid == 0) {
        double s = 0.0;
        #pragma unroll
        for (int i = 0; i < 8; i++) s += (double)skl[i];
        atomicAdd(&g_kl_sum, s);
    }
}

// ----------------------------------------------------------------------------
// Kernel 2: edge scatter-add
// ----------------------------------------------------------------------------
__global__ void scatter_kernel(const int* __restrict__ esrc,
                               const int* __restrict__ edst)
{
    const int e    = (blockIdx.x * blockDim.x + threadIdx.x) >> 5;
    const int lane = threadIdx.x & 31;
    if (e >= N_EDGES) return;
    const int s = __ldg(esrc + e);
    const int d = __ldg(edst + e);
    const float4 v = ((const float4*)g_z)[(size_t)s * 32 + lane];
    float* p = &g_agg[(size_t)d * FDIM + 4*lane];
    asm volatile("red.global.add.v4.f32 [%0], {%1, %2, %3, %4};"
                 :: "l"(p), "f"(v.x), "f"(v.y), "f"(v.z), "f"(v.w) : "memory");
}

// ----------------------------------------------------------------------------
// Kernel 3: decoder (tf32 tensor cores) + heads + loss
// ----------------------------------------------------------------------------
extern "C" __global__ void __launch_bounds__(256, 2)
dec_kernel(const int*   __restrict__ op_id,
           const float* __restrict__ lat,
           const float* __restrict__ Wself,
           const float* __restrict__ Wagg,
           const float* __restrict__ muW,
           const float* __restrict__ mub,
           const float* __restrict__ lvW,
           const float* __restrict__ lvb,
           const float* __restrict__ opw,
           float* __restrict__ op_loss,
           float* __restrict__ op_cnt)
{
    extern __shared__ float sm[];
    float* X  = sm;            // [64][260] : cols 0:128 z, 128:256 agg
    float* Wc = sm + 16640;    // [64][136] chunk
    float* Yd = sm + 16640;    // [64][132] aliases Wc after GEMM
    __shared__ float sL[8];

    const int tid  = threadIdx.x;
    const int lane = tid & 31;
    const int w    = tid >> 5;
    const int base = blockIdx.x * TILE;
    const int mp   = w & 1;
    const int nq   = w >> 1;
    const int g    = lane >> 2;
    const int t    = lane & 3;
    const uint32_t xb = smem_u32(X);

    // ---- gather z/agg node-major ----
    #pragma unroll
    for (int it = 0; it < 8; it++) {
        const int idx = tid + it*256;       // 2048
        const int r = idx >> 5, c4 = (idx & 31) << 2;
        const int n = base + r;
        if (n < N_NODES) {
            *(float4*)(X + r*LDXD + c4)        = *(const float4*)(g_z   + (size_t)n*FDIM + c4);
            *(float4*)(X + r*LDXD + FDIM + c4) = *(const float4*)(g_agg + (size_t)n*FDIM + c4);
        } else {
            const float4 z4 = make_float4(0.f,0.f,0.f,0.f);
            *(float4*)(X + r*LDXD + c4) = z4;
            *(float4*)(X + r*LDXD + FDIM + c4) = z4;
        }
    }
    __syncthreads();

    // ---- GEMM: yd = relu([z|agg] @ [Wself;Wagg]), K=256 (4 chunks x 64) ----
    float acc[2][4][4];
    #pragma unroll
    for (int i = 0; i < 2; i++)
        #pragma unroll
        for (int nt = 0; nt < 4; nt++)
            #pragma unroll
            for (int j = 0; j < 4; j++) acc[i][nt][j] = 0.f;

    for (int ch = 0; ch < 4; ch++) {
        #pragma unroll
        for (int i = 0; i < 8; i++) {
            const int idx = tid + i*256;    // 2048
            const int row = idx >> 5, c4 = (idx & 31) << 2;
            const int kk = ch*64 + row;
            const float* src = (kk < FDIM) ? (Wself + (size_t)kk*FDIM + c4)
                                           : (Wagg + (size_t)(kk - FDIM)*FDIM + c4);
            *(float4*)(Wc + row*LDW1 + c4) = __ldg((const float4*)src);
        }
        __syncthreads();
        #pragma unroll
        for (int ks = 0; ks < 8; ks++) {
            const int kk = ks * 8;
            const int kcol = ch*64 + kk + ((lane >> 4) << 2);
            uint32_t a[2][4];
            #pragma unroll
            for (int i = 0; i < 2; i++) {
                const uint32_t addr = xb +
                    (((mp*32 + i*16 + (lane & 15)) * LDXD + kcol) << 2);
                ldsm_x4(a[i][0], a[i][1], a[i][2], a[i][3], addr);
            }
            #pragma unroll
            for (int nt = 0; nt < 4; nt++) {
                const int ncol = nq*32 + nt*8 + g;
                const uint32_t b0 = __float_as_uint(Wc[(kk + t)*LDW1 + ncol]);
                const uint32_t b1r = __float_as_uint(Wc[(kk + t + 4)*LDW1 + ncol]);
                mma_tf32(acc[0][nt], a[0], b0, b1r);
                mma_tf32(acc[1][nt], a[1], b0, b1r);
            }
        }
        __syncthreads();
    }

    // ---- yd = relu(acc) -> smem ----
    #pragma unroll
    for (int i = 0; i < 2; i++)
        #pragma unroll
        for (int nt = 0; nt < 4; nt++) {
            const int r = mp*32 + i*16 + g;
            const int c = nq*32 + nt*8 + 2*t;
            Yd[r*LDH + c]       = fmaxf(acc[i][nt][0], 0.f);
            Yd[r*LDH + c + 1]   = fmaxf(acc[i][nt][1], 0.f);
            Yd[(r+8)*LDH + c]   = fmaxf(acc[i][nt][2], 0.f);
            Yd[(r+8)*LDH + c+1] = fmaxf(acc[i][nt][3], 0.f);
        }
    __syncthreads();

    // ---- heads + per-op einsum + loss, warp per node ----
    float latw = 0.f;
    #pragma unroll 1
    for (int i = 0; i < 8; i++) {
        const int r = w * 8 + i;
        const int n = base + r;
        if (n >= N_NODES) break;

        const float4 yd4 = *(const float4*)(Yd + (size_t)r*LDH + 4*lane);
        float mu[LDIM], lv[LDIM];
        #pragma unroll
        for (int l = 0; l < LDIM; l++) { mu[l] = 0.f; lv[l] = 0.f; }
        const float yc[4] = { yd4.x, yd4.y, yd4.z, yd4.w };
        #pragma unroll
        for (int c = 0; c < 4; c++) {
            const int row = 4*lane + c;
            const float4 ma = __ldg((const float4*)(muW + (size_t)row * LDIM));
            const float4 mb = __ldg((const float4*)(muW + (size_t)row * LDIM + 4));
            const float4 la = __ldg((const float4*)(lvW + (size_t)row * LDIM));
            const float4 lb = __ldg((const float4*)(lvW + (size_t)row * LDIM + 4));
            const float y = yc[c];
            mu[0] += y*ma.x; mu[1] += y*ma.y; mu[2] += y*ma.z; mu[3] += y*ma.w;
            mu[4] += y*mb.x; mu[5] += y*mb.y; mu[6] += y*mb.z; mu[7] += y*mb.w;
            lv[0] += y*la.x; lv[1] += y*la.y; lv[2] += y*la.z; lv[3] += y*la.w;
            lv[4] += y*lb.x; lv[5] += y*lb.y; lv[6] += y*lb.z; lv[7] += y*lb.w;
        }
        #pragma unroll
        for (int l = 0; l < LDIM; l++) {
            #pragma unroll
            for (int o = 16; o; o >>= 1) {
                mu[l] += __shfl_xor_sync(0xffffffffu, mu[l], o);
                lv[l] += __shfl_xor_sync(0xffffffffu, lv[l], o);
            }
            mu[l] += __ldg(mub + l);
            lv[l] += __ldg(lvb + l);
        }

        const int op = __ldg(op_id + n);
        float lk = 0.f;
        if (lane < LDIM) {
            const float* wrow = opw + (size_t)op * (2 * LDIM * LDIM);
            float mp2 = 0.f, lp = 0.f;
            #pragma unroll
            for (int l = 0; l < LDIM; l++) {
                mp2 += mu[l] * __ldg(wrow + l * 2 * LDIM + lane);
                lp  += lv[l] * __ldg(wrow + l * 2 * LDIM + LDIM + lane);
            }
            const float label = __ldg(lat + (size_t)n * LDIM + lane);
            const float d = mp2 - label;
            lk = d * d / (2.f * expf(lp) + 1e-7f) + 0.5f * lp;
        }
        #pragma unroll
        for (int o = 16; o; o >>= 1) lk += __shfl_xor_sync(0xffffffffu, lk, o);
        const float lossn = lk * (1.f / LDIM);
        if (lane == 0) {
            atomicAdd(op_loss + op, lossn);
            atomicAdd(op_cnt  + op, 1.f);
            latw += lossn;
        }
    }
    if (lane == 0) sL[w] = latw;
    __syncthreads();
    if (tid == 0) {
        double s = 0.0;
        #pragma unroll
        for (int i = 0; i < 8; i++) s += (double)sL[i];
        atomicAdd(&g_lat_sum, s);
    }
}

// ----------------------------------------------------------------------------
// Kernel 4: finalize
// ----------------------------------------------------------------------------
__global__ void fin_kernel(float* __restrict__ out)
{
    if (threadIdx.x == 0) {
        const double lat_loss = g_lat_sum / (double)N_NODES;
        const double kl = -0.5 * (g_kl_sum / ((double)N_NODES * (double)FDIM));
        out[0] = (float)(lat_loss + kl);
    }
}

// ----------------------------------------------------------------------------
extern "C" void kernel_launch(void* const* d_in, const int* in_sizes, int n_in,
                              void* d_out, int out_size)
{
    const int*   op_id = (const int*)  d_in[0];
    const int*   sv_id = (const int*)  d_in[1];
    const int*   st_id = (const int*)  d_in[2];
    const float* lat   = (const float*)d_in[3];
    const int*   esrc  = (const int*)  d_in[4];
    const int*   edst  = (const int*)  d_in[5];
    const float* eps   = (const float*)d_in[6];
    const float* opE   = (const float*)d_in[7];
    const float* svE   = (const float*)d_in[8];
    const float* stE   = (const float*)d_in[9];
    const float* W1    = (const float*)d_in[10];
    const float* b1    = (const float*)d_in[11];
    const float* W2    = (const float*)d_in[12];
    const float* b2    = (const float*)d_in[13];
    const float* Wself = (const float*)d_in[14];
    const float* Wagg  = (const float*)d_in[15];
    const float* muW   = (const float*)d_in[16];
    const float* mub   = (const float*)d_in[17];
    const float* lvW   = (const float*)d_in[18];
    const float* lvb   = (const float*)d_in[19];
    const float* opw   = (const float*)d_in[20];

    float* out     = (float*)d_out;
    float* op_loss = out + 1;
    float* op_cnt  = out + 1 + OPC;

    const int ENC_SMEM = 26944 * sizeof(float);   // 107776 B
    const int DEC_SMEM = 25344 * sizeof(float);   // 101376 B
    static bool attr_done = false;
    if (!attr_done) {
        cudaFuncSetAttribute(enc_kernel, cudaFuncAttributeMaxDynamicSharedMemorySize, ENC_SMEM);
        cudaFuncSetAttribute(dec_kernel, cudaFuncAttributeMaxDynamicSharedMemorySize, DEC_SMEM);
        attr_done = true;
    }

    const int n_tiles = (N_NODES + TILE - 1) / TILE;   // 7813

    zero_kernel<<<62500, 256>>>(out);

    enc_kernel<<<n_tiles, 256, ENC_SMEM>>>(op_id, sv_id, st_id, lat, eps,
                                           opE, svE, stE, W1, b1, W2, b2);

    scatter_kernel<<<(N_EDGES + 7) / 8, 256>>>(esrc, edst);

    dec_kernel<<<n_tiles, 256, DEC_SMEM>>>(op_id, lat, Wself, Wagg,
                                           muW, mub, lvW, lvb, opw,
                                           op_loss, op_cnt);

    fin_kernel<<<1, 32>>>(out);
}

// round 4
// speedup vs baseline: 7.3964x; 1.8738x over previous
#include <cuda_runtime.h>
#include <cstdint>

#define N_NODES 500000
#define N_EDGES 1000000
#define EMB 64
#define FDIM 128
#define LDIM 8
#define OPC 5000

#define TILE 64
#define LDX1 204      // enc feats row stride (200 + pad)
#define LDH  132      // hidden row stride
#define LDW1 136      // staged W row stride (128 + pad)
#define LDW2 264      // staged W2 row stride (256 + pad)
#define LDXD 260      // dec [z|agg] row stride (256 + pad)
#define LDWH 24       // heads weight stride (16 + pad)
#define LDYH 20       // heads output stride (16 + pad)

// ---- scratch (no allocations allowed) ----
__device__ float  g_z  [(size_t)N_NODES * FDIM];
__device__ float  g_agg[(size_t)N_NODES * FDIM];
__device__ double g_kl_sum;
__device__ double g_lat_sum;

// ---- helpers ----
__device__ __forceinline__ uint32_t smem_u32(const void* p) {
    uint32_t a;
    asm("{ .reg .u64 t; cvta.to.shared.u64 t, %1; cvt.u32.u64 %0, t; }"
        : "=r"(a) : "l"(p));
    return a;
}
__device__ __forceinline__ void ldsm_x4(uint32_t& r0, uint32_t& r1,
                                        uint32_t& r2, uint32_t& r3,
                                        uint32_t addr) {
    asm volatile("ldmatrix.sync.aligned.m8n8.x4.shared.b16 {%0,%1,%2,%3}, [%4];"
                 : "=r"(r0), "=r"(r1), "=r"(r2), "=r"(r3) : "r"(addr));
}
__device__ __forceinline__ void mma_tf32(float* d, const uint32_t* a,
                                         uint32_t b0, uint32_t b1) {
    asm volatile("mma.sync.aligned.m16n8k8.row.col.f32.tf32.tf32.f32 "
                 "{%0,%1,%2,%3}, {%4,%5,%6,%7}, {%8,%9}, {%0,%1,%2,%3};"
                 : "+f"(d[0]), "+f"(d[1]), "+f"(d[2]), "+f"(d[3])
                 : "r"(a[0]), "r"(a[1]), "r"(a[2]), "r"(a[3]),
                   "r"(b0), "r"(b1));
}

// ----------------------------------------------------------------------------
// Kernel 0: zero agg scratch, output head, scalar accumulators
// ----------------------------------------------------------------------------
__global__ void zero_kernel(float* __restrict__ out)
{
    size_t i = (size_t)blockIdx.x * blockDim.x + threadIdx.x;
    const size_t tot4 = (size_t)N_NODES * FDIM / 4;
    if (i < tot4) ((float4*)g_agg)[i] = make_float4(0.f, 0.f, 0.f, 0.f);
    if (i < (size_t)(1 + 2*OPC)) out[i] = 0.f;
    if (i == 0) { g_kl_sum = 0.0; g_lat_sum = 0.0; }
}

// ----------------------------------------------------------------------------
// Kernel 1: encoder (tf32 tensor cores), 64-node tile, 256 threads
// ----------------------------------------------------------------------------
extern "C" __global__ void __launch_bounds__(256, 2)
enc_kernel(const int*   __restrict__ op_id,
           const int*   __restrict__ sv_id,
           const int*   __restrict__ st_id,
           const float* __restrict__ lat,
           const float* __restrict__ eps,
           const float* __restrict__ opE,
           const float* __restrict__ svE,
           const float* __restrict__ stE,
           const float* __restrict__ W1,
           const float* __restrict__ b1,
           const float* __restrict__ W2,
           const float* __restrict__ b2)
{
    extern __shared__ float sm[];
    float* X1  = sm;                 // [64][204]
    float* Wc  = sm + 13056;         // [40][136]
    float* Hs  = sm + 18496;         // [64][132]
    float* W2c = sm;                 // [64][264]  (aliases X1)
    float* Y   = sm;                 // [64][264]  (aliases W2c)
    __shared__ float skl[8];

    const int tid  = threadIdx.x;
    const int lane = tid & 31;
    const int w    = tid >> 5;
    const int base = blockIdx.x * TILE;
    const int mp   = w & 1;
    const int nq   = w >> 1;
    const int g    = lane >> 2;
    const int t    = lane & 3;

    const uint32_t x1b = smem_u32(X1);
    const uint32_t hsb = smem_u32(Hs);

    // ---- gather feats ----
    {
        const int r = tid >> 2, q = tid & 3;
        const int n = base + r;
        float* row = X1 + r * LDX1;
        if (n < N_NODES) {
            const int op = op_id[n], sv = sv_id[n], st = st_id[n];
            #pragma unroll
            for (int j = 0; j < 4; j++) {
                *(float4*)(row + q*16 + 4*j)       = __ldg((const float4*)(opE + (size_t)op*EMB + q*16 + 4*j));
                *(float4*)(row + 64 + q*16 + 4*j)  = __ldg((const float4*)(svE + (size_t)sv*EMB + q*16 + 4*j));
                *(float4*)(row + 128 + q*16 + 4*j) = __ldg((const float4*)(stE + (size_t)st*EMB + q*16 + 4*j));
            }
            if (q == 0) {
                *(float4*)(row + 192) = __ldg((const float4*)(lat + (size_t)n*LDIM));
                *(float4*)(row + 196) = __ldg((const float4*)(lat + (size_t)n*LDIM + 4));
            }
        } else {
            const float4 z4 = make_float4(0.f,0.f,0.f,0.f);
            #pragma unroll
            for (int j = 0; j < 4; j++) {
                *(float4*)(row + q*16 + 4*j) = z4;
                *(float4*)(row + 64 + q*16 + 4*j) = z4;
                *(float4*)(row + 128 + q*16 + 4*j) = z4;
            }
            if (q == 0) { *(float4*)(row + 192) = z4; *(float4*)(row + 196) = z4; }
        }
    }
    __syncthreads();

    // ---- GEMM1: K=200 (5 chunks x 40) ----
    float acc1[2][4][4];
    #pragma unroll
    for (int i = 0; i < 2; i++)
        #pragma unroll
        for (int nt = 0; nt < 4; nt++)
            #pragma unroll
            for (int j = 0; j < 4; j++) acc1[i][nt][j] = 0.f;

    for (int ch = 0; ch < 5; ch++) {
        #pragma unroll
        for (int i = 0; i < 5; i++) {
            const int idx = tid + i*256;
            const int row = idx >> 5, c4 = (idx & 31) << 2;
            *(float4*)(Wc + row*LDW1 + c4) =
                __ldg((const float4*)(W1 + (size_t)(ch*40 + row)*FDIM + c4));
        }
        __syncthreads();
        #pragma unroll
        for (int ks = 0; ks < 5; ks++) {
            const int kk = ks * 8;
            const int kcol = ch*40 + kk + ((lane >> 4) << 2);
            uint32_t a[2][4];
            #pragma unroll
            for (int i = 0; i < 2; i++) {
                const uint32_t addr = x1b +
                    (((mp*32 + i*16 + (lane & 15)) * LDX1 + kcol) << 2);
                ldsm_x4(a[i][0], a[i][1], a[i][2], a[i][3], addr);
            }
            #pragma unroll
            for (int nt = 0; nt < 4; nt++) {
                const int ncol = nq*32 + nt*8 + g;
                const uint32_t b0 = __float_as_uint(Wc[(kk + t)*LDW1 + ncol]);
                const uint32_t b1r = __float_as_uint(Wc[(kk + t + 4)*LDW1 + ncol]);
                mma_tf32(acc1[0][nt], a[0], b0, b1r);
                mma_tf32(acc1[1][nt], a[1], b0, b1r);
            }
        }
        __syncthreads();
    }

    // ---- h = relu(y1 + b1) ----
    #pragma unroll
    for (int i = 0; i < 2; i++)
        #pragma unroll
        for (int nt = 0; nt < 4; nt++) {
            const int r = mp*32 + i*16 + g;
            const int c = nq*32 + nt*8 + 2*t;
            const float bA = __ldg(b1 + c), bB = __ldg(b1 + c + 1);
            Hs[r*LDH + c]       = fmaxf(acc1[i][nt][0] + bA, 0.f);
            Hs[r*LDH + c + 1]   = fmaxf(acc1[i][nt][1] + bB, 0.f);
            Hs[(r+8)*LDH + c]   = fmaxf(acc1[i][nt][2] + bA, 0.f);
            Hs[(r+8)*LDH + c+1] = fmaxf(acc1[i][nt][3] + bB, 0.f);
        }
    __syncthreads();

    // ---- GEMM2: K=128 (2 chunks x 64), N=256 ----
    float acc2[2][8][4];
    #pragma unroll
    for (int i = 0; i < 2; i++)
        #pragma unroll
        for (int nt = 0; nt < 8; nt++)
            #pragma unroll
            for (int j = 0; j < 4; j++) acc2[i][nt][j] = 0.f;

    for (int ch = 0; ch < 2; ch++) {
        #pragma unroll
        for (int i = 0; i < 16; i++) {
            const int idx = tid + i*256;
            const int row = idx >> 6, c4 = (idx & 63) << 2;
            *(float4*)(W2c + row*LDW2 + c4) =
                __ldg((const float4*)(W2 + (size_t)(ch*64 + row)*(2*FDIM) + c4));
        }
        __syncthreads();
        #pragma unroll
        for (int ks = 0; ks < 8; ks++) {
            const int kk = ks * 8;
            const int kcol = ch*64 + kk + ((lane >> 4) << 2);
            uint32_t a[2][4];
            #pragma unroll
            for (int i = 0; i < 2; i++) {
                const uint32_t addr = hsb +
                    (((mp*32 + i*16 + (lane & 15)) * LDH + kcol) << 2);
                ldsm_x4(a[i][0], a[i][1], a[i][2], a[i][3], addr);
            }
            #pragma unroll
            for (int nt = 0; nt < 8; nt++) {
                const int ncol = nq*64 + nt*8 + g;
                const uint32_t b0 = __float_as_uint(W2c[(kk + t)*LDW2 + ncol]);
                const uint32_t b1r = __float_as_uint(W2c[(kk + t + 4)*LDW2 + ncol]);
                mma_tf32(acc2[0][nt], a[0], b0, b1r);
                mma_tf32(acc2[1][nt], a[1], b0, b1r);
            }
        }
        __syncthreads();
    }

    // ---- y frags -> smem ----
    #pragma unroll
    for (int i = 0; i < 2; i++)
        #pragma unroll
        for (int nt = 0; nt < 8; nt++) {
            const int r = mp*32 + i*16 + g;
            const int c = nq*64 + nt*8 + 2*t;
            *(float2*)(Y + r*LDW2 + c)     = make_float2(acc2[i][nt][0], acc2[i][nt][1]);
            *(float2*)(Y + (r+8)*LDW2 + c) = make_float2(acc2[i][nt][2], acc2[i][nt][3]);
        }
    __syncthreads();

    // ---- epilogue ----
    float klw = 0.f;
    #pragma unroll
    for (int it = 0; it < 8; it++) {
        const int idx = tid + it*256;
        const int r = idx >> 5, c4 = (idx & 31) << 2;
        const int n = base + r;
        if (n >= N_NODES) continue;
        float4 mu4 = *(float4*)(Y + r*LDW2 + c4);
        float4 lv4 = *(float4*)(Y + r*LDW2 + FDIM + c4);
        const float4 bm = __ldg((const float4*)(b2 + c4));
        const float4 bl = __ldg((const float4*)(b2 + FDIM + c4));
        mu4.x += bm.x; mu4.y += bm.y; mu4.z += bm.z; mu4.w += bm.w;
        lv4.x = tanhf(lv4.x + bl.x); lv4.y = tanhf(lv4.y + bl.y);
        lv4.z = tanhf(lv4.z + bl.z); lv4.w = tanhf(lv4.w + bl.w);
        const float4 e = __ldg((const float4*)(eps + (size_t)n*FDIM + c4));
        float4 z;
        z.x = mu4.x + expf(0.5f*lv4.x) * e.x;
        z.y = mu4.y + expf(0.5f*lv4.y) * e.y;
        z.z = mu4.z + expf(0.5f*lv4.z) * e.z;
        z.w = mu4.w + expf(0.5f*lv4.w) * e.w;
        *(float4*)(g_z + (size_t)n*FDIM + c4) = z;
        klw += (lv4.x + 1.f - expf(lv4.x) - mu4.x*mu4.x);
        klw += (lv4.y + 1.f - expf(lv4.y) - mu4.y*mu4.y);
        klw += (lv4.z + 1.f - expf(lv4.z) - mu4.z*mu4.z);
        klw += (lv4.w + 1.f - expf(lv4.w) - mu4.w*mu4.w);
    }
    #pragma unroll
    for (int o = 16; o; o >>= 1) klw += __shfl_xor_sync(0xffffffffu, klw, o);
    if (lane == 0) skl[w] = klw;
    __syncthreads();
    if (tid == 0) {
        double s = 0.0;
        #pragma unroll
        for (int i = 0; i < 8; i++) s += (double)skl[i];
        atomicAdd(&g_kl_sum, s);
    }
}

// ----------------------------------------------------------------------------
// Kernel 2: edge scatter-add
// ----------------------------------------------------------------------------
__global__ void scatter_kernel(const int* __restrict__ esrc,
                               const int* __restrict__ edst)
{
    const int e    = (blockIdx.x * blockDim.x + threadIdx.x) >> 5;
    const int lane = threadIdx.x & 31;
    if (e >= N_EDGES) return;
    const int s = __ldg(esrc + e);
    const int d = __ldg(edst + e);
    const float4 v = ((const float4*)g_z)[(size_t)s * 32 + lane];
    float* p = &g_agg[(size_t)d * FDIM + 4*lane];
    asm volatile("red.global.add.v4.f32 [%0], {%1, %2, %3, %4};"
                 :: "l"(p), "f"(v.x), "f"(v.y), "f"(v.z), "f"(v.w) : "memory");
}

// ----------------------------------------------------------------------------
// Kernel 3: decoder (tf32) + heads via mma + thread-parallel loss
// ----------------------------------------------------------------------------
extern "C" __global__ void __launch_bounds__(256, 2)
dec_kernel(const int*   __restrict__ op_id,
           const float* __restrict__ lat,
           const float* __restrict__ Wself,
           const float* __restrict__ Wagg,
           const float* __restrict__ muW,
           const float* __restrict__ mub,
           const float* __restrict__ lvW,
           const float* __restrict__ lvb,
           const float* __restrict__ opw,
           float* __restrict__ op_loss,
           float* __restrict__ op_cnt)
{
    extern __shared__ float sm[];
    float* X  = sm;            // [64][260]
    float* Wc = sm + 16640;    // [64][136]
    float* Yd = sm + 16640;    // [64][132] (aliases Wc after GEMM)
    float* Wh = sm;            // [128][24] (aliases X after GEMM)
    float* Yh = sm + 3072;     // [64][20]  (aliases X tail)
    __shared__ float sL[8];

    const int tid  = threadIdx.x;
    const int lane = tid & 31;
    const int w    = tid >> 5;
    const int base = blockIdx.x * TILE;
    const int mp   = w & 1;
    const int nq   = w >> 1;
    const int g    = lane >> 2;
    const int t    = lane & 3;
    const uint32_t xb  = smem_u32(X);
    const uint32_t ydb = smem_u32(Yd);

    // ---- gather z/agg node-major ----
    #pragma unroll
    for (int it = 0; it < 8; it++) {
        const int idx = tid + it*256;
        const int r = idx >> 5, c4 = (idx & 31) << 2;
        const int n = base + r;
        if (n < N_NODES) {
            *(float4*)(X + r*LDXD + c4)        = *(const float4*)(g_z   + (size_t)n*FDIM + c4);
            *(float4*)(X + r*LDXD + FDIM + c4) = *(const float4*)(g_agg + (size_t)n*FDIM + c4);
        } else {
            const float4 z4 = make_float4(0.f,0.f,0.f,0.f);
            *(float4*)(X + r*LDXD + c4) = z4;
            *(float4*)(X + r*LDXD + FDIM + c4) = z4;
        }
    }
    __syncthreads();

    // ---- GEMM: yd = relu([z|agg] @ [Wself;Wagg]), K=256 (4 chunks x 64) ----
    float acc[2][4][4];
    #pragma unroll
    for (int i = 0; i < 2; i++)
        #pragma unroll
        for (int nt = 0; nt < 4; nt++)
            #pragma unroll
            for (int j = 0; j < 4; j++) acc[i][nt][j] = 0.f;

    for (int ch = 0; ch < 4; ch++) {
        #pragma unroll
        for (int i = 0; i < 8; i++) {
            const int idx = tid + i*256;
            const int row = idx >> 5, c4 = (idx & 31) << 2;
            const int kk = ch*64 + row;
            const float* src = (kk < FDIM) ? (Wself + (size_t)kk*FDIM + c4)
                                           : (Wagg + (size_t)(kk - FDIM)*FDIM + c4);
            *(float4*)(Wc + row*LDW1 + c4) = __ldg((const float4*)src);
        }
        __syncthreads();
        #pragma unroll
        for (int ks = 0; ks < 8; ks++) {
            const int kk = ks * 8;
            const int kcol = ch*64 + kk + ((lane >> 4) << 2);
            uint32_t a[2][4];
            #pragma unroll
            for (int i = 0; i < 2; i++) {
                const uint32_t addr = xb +
                    (((mp*32 + i*16 + (lane & 15)) * LDXD + kcol) << 2);
                ldsm_x4(a[i][0], a[i][1], a[i][2], a[i][3], addr);
            }
            #pragma unroll
            for (int nt = 0; nt < 4; nt++) {
                const int ncol = nq*32 + nt*8 + g;
                const uint32_t b0 = __float_as_uint(Wc[(kk + t)*LDW1 + ncol]);
                const uint32_t b1r = __float_as_uint(Wc[(kk + t + 4)*LDW1 + ncol]);
                mma_tf32(acc[0][nt], a[0], b0, b1r);
                mma_tf32(acc[1][nt], a[1], b0, b1r);
            }
        }
        __syncthreads();
    }

    // ---- yd = relu(acc) -> smem ; stage heads weights Wh = [muW|lvW] ----
    #pragma unroll
    for (int i = 0; i < 2; i++)
        #pragma unroll
        for (int nt = 0; nt < 4; nt++) {
            const int r = mp*32 + i*16 + g;
            const int c = nq*32 + nt*8 + 2*t;
            Yd[r*LDH + c]       = fmaxf(acc[i][nt][0], 0.f);
            Yd[r*LDH + c + 1]   = fmaxf(acc[i][nt][1], 0.f);
            Yd[(r+8)*LDH + c]   = fmaxf(acc[i][nt][2], 0.f);
            Yd[(r+8)*LDH + c+1] = fmaxf(acc[i][nt][3], 0.f);
        }
    {
        #pragma unroll
        for (int i = 0; i < 4; i++) {
            const int idx = tid + i*256;        // 1024 = 128*8
            const int k = idx >> 3, l = idx & 7;
            Wh[k*LDWH + l]     = __ldg(muW + (size_t)k*LDIM + l);
            Wh[k*LDWH + 8 + l] = __ldg(lvW + (size_t)k*LDIM + l);
        }
    }
    __syncthreads();

    // ---- heads mma: y_heads[64][16] = yd @ Wh ----
    {
        const int mt = w & 3;          // m-tile (16 rows)
        const int nh = w >> 2 >= 2 ? 1 : (w >> 2);   // 0..1 (warps 0-7 -> nh 0,0,0,0,1,1,1,1)
        float ah[4] = {0.f, 0.f, 0.f, 0.f};
        #pragma unroll
        for (int ks = 0; ks < 16; ks++) {
            const int kk = ks * 8;
            uint32_t a[4];
            const uint32_t addr = ydb +
                (((mt*16 + (lane & 15)) * LDH + kk + ((lane >> 4) << 2)) << 2);
            ldsm_x4(a[0], a[1], a[2], a[3], addr);
            const uint32_t b0 = __float_as_uint(Wh[(kk + t)*LDWH + nh*8 + g]);
            const uint32_t b1r = __float_as_uint(Wh[(kk + t + 4)*LDWH + nh*8 + g]);
            mma_tf32(ah, a, b0, b1r);
        }
        const int r = mt*16 + g;
        const int c = nh*8 + 2*t;
        const float bx = nh ? __ldg(lvb + 2*t)     : __ldg(mub + 2*t);
        const float by = nh ? __ldg(lvb + 2*t + 1) : __ldg(mub + 2*t + 1);
        Yh[r*LDYH + c]         = ah[0] + bx;
        Yh[r*LDYH + c + 1]     = ah[1] + by;
        Yh[(r+8)*LDYH + c]     = ah[2] + bx;
        Yh[(r+8)*LDYH + c + 1] = ah[3] + by;
    }
    __syncthreads();

    // ---- loss: thread = (node r = tid>>2, k-pair kg = tid&3) ----
    {
        const int r  = tid >> 2;
        const int kg = tid & 3;
        const int n  = base + r;
        const bool valid = (n < N_NODES);
        float part = 0.f;
        int op = 0;
        float lossA = 0.f, lossB = 0.f;
        if (valid) {
            op = __ldg(op_id + n);
            const float4 muA = *(const float4*)(Yh + r*LDYH);
            const float4 muB = *(const float4*)(Yh + r*LDYH + 4);
            const float4 lvA = *(const float4*)(Yh + r*LDYH + 8);
            const float4 lvB = *(const float4*)(Yh + r*LDYH + 12);
            const float muv[8] = { muA.x, muA.y, muA.z, muA.w, muB.x, muB.y, muB.z, muB.w };
            const float lvv[8] = { lvA.x, lvA.y, lvA.z, lvA.w, lvB.x, lvB.y, lvB.z, lvB.w };
            const float* wrow = opw + (size_t)op * (2 * LDIM * LDIM);
            float mpA = 0.f, mpB = 0.f, lpA = 0.f, lpB = 0.f;
            #pragma unroll
            for (int l = 0; l < LDIM; l++) {
                const float2 wm = __ldg((const float2*)(wrow + l*2*LDIM + 2*kg));
                const float2 wl = __ldg((const float2*)(wrow + l*2*LDIM + LDIM + 2*kg));
                mpA += muv[l] * wm.x; mpB += muv[l] * wm.y;
                lpA += lvv[l] * wl.x; lpB += lvv[l] * wl.y;
            }
            const float2 lab = __ldg((const float2*)(lat + (size_t)n*LDIM + 2*kg));
            const float dA = mpA - lab.x, dB = mpB - lab.y;
            lossA = dA*dA / (2.f*expf(lpA) + 1e-7f) + 0.5f*lpA;
            lossB = dB*dB / (2.f*expf(lpB) + 1e-7f) + 0.5f*lpB;
            part = lossA + lossB;
        }
        part += __shfl_xor_sync(0xffffffffu, part, 1);
        part += __shfl_xor_sync(0xffffffffu, part, 2);
        const float lossn = part * (1.f / LDIM);
        if (valid && kg == 0) {
            atomicAdd(op_loss + op, lossn);
            atomicAdd(op_cnt  + op, 1.f);
        }
        float wval = (valid && kg == 0) ? lossn : 0.f;
        wval += __shfl_xor_sync(0xffffffffu, wval, 4);
        wval += __shfl_xor_sync(0xffffffffu, wval, 8);
        wval += __shfl_xor_sync(0xffffffffu, wval, 16);
        if (lane == 0) sL[w] = wval;
    }
    __syncthreads();
    if (tid == 0) {
        double s = 0.0;
        #pragma unroll
        for (int i = 0; i < 8; i++) s += (double)sL[i];
        atomicAdd(&g_lat_sum, s);
    }
}

// ----------------------------------------------------------------------------
// Kernel 4: finalize
// ----------------------------------------------------------------------------
__global__ void fin_kernel(float* __restrict__ out)
{
    if (threadIdx.x == 0) {
        const double lat_loss = g_lat_sum / (double)N_NODES;
        const double kl = -0.5 * (g_kl_sum / ((double)N_NODES * (double)FDIM));
        out[0] = (float)(lat_loss + kl);
    }
}

// ----------------------------------------------------------------------------
extern "C" void kernel_launch(void* const* d_in, const int* in_sizes, int n_in,
                              void* d_out, int out_size)
{
    const int*   op_id = (const int*)  d_in[0];
    const int*   sv_id = (const int*)  d_in[1];
    const int*   st_id = (const int*)  d_in[2];
    const float* lat   = (const float*)d_in[3];
    const int*   esrc  = (const int*)  d_in[4];
    const int*   edst  = (const int*)  d_in[5];
    const float* eps   = (const float*)d_in[6];
    const float* opE   = (const float*)d_in[7];
    const float* svE   = (const float*)d_in[8];
    const float* stE   = (const float*)d_in[9];
    const float* W1    = (const float*)d_in[10];
    const float* b1    = (const float*)d_in[11];
    const float* W2    = (const float*)d_in[12];
    const float* b2    = (const float*)d_in[13];
    const float* Wself = (const float*)d_in[14];
    const float* Wagg  = (const float*)d_in[15];
    const float* muW   = (const float*)d_in[16];
    const float* mub   = (const float*)d_in[17];
    const float* lvW   = (const float*)d_in[18];
    const float* lvb   = (const float*)d_in[19];
    const float* opw   = (const float*)d_in[20];

    float* out     = (float*)d_out;
    float* op_loss = out + 1;
    float* op_cnt  = out + 1 + OPC;

    const int ENC_SMEM = 26944 * sizeof(float);   // 107776 B
    const int DEC_SMEM = 25344 * sizeof(float);   // 101376 B
    static bool attr_done = false;
    if (!attr_done) {
        cudaFuncSetAttribute(enc_kernel, cudaFuncAttributeMaxDynamicSharedMemorySize, ENC_SMEM);
        cudaFuncSetAttribute(dec_kernel, cudaFuncAttributeMaxDynamicSharedMemorySize, DEC_SMEM);
        attr_done = true;
    }

    const int n_tiles = (N_NODES + TILE - 1) / TILE;   // 7813

    zero_kernel<<<62500, 256>>>(out);

    enc_kernel<<<n_tiles, 256, ENC_SMEM>>>(op_id, sv_id, st_id, lat, eps,
                                           opE, svE, stE, W1, b1, W2, b2);

    scatter_kernel<<<(N_EDGES + 7) / 8, 256>>>(esrc, edst);

    dec_kernel<<<n_tiles, 256, DEC_SMEM>>>(op_id, lat, Wself, Wagg,
                                           muW, mub, lvW, lvb, opw,
                                           op_loss, op_cnt);

    fin_kernel<<<1, 32>>>(out);
}

// round 5
// speedup vs baseline: 9.5143x; 1.2863x over previous
#include <cuda_runtime.h>
#include <cstdint>

#define N_NODES 500000
#define N_EDGES 1000000
#define EMB 64
#define FDIM 128
#define LDIM 8
#define OPC 5000

#define TILE 64

// ---- scratch (no allocations allowed) ----
__device__ float  g_z  [(size_t)N_NODES * FDIM];
__device__ float  g_agg[(size_t)N_NODES * FDIM];
__device__ double g_kl_sum;
__device__ double g_lat_sum;

// ---- helpers ----
__device__ __forceinline__ uint32_t smem_u32(const void* p) {
    uint32_t a;
    asm("{ .reg .u64 t; cvta.to.shared.u64 t, %1; cvt.u32.u64 %0, t; }"
        : "=r"(a) : "l"(p));
    return a;
}
__device__ __forceinline__ void ldsm_x4(uint32_t& r0, uint32_t& r1,
                                        uint32_t& r2, uint32_t& r3,
                                        uint32_t addr) {
    asm volatile("ldmatrix.sync.aligned.m8n8.x4.shared.b16 {%0,%1,%2,%3}, [%4];"
                 : "=r"(r0), "=r"(r1), "=r"(r2), "=r"(r3) : "r"(addr));
}
__device__ __forceinline__ void mma_bf16(float* d, const uint32_t* a,
                                         uint32_t b0, uint32_t b1) {
    asm volatile("mma.sync.aligned.m16n8k16.row.col.f32.bf16.bf16.f32 "
                 "{%0,%1,%2,%3}, {%4,%5,%6,%7}, {%8,%9}, {%0,%1,%2,%3};"
                 : "+f"(d[0]), "+f"(d[1]), "+f"(d[2]), "+f"(d[3])
                 : "r"(a[0]), "r"(a[1]), "r"(a[2]), "r"(a[3]),
                   "r"(b0), "r"(b1));
}
// pack: lo in low half, hi in high half
__device__ __forceinline__ uint32_t bf2(float lo, float hi) {
    uint32_t d;
    asm("cvt.rn.satfinite.bf16x2.f32 %0, %1, %2;" : "=r"(d) : "f"(hi), "f"(lo));
    return d;
}

// ----------------------------------------------------------------------------
// Kernel 0: zero agg scratch, output head, scalar accumulators
// ----------------------------------------------------------------------------
__global__ void zero_kernel(float* __restrict__ out)
{
    size_t i = (size_t)blockIdx.x * blockDim.x + threadIdx.x;
    const size_t tot4 = (size_t)N_NODES * FDIM / 4;
    if (i < tot4) ((float4*)g_agg)[i] = make_float4(0.f, 0.f, 0.f, 0.f);
    if (i < (size_t)(1 + 2*OPC)) out[i] = 0.f;
    if (i == 0) { g_kl_sum = 0.0; g_lat_sum = 0.0; }
}

// ----------------------------------------------------------------------------
// Kernel 1: encoder (bf16 mma), 64-node tile, 256 threads
//   smem: X1 bf16[64][216] | Wp1 u32[32][136] | Hs bf16[64][136]
//   phase2: Wp2 u32[32][264] aliases X1+Wp1
// ----------------------------------------------------------------------------
extern "C" __global__ void __launch_bounds__(256, 2)
enc_kernel(const int*   __restrict__ op_id,
           const int*   __restrict__ sv_id,
           const int*   __restrict__ st_id,
           const float* __restrict__ lat,
           const float* __restrict__ eps,
           const float* __restrict__ opE,
           const float* __restrict__ svE,
           const float* __restrict__ stE,
           const float* __restrict__ W1,
           const float* __restrict__ b1,
           const float* __restrict__ W2,
           const float* __restrict__ b2)
{
    extern __shared__ __align__(16) char smraw[];
    uint16_t* X1  = (uint16_t*)smraw;               // [64][216]
    uint32_t* Wp1 = (uint32_t*)(smraw + 27648);     // [32][136]
    uint16_t* Hs  = (uint16_t*)(smraw + 45056);     // [64][136]
    uint32_t* Wp2 = (uint32_t*)smraw;               // [32][264]
    __shared__ float skl[8];

    const int tid  = threadIdx.x;
    const int lane = tid & 31;
    const int w    = tid >> 5;
    const int base = blockIdx.x * TILE;
    const int g    = lane >> 2;
    const int t    = lane & 3;
    const uint32_t x1b = smem_u32(X1);
    const uint32_t hsb = smem_u32(Hs);

    // ---- gather feats -> bf16 X1 ----
    {
        const int r = tid >> 2, q = tid & 3;
        const int n = base + r;
        uint16_t* row = X1 + r * 216;
        if (n < N_NODES) {
            const int op = op_id[n], sv = sv_id[n], st = st_id[n];
            #pragma unroll
            for (int j = 0; j < 4; j++) {
                float4 v = __ldg((const float4*)(opE + (size_t)op*EMB + q*16 + 4*j));
                *(uint2*)(row + q*16 + 4*j) = make_uint2(bf2(v.x,v.y), bf2(v.z,v.w));
                v = __ldg((const float4*)(svE + (size_t)sv*EMB + q*16 + 4*j));
                *(uint2*)(row + 64 + q*16 + 4*j) = make_uint2(bf2(v.x,v.y), bf2(v.z,v.w));
                v = __ldg((const float4*)(stE + (size_t)st*EMB + q*16 + 4*j));
                *(uint2*)(row + 128 + q*16 + 4*j) = make_uint2(bf2(v.x,v.y), bf2(v.z,v.w));
            }
            if (q == 0) {
                float4 v0 = __ldg((const float4*)(lat + (size_t)n*LDIM));
                float4 v1 = __ldg((const float4*)(lat + (size_t)n*LDIM + 4));
                *(uint2*)(row + 192) = make_uint2(bf2(v0.x,v0.y), bf2(v0.z,v0.w));
                *(uint2*)(row + 196) = make_uint2(bf2(v1.x,v1.y), bf2(v1.z,v1.w));
            } else if (q == 1) {
                *(uint2*)(row + 200) = make_uint2(0u, 0u);
                *(uint2*)(row + 204) = make_uint2(0u, 0u);
            }
        } else {
            #pragma unroll
            for (int j = 0; j < 4; j++) {
                *(uint2*)(row + q*16 + 4*j)       = make_uint2(0u, 0u);
                *(uint2*)(row + 64 + q*16 + 4*j)  = make_uint2(0u, 0u);
                *(uint2*)(row + 128 + q*16 + 4*j) = make_uint2(0u, 0u);
            }
            if (q == 0) {
                *(uint2*)(row + 192) = make_uint2(0u, 0u);
                *(uint2*)(row + 196) = make_uint2(0u, 0u);
            } else if (q == 1) {
                *(uint2*)(row + 200) = make_uint2(0u, 0u);
                *(uint2*)(row + 204) = make_uint2(0u, 0u);
            }
        }
    }
    __syncthreads();

    // ---- GEMM1: h = relu(X1 @ W1 + b1), K=208 (13 k16 steps, 4 chunks) ----
    float acc1[2][4][4];
    #pragma unroll
    for (int i = 0; i < 2; i++)
        #pragma unroll
        for (int nt = 0; nt < 4; nt++)
            #pragma unroll
            for (int j = 0; j < 4; j++) acc1[i][nt][j] = 0.f;

    const int mp  = w & 1;
    const int nq1 = w >> 1;   // 0..3

    for (int ch = 0; ch < 4; ch++) {
        #pragma unroll
        for (int i = 0; i < 4; i++) {
            const int idx = tid + i*256;          // 1024 = 32 kp x 32 n4
            const int kp_l = idx >> 5, n4 = (idx & 31) << 2;
            const int k0 = ch*64 + 2*kp_l;
            float4 va = make_float4(0.f,0.f,0.f,0.f);
            float4 vb = va;
            if (k0 < 200)     va = __ldg((const float4*)(W1 + (size_t)k0*FDIM + n4));
            if (k0 + 1 < 200) vb = __ldg((const float4*)(W1 + (size_t)(k0+1)*FDIM + n4));
            *(uint4*)(Wp1 + kp_l*136 + n4) =
                make_uint4(bf2(va.x,vb.x), bf2(va.y,vb.y), bf2(va.z,vb.z), bf2(va.w,vb.w));
        }
        __syncthreads();
        const int nsteps = (ch < 3) ? 4 : 1;
        for (int s = 0; s < nsteps; s++) {
            const int koff = s << 3;
            const int kidx = ch*64 + (s << 4);
            uint32_t a0[4], a1[4];
            const uint32_t addr = x1b + (mp*32 + (lane & 15)) * 432
                                + ((kidx + ((lane >> 4) << 3)) << 1);
            ldsm_x4(a0[0], a0[1], a0[2], a0[3], addr);
            ldsm_x4(a1[0], a1[1], a1[2], a1[3], addr + 16*432);
            #pragma unroll
            for (int nt = 0; nt < 4; nt++) {
                const int ncol = nq1*32 + nt*8 + g;
                const uint32_t b0 = Wp1[(koff + t)*136 + ncol];
                const uint32_t bv = Wp1[(koff + 4 + t)*136 + ncol];
                mma_bf16(acc1[0][nt], a0, b0, bv);
                mma_bf16(acc1[1][nt], a1, b0, bv);
            }
        }
        __syncthreads();
    }

    // ---- h = relu(+bias) -> Hs bf16 ----
    #pragma unroll
    for (int i = 0; i < 2; i++)
        #pragma unroll
        for (int nt = 0; nt < 4; nt++) {
            const int r = mp*32 + i*16 + g;
            const int c = nq1*32 + nt*8 + 2*t;
            const float bA = __ldg(b1 + c), bB = __ldg(b1 + c + 1);
            ((uint32_t*)Hs)[r*68 + (c>>1)] =
                bf2(fmaxf(acc1[i][nt][0] + bA, 0.f), fmaxf(acc1[i][nt][1] + bB, 0.f));
            ((uint32_t*)Hs)[(r+8)*68 + (c>>1)] =
                bf2(fmaxf(acc1[i][nt][2] + bA, 0.f), fmaxf(acc1[i][nt][3] + bB, 0.f));
        }
    __syncthreads();

    // ---- GEMM2: y = h @ W2, K=128 (8 steps, 2 chunks), paired mu/lv per warp ----
    float acc2[4][4][4];
    #pragma unroll
    for (int mi = 0; mi < 4; mi++)
        #pragma unroll
        for (int j = 0; j < 4; j++)
            #pragma unroll
            for (int e = 0; e < 4; e++) acc2[mi][j][e] = 0.f;

    for (int ch = 0; ch < 2; ch++) {
        #pragma unroll
        for (int i = 0; i < 8; i++) {
            const int idx = tid + i*256;          // 2048 = 32 kp x 64 n4
            const int kp_l = idx >> 6, n4 = (idx & 63) << 2;
            const int k0 = ch*64 + 2*kp_l;
            const float4 va = __ldg((const float4*)(W2 + (size_t)k0*(2*FDIM) + n4));
            const float4 vb = __ldg((const float4*)(W2 + (size_t)(k0+1)*(2*FDIM) + n4));
            *(uint4*)(Wp2 + kp_l*264 + n4) =
                make_uint4(bf2(va.x,vb.x), bf2(va.y,vb.y), bf2(va.z,vb.z), bf2(va.w,vb.w));
        }
        __syncthreads();
        for (int s = 0; s < 4; s++) {
            const int koff = s << 3;
            const int kidx = ch*64 + (s << 4);
            uint32_t a[4][4];
            #pragma unroll
            for (int mi = 0; mi < 4; mi++) {
                const uint32_t addr = hsb + (mi*16 + (lane & 15)) * 272
                                    + ((kidx + ((lane >> 4) << 3)) << 1);
                ldsm_x4(a[mi][0], a[mi][1], a[mi][2], a[mi][3], addr);
            }
            #pragma unroll
            for (int j = 0; j < 4; j++) {
                const int cb = (j < 2) ? (w*16 + 8*j) : (FDIM + w*16 + 8*(j-2));
                const uint32_t b0 = Wp2[(koff + t)*264 + cb + g];
                const uint32_t bv = Wp2[(koff + 4 + t)*264 + cb + g];
                #pragma unroll
                for (int mi = 0; mi < 4; mi++)
                    mma_bf16(acc2[mi][j], a[mi], b0, bv);
            }
        }
        __syncthreads();
    }

    // ---- epilogue in registers: z = mu + exp(0.5*tanh(lv))*eps, KL ----
    float klw = 0.f;
    #pragma unroll
    for (int j = 0; j < 2; j++) {
        const int c = w*16 + 8*j + 2*t;
        const float bmx = __ldg(b2 + c),        bmy = __ldg(b2 + c + 1);
        const float blx = __ldg(b2 + FDIM + c), bly = __ldg(b2 + FDIM + c + 1);
        #pragma unroll
        for (int mi = 0; mi < 4; mi++) {
            const float* fm = acc2[mi][j];
            const float* fl = acc2[mi][j+2];
            #pragma unroll
            for (int half = 0; half < 2; half++) {
                const int r = mi*16 + g + half*8;
                const int n = base + r;
                if (n < N_NODES) {
                    const float mux = fm[2*half]   + bmx;
                    const float muy = fm[2*half+1] + bmy;
                    const float lvx = tanhf(fl[2*half]   + blx);
                    const float lvy = tanhf(fl[2*half+1] + bly);
                    const float2 e = __ldg((const float2*)(eps + (size_t)n*FDIM + c));
                    float2 z;
                    z.x = mux + expf(0.5f*lvx) * e.x;
                    z.y = muy + expf(0.5f*lvy) * e.y;
                    *(float2*)(g_z + (size_t)n*FDIM + c) = z;
                    klw += lvx + 1.f - expf(lvx) - mux*mux;
                    klw += lvy + 1.f - expf(lvy) - muy*muy;
                }
            }
        }
    }
    #pragma unroll
    for (int o = 16; o; o >>= 1) klw += __shfl_xor_sync(0xffffffffu, klw, o);
    if (lane == 0) skl[w] = klw;
    __syncthreads();
    if (tid == 0) {
        double s = 0.0;
        #pragma unroll
        for (int i = 0; i < 8; i++) s += (double)skl[i];
        atomicAdd(&g_kl_sum, s);
    }
}

// ----------------------------------------------------------------------------
// Kernel 2: edge scatter-add
// ----------------------------------------------------------------------------
__global__ void scatter_kernel(const int* __restrict__ esrc,
                               const int* __restrict__ edst)
{
    const int e    = (blockIdx.x * blockDim.x + threadIdx.x) >> 5;
    const int lane = threadIdx.x & 31;
    if (e >= N_EDGES) return;
    const int s = __ldg(esrc + e);
    const int d = __ldg(edst + e);
    const float4 v = ((const float4*)g_z)[(size_t)s * 32 + lane];
    float* p = &g_agg[(size_t)d * FDIM + 4*lane];
    asm volatile("red.global.add.v4.f32 [%0], {%1, %2, %3, %4};"
                 :: "l"(p), "f"(v.x), "f"(v.y), "f"(v.z), "f"(v.w) : "memory");
}

// ----------------------------------------------------------------------------
// Kernel 3: decoder (bf16 mma) + heads mma + thread-parallel loss
//   smem: X bf16[64][264] | Wp u32[64][136]
//   after GEMM: Yd bf16[64][136] @0 | Whp u32[64][24] @17408 | Yh f32[64][20] @23552
// ----------------------------------------------------------------------------
extern "C" __global__ void __launch_bounds__(256, 3)
dec_kernel(const int*   __restrict__ op_id,
           const float* __restrict__ lat,
           const float* __restrict__ Wself,
           const float* __restrict__ Wagg,
           const float* __restrict__ muW,
           const float* __restrict__ mub,
           const float* __restrict__ lvW,
           const float* __restrict__ lvb,
           const float* __restrict__ opw,
           float* __restrict__ op_loss,
           float* __restrict__ op_cnt)
{
    extern __shared__ __align__(16) char smraw[];
    uint16_t* X   = (uint16_t*)smraw;               // [64][264]
    uint32_t* Wp  = (uint32_t*)(smraw + 33792);     // [64][136]
    uint16_t* Yd  = (uint16_t*)smraw;               // [64][136]
    uint32_t* Whp = (uint32_t*)(smraw + 17408);     // [64][24]
    float*    Yh  = (float*)(smraw + 23552);        // [64][20]
    __shared__ float sL[8];

    const int tid  = threadIdx.x;
    const int lane = tid & 31;
    const int w    = tid >> 5;
    const int base = blockIdx.x * TILE;
    const int g    = lane >> 2;
    const int t    = lane & 3;
    const uint32_t xb  = smem_u32(X);
    const uint32_t ydb = smem_u32(Yd);

    // ---- gather z/agg -> bf16 X ----
    #pragma unroll
    for (int it = 0; it < 8; it++) {
        const int idx = tid + it*256;
        const int r = idx >> 5, c4 = (idx & 31) << 2;
        const int n = base + r;
        uint16_t* row = X + r * 264;
        if (n < N_NODES) {
            const float4 vz = __ldg((const float4*)(g_z   + (size_t)n*FDIM + c4));
            const float4 va = __ldg((const float4*)(g_agg + (size_t)n*FDIM + c4));
            *(uint2*)(row + c4)        = make_uint2(bf2(vz.x,vz.y), bf2(vz.z,vz.w));
            *(uint2*)(row + FDIM + c4) = make_uint2(bf2(va.x,va.y), bf2(va.z,va.w));
        } else {
            *(uint2*)(row + c4)        = make_uint2(0u, 0u);
            *(uint2*)(row + FDIM + c4) = make_uint2(0u, 0u);
        }
    }
    __syncthreads();

    // ---- GEMM: yd = relu([z|agg] @ [Wself;Wagg]), K=256 (16 steps, 2 chunks) ----
    float acc[2][4][4];
    #pragma unroll
    for (int i = 0; i < 2; i++)
        #pragma unroll
        for (int nt = 0; nt < 4; nt++)
            #pragma unroll
            for (int e = 0; e < 4; e++) acc[i][nt][e] = 0.f;

    const int mp  = w & 1;
    const int nqd = w >> 1;   // 0..3

    for (int ch = 0; ch < 2; ch++) {
        const float* Wsrc = ch ? Wagg : Wself;
        #pragma unroll
        for (int i = 0; i < 8; i++) {
            const int idx = tid + i*256;          // 2048 = 64 kp x 32 n4
            const int kp_l = idx >> 5, n4 = (idx & 31) << 2;
            const int k0 = 2*kp_l;
            const float4 va = __ldg((const float4*)(Wsrc + (size_t)k0*FDIM + n4));
            const float4 vb = __ldg((const float4*)(Wsrc + (size_t)(k0+1)*FDIM + n4));
            *(uint4*)(Wp + kp_l*136 + n4) =
                make_uint4(bf2(va.x,vb.x), bf2(va.y,vb.y), bf2(va.z,vb.z), bf2(va.w,vb.w));
        }
        __syncthreads();
        for (int s = 0; s < 8; s++) {
            const int koff = s << 3;
            const int kidx = ch*FDIM + (s << 4);
            uint32_t a0[4], a1[4];
            const uint32_t addr = xb + (mp*32 + (lane & 15)) * 528
                                + ((kidx + ((lane >> 4) << 3)) << 1);
            ldsm_x4(a0[0], a0[1], a0[2], a0[3], addr);
            ldsm_x4(a1[0], a1[1], a1[2], a1[3], addr + 16*528);
            #pragma unroll
            for (int nt = 0; nt < 4; nt++) {
                const int ncol = nqd*32 + nt*8 + g;
                const uint32_t b0 = Wp[(koff + t)*136 + ncol];
                const uint32_t bv = Wp[(koff + 4 + t)*136 + ncol];
                mma_bf16(acc[0][nt], a0, b0, bv);
                mma_bf16(acc[1][nt], a1, b0, bv);
            }
        }
        __syncthreads();
    }

    // ---- yd = relu -> Yd bf16 ; stage heads weights Whp ----
    #pragma unroll
    for (int i = 0; i < 2; i++)
        #pragma unroll
        for (int nt = 0; nt < 4; nt++) {
            const int r = mp*32 + i*16 + g;
            const int c = nqd*32 + nt*8 + 2*t;
            ((uint32_t*)Yd)[r*68 + (c>>1)] =
                bf2(fmaxf(acc[i][nt][0], 0.f), fmaxf(acc[i][nt][1], 0.f));
            ((uint32_t*)Yd)[(r+8)*68 + (c>>1)] =
                bf2(fmaxf(acc[i][nt][2], 0.f), fmaxf(acc[i][nt][3], 0.f));
        }
    #pragma unroll
    for (int i = 0; i < 4; i++) {
        const int idx = tid + i*256;              // 1024 = 64 kp x 16 n
        const int kp = idx >> 4, nn = idx & 15;
        float lo, hi;
        if (nn < 8) {
            lo = __ldg(muW + (size_t)(2*kp)*LDIM + nn);
            hi = __ldg(muW + (size_t)(2*kp+1)*LDIM + nn);
        } else {
            lo = __ldg(lvW + (size_t)(2*kp)*LDIM + nn - 8);
            hi = __ldg(lvW + (size_t)(2*kp+1)*LDIM + nn - 8);
        }
        Whp[kp*24 + nn] = bf2(lo, hi);
    }
    __syncthreads();

    // ---- heads mma: Yh[64][16] = yd @ [muW|lvW] + bias ----
    {
        const int mt = w & 3;
        const int nh = (w >> 2) & 1;
        float ah[4] = {0.f, 0.f, 0.f, 0.f};
        for (int s = 0; s < 8; s++) {
            const int koff = s << 3;
            uint32_t a[4];
            const uint32_t addr = ydb + (mt*16 + (lane & 15)) * 272
                                + (((s << 4) + ((lane >> 4) << 3)) << 1);
            ldsm_x4(a[0], a[1], a[2], a[3], addr);
            const uint32_t b0 = Whp[(koff + t)*24 + nh*8 + g];
            const uint32_t bv = Whp[(koff + 4 + t)*24 + nh*8 + g];
            mma_bf16(ah, a, b0, bv);
        }
        const int r = mt*16 + g;
        const int c = nh*8 + 2*t;
        const float* bp = nh ? lvb : mub;
        const float bx = __ldg(bp + 2*t), by = __ldg(bp + 2*t + 1);
        Yh[r*20 + c]         = ah[0] + bx;
        Yh[r*20 + c + 1]     = ah[1] + by;
        Yh[(r+8)*20 + c]     = ah[2] + bx;
        Yh[(r+8)*20 + c + 1] = ah[3] + by;
    }
    __syncthreads();

    // ---- loss: thread = (node r = tid>>2, k-pair kg = tid&3) ----
    {
        const int r  = tid >> 2;
        const int kg = tid & 3;
        const int n  = base + r;
        const bool valid = (n < N_NODES);
        float part = 0.f;
        int op = 0;
        if (valid) {
            op = __ldg(op_id + n);
            const float4 muA = *(const float4*)(Yh + r*20);
            const float4 muB = *(const float4*)(Yh + r*20 + 4);
            const float4 lvA = *(const float4*)(Yh + r*20 + 8);
            const float4 lvB = *(const float4*)(Yh + r*20 + 12);
            const float muv[8] = { muA.x, muA.y, muA.z, muA.w, muB.x, muB.y, muB.z, muB.w };
            const float lvv[8] = { lvA.x, lvA.y, lvA.z, lvA.w, lvB.x, lvB.y, lvB.z, lvB.w };
            const float* wrow = opw + (size_t)op * (2 * LDIM * LDIM);
            float mpA = 0.f, mpB = 0.f, lpA = 0.f, lpB = 0.f;
            #pragma unroll
            for (int l = 0; l < LDIM; l++) {
                const float2 wm = __ldg((const float2*)(wrow + l*2*LDIM + 2*kg));
                const float2 wl = __ldg((const float2*)(wrow + l*2*LDIM + LDIM + 2*kg));
                mpA += muv[l] * wm.x; mpB += muv[l] * wm.y;
                lpA += lvv[l] * wl.x; lpB += lvv[l] * wl.y;
            }
            const float2 lab = __ldg((const float2*)(lat + (size_t)n*LDIM + 2*kg));
            const float dA = mpA - lab.x, dB = mpB - lab.y;
            part = dA*dA / (2.f*expf(lpA) + 1e-7f) + 0.5f*lpA
                 + dB*dB / (2.f*expf(lpB) + 1e-7f) + 0.5f*lpB;
        }
        part += __shfl_xor_sync(0xffffffffu, part, 1);
        part += __shfl_xor_sync(0xffffffffu, part, 2);
        const float lossn = part * (1.f / LDIM);
        if (valid && kg == 0) {
            atomicAdd(op_loss + op, lossn);
            atomicAdd(op_cnt  + op, 1.f);
        }
        float wval = (valid && kg == 0) ? lossn : 0.f;
        wval += __shfl_xor_sync(0xffffffffu, wval, 4);
        wval += __shfl_xor_sync(0xffffffffu, wval, 8);
        wval += __shfl_xor_sync(0xffffffffu, wval, 16);
        if (lane == 0) sL[w] = wval;
    }
    __syncthreads();
    if (tid == 0) {
        double s = 0.0;
        #pragma unroll
        for (int i = 0; i < 8; i++) s += (double)sL[i];
        atomicAdd(&g_lat_sum, s);
    }
}

// ----------------------------------------------------------------------------
// Kernel 4: finalize
// ----------------------------------------------------------------------------
__global__ void fin_kernel(float* __restrict__ out)
{
    if (threadIdx.x == 0) {
        const double lat_loss = g_lat_sum / (double)N_NODES;
        const double kl = -0.5 * (g_kl_sum / ((double)N_NODES * (double)FDIM));
        out[0] = (float)(lat_loss + kl);
    }
}

// ----------------------------------------------------------------------------
extern "C" void kernel_launch(void* const* d_in, const int* in_sizes, int n_in,
                              void* d_out, int out_size)
{
    const int*   op_id = (const int*)  d_in[0];
    const int*   sv_id = (const int*)  d_in[1];
    const int*   st_id = (const int*)  d_in[2];
    const float* lat   = (const float*)d_in[3];
    const int*   esrc  = (const int*)  d_in[4];
    const int*   edst  = (const int*)  d_in[5];
    const float* eps   = (const float*)d_in[6];
    const float* opE   = (const float*)d_in[7];
    const float* svE   = (const float*)d_in[8];
    const float* stE   = (const float*)d_in[9];
    const float* W1    = (const float*)d_in[10];
    const float* b1    = (const float*)d_in[11];
    const float* W2    = (const float*)d_in[12];
    const float* b2    = (const float*)d_in[13];
    const float* Wself = (const float*)d_in[14];
    const float* Wagg  = (const float*)d_in[15];
    const float* muW   = (const float*)d_in[16];
    const float* mub   = (const float*)d_in[17];
    const float* lvW   = (const float*)d_in[18];
    const float* lvb   = (const float*)d_in[19];
    const float* opw   = (const float*)d_in[20];

    float* out     = (float*)d_out;
    float* op_loss = out + 1;
    float* op_cnt  = out + 1 + OPC;

    const int ENC_SMEM = 62464;
    const int DEC_SMEM = 68608;
    static bool attr_done = false;
    if (!attr_done) {
        cudaFuncSetAttribute(enc_kernel, cudaFuncAttributeMaxDynamicSharedMemorySize, ENC_SMEM);
        cudaFuncSetAttribute(dec_kernel, cudaFuncAttributeMaxDynamicSharedMemorySize, DEC_SMEM);
        attr_done = true;
    }

    const int n_tiles = (N_NODES + TILE - 1) / TILE;   // 7813

    zero_kernel<<<62500, 256>>>(out);

    enc_kernel<<<n_tiles, 256, ENC_SMEM>>>(op_id, sv_id, st_id, lat, eps,
                                           opE, svE, stE, W1, b1, W2, b2);

    scatter_kernel<<<(N_EDGES + 7) / 8, 256>>>(esrc, edst);

    dec_kernel<<<n_tiles, 256, DEC_SMEM>>>(op_id, lat, Wself, Wagg,
                                           muW, mub, lvW, lvb, opw,
                                           op_loss, op_cnt);

    fin_kernel<<<1, 32>>>(out);
}

// round 6
// speedup vs baseline: 11.0167x; 1.1579x over previous
#include <cuda_runtime.h>
#include <cstdint>

#define N_NODES 500000
#define N_EDGES 1000000
#define EMB 64
#define FDIM 128
#define LDIM 8
#define OPC 5000

#define TILE 64

// ---- scratch (no allocations allowed) ----
__device__ uint16_t g_zh [(size_t)N_NODES * FDIM];   // z in bf16 (128 MB)
__device__ float    g_agg[(size_t)N_NODES * FDIM];   // 256 MB
__device__ double   g_kl_sum;
__device__ double   g_lat_sum;

// ---- pre-packed weights/embeddings (bf16) ----
__device__ uint32_t g_pW1[128 * 128];    // [kpair][n] for W1 (k padded to 256)
__device__ uint32_t g_pW2[64 * 256];     // [kpair][n] for W2
__device__ uint32_t g_pWd[128 * 128];    // [kpair][n], kp<64 Wself, kp>=64 Wagg
__device__ uint32_t g_pWh[64 * 16];      // [kpair][mu0..7 | lv0..7]
__device__ uint16_t g_pOpE[OPC * EMB];
__device__ uint16_t g_pSvE[2000 * EMB];
__device__ uint16_t g_pStE[16 * EMB];

// ---- helpers ----
__device__ __forceinline__ uint32_t smem_u32(const void* p) {
    uint32_t a;
    asm("{ .reg .u64 t; cvta.to.shared.u64 t, %1; cvt.u32.u64 %0, t; }"
        : "=r"(a) : "l"(p));
    return a;
}
__device__ __forceinline__ void ldsm_x4(uint32_t& r0, uint32_t& r1,
                                        uint32_t& r2, uint32_t& r3,
                                        uint32_t addr) {
    asm volatile("ldmatrix.sync.aligned.m8n8.x4.shared.b16 {%0,%1,%2,%3}, [%4];"
                 : "=r"(r0), "=r"(r1), "=r"(r2), "=r"(r3) : "r"(addr));
}
__device__ __forceinline__ void mma_bf16(float* d, const uint32_t* a,
                                         uint32_t b0, uint32_t b1) {
    asm volatile("mma.sync.aligned.m16n8k16.row.col.f32.bf16.bf16.f32 "
                 "{%0,%1,%2,%3}, {%4,%5,%6,%7}, {%8,%9}, {%0,%1,%2,%3};"
                 : "+f"(d[0]), "+f"(d[1]), "+f"(d[2]), "+f"(d[3])
                 : "r"(a[0]), "r"(a[1]), "r"(a[2]), "r"(a[3]),
                   "r"(b0), "r"(b1));
}
__device__ __forceinline__ uint32_t bf2(float lo, float hi) {
    uint32_t d;
    asm("cvt.rn.satfinite.bf16x2.f32 %0, %1, %2;" : "=r"(d) : "f"(hi), "f"(lo));
    return d;
}
__device__ __forceinline__ float2 up_bf2(uint32_t u) {
    float2 r;
    r.x = __uint_as_float(u << 16);
    r.y = __uint_as_float(u & 0xffff0000u);
    return r;
}

// ----------------------------------------------------------------------------
// Kernel P: pack weights + embeddings to bf16
// ----------------------------------------------------------------------------
__global__ void prep_kernel(const float* __restrict__ W1,
                            const float* __restrict__ W2,
                            const float* __restrict__ Wself,
                            const float* __restrict__ Wagg,
                            const float* __restrict__ muW,
                            const float* __restrict__ lvW,
                            const float* __restrict__ opE,
                            const float* __restrict__ svE,
                            const float* __restrict__ stE)
{
    const int i = blockIdx.x * blockDim.x + threadIdx.x;
    if (i < 16384) {                                     // pW1
        const int kp = i >> 7, n = i & 127;
        const int k0 = 2 * kp;
        const float lo = (k0 < 200)     ? __ldg(W1 + (size_t)k0 * FDIM + n)     : 0.f;
        const float hi = (k0 + 1 < 200) ? __ldg(W1 + (size_t)(k0+1) * FDIM + n) : 0.f;
        g_pW1[i] = bf2(lo, hi);
    } else if (i < 32768) {                              // pW2
        const int j = i - 16384;
        const int kp = j >> 8, n = j & 255;
        const int k0 = 2 * kp;
        g_pW2[j] = bf2(__ldg(W2 + (size_t)k0 * 256 + n),
                       __ldg(W2 + (size_t)(k0+1) * 256 + n));
    } else if (i < 49152) {                              // pWd
        const int j = i - 32768;
        const int kp = j >> 7, n = j & 127;
        const float* src = (kp < 64) ? Wself : Wagg;
        const int k0 = (kp < 64) ? 2*kp : 2*(kp - 64);
        g_pWd[j] = bf2(__ldg(src + (size_t)k0 * FDIM + n),
                       __ldg(src + (size_t)(k0+1) * FDIM + n));
    } else if (i < 50176) {                              // pWh
        const int j = i - 49152;
        const int kp = j >> 4, nn = j & 15;
        float lo, hi;
        if (nn < 8) {
            lo = __ldg(muW + (size_t)(2*kp) * LDIM + nn);
            hi = __ldg(muW + (size_t)(2*kp+1) * LDIM + nn);
        } else {
            lo = __ldg(lvW + (size_t)(2*kp) * LDIM + nn - 8);
            hi = __ldg(lvW + (size_t)(2*kp+1) * LDIM + nn - 8);
        }
        g_pWh[j] = bf2(lo, hi);
    } else if (i < 210176) {                             // pOpE (u32 pairs)
        const int j = i - 50176;
        const float2 v = __ldg((const float2*)(opE + 2*(size_t)j));
        ((uint32_t*)g_pOpE)[j] = bf2(v.x, v.y);
    } else if (i < 274176) {                             // pSvE
        const int j = i - 210176;
        const float2 v = __ldg((const float2*)(svE + 2*(size_t)j));
        ((uint32_t*)g_pSvE)[j] = bf2(v.x, v.y);
    } else if (i < 274688) {                             // pStE
        const int j = i - 274176;
        const float2 v = __ldg((const float2*)(stE + 2*(size_t)j));
        ((uint32_t*)g_pStE)[j] = bf2(v.x, v.y);
    }
}

// ----------------------------------------------------------------------------
// Kernel 0: zero agg scratch, output head, scalar accumulators
// ----------------------------------------------------------------------------
__global__ void zero_kernel(float* __restrict__ out)
{
    size_t i = (size_t)blockIdx.x * blockDim.x + threadIdx.x;
    const size_t tot4 = (size_t)N_NODES * FDIM / 4;
    if (i < tot4) ((float4*)g_agg)[i] = make_float4(0.f, 0.f, 0.f, 0.f);
    if (i < (size_t)(1 + 2*OPC)) out[i] = 0.f;
    if (i == 0) { g_kl_sum = 0.0; g_lat_sum = 0.0; }
}

// ----------------------------------------------------------------------------
// Kernel 1: encoder (bf16 mma), 64-node tile, 256 threads
// ----------------------------------------------------------------------------
extern "C" __global__ void __launch_bounds__(256, 2)
enc_kernel(const int*   __restrict__ op_id,
           const int*   __restrict__ sv_id,
           const int*   __restrict__ st_id,
           const float* __restrict__ lat,
           const float* __restrict__ eps,
           const float* __restrict__ b1,
           const float* __restrict__ b2)
{
    extern __shared__ __align__(16) char smraw[];
    uint16_t* X1  = (uint16_t*)smraw;               // [64][216]
    uint32_t* Wp1 = (uint32_t*)(smraw + 27648);     // [32][136]
    uint16_t* Hs  = (uint16_t*)(smraw + 45056);     // [64][136]
    uint32_t* Wp2 = (uint32_t*)smraw;               // [32][264] (aliases X1)
    __shared__ float skl[8];

    const int tid  = threadIdx.x;
    const int lane = tid & 31;
    const int w    = tid >> 5;
    const int base = blockIdx.x * TILE;
    const int g    = lane >> 2;
    const int t    = lane & 3;
    const uint32_t x1b = smem_u32(X1);
    const uint32_t hsb = smem_u32(Hs);

    // ---- gather feats (pre-packed bf16 copies) ----
    {
        const int r = tid >> 2, q = tid & 3;
        const int n = base + r;
        uint16_t* row = X1 + r * 216;
        if (n < N_NODES) {
            const int op = op_id[n], sv = sv_id[n], st = st_id[n];
            const uint4* so = (const uint4*)(g_pOpE + (size_t)op*EMB + q*16);
            const uint4* ss = (const uint4*)(g_pSvE + (size_t)sv*EMB + q*16);
            const uint4* st4 = (const uint4*)(g_pStE + (size_t)st*EMB + q*16);
            *(uint4*)(row + q*16)          = __ldg(so);
            *(uint4*)(row + q*16 + 8)      = __ldg(so + 1);
            *(uint4*)(row + 64 + q*16)     = __ldg(ss);
            *(uint4*)(row + 64 + q*16 + 8) = __ldg(ss + 1);
            *(uint4*)(row + 128 + q*16)    = __ldg(st4);
            *(uint4*)(row + 128 + q*16 + 8)= __ldg(st4 + 1);
            if (q == 0) {
                const float4 v0 = __ldg((const float4*)(lat + (size_t)n*LDIM));
                const float4 v1 = __ldg((const float4*)(lat + (size_t)n*LDIM + 4));
                *(uint4*)(row + 192) = make_uint4(bf2(v0.x,v0.y), bf2(v0.z,v0.w),
                                                  bf2(v1.x,v1.y), bf2(v1.z,v1.w));
            } else if (q == 1) {
                *(uint4*)(row + 200) = make_uint4(0u,0u,0u,0u);
            }
        } else {
            const uint4 z4 = make_uint4(0u,0u,0u,0u);
            *(uint4*)(row + q*16)           = z4;
            *(uint4*)(row + q*16 + 8)       = z4;
            *(uint4*)(row + 64 + q*16)      = z4;
            *(uint4*)(row + 64 + q*16 + 8)  = z4;
            *(uint4*)(row + 128 + q*16)     = z4;
            *(uint4*)(row + 128 + q*16 + 8) = z4;
            if (q == 0)      *(uint4*)(row + 192) = z4;
            else if (q == 1) *(uint4*)(row + 200) = z4;
        }
    }
    __syncthreads();

    // ---- GEMM1: h = relu(X1 @ W1 + b1), K=208 ----
    float acc1[2][4][4];
    #pragma unroll
    for (int i = 0; i < 2; i++)
        #pragma unroll
        for (int nt = 0; nt < 4; nt++)
            #pragma unroll
            for (int j = 0; j < 4; j++) acc1[i][nt][j] = 0.f;

    const int mp  = w & 1;
    const int nq1 = w >> 1;

    for (int ch = 0; ch < 4; ch++) {
        #pragma unroll
        for (int i = 0; i < 4; i++) {
            const int idx = tid + i*256;
            const int kp_l = idx >> 5, n4 = (idx & 31) << 2;
            *(uint4*)(Wp1 + kp_l*136 + n4) =
                __ldg((const uint4*)(g_pW1 + (size_t)(ch*32 + kp_l)*FDIM + n4));
        }
        __syncthreads();
        const int nsteps = (ch < 3) ? 4 : 1;
        for (int s = 0; s < nsteps; s++) {
            const int koff = s << 3;
            const int kidx = ch*64 + (s << 4);
            uint32_t a0[4], a1[4];
            const uint32_t addr = x1b + (mp*32 + (lane & 15)) * 432
                                + ((kidx + ((lane >> 4) << 3)) << 1);
            ldsm_x4(a0[0], a0[1], a0[2], a0[3], addr);
            ldsm_x4(a1[0], a1[1], a1[2], a1[3], addr + 16*432);
            #pragma unroll
            for (int nt = 0; nt < 4; nt++) {
                const int ncol = nq1*32 + nt*8 + g;
                const uint32_t b0 = Wp1[(koff + t)*136 + ncol];
                const uint32_t bv = Wp1[(koff + 4 + t)*136 + ncol];
                mma_bf16(acc1[0][nt], a0, b0, bv);
                mma_bf16(acc1[1][nt], a1, b0, bv);
            }
        }
        __syncthreads();
    }

    // ---- h = relu(+bias) -> Hs bf16 ----
    #pragma unroll
    for (int i = 0; i < 2; i++)
        #pragma unroll
        for (int nt = 0; nt < 4; nt++) {
            const int r = mp*32 + i*16 + g;
            const int c = nq1*32 + nt*8 + 2*t;
            const float bA = __ldg(b1 + c), bB = __ldg(b1 + c + 1);
            ((uint32_t*)Hs)[r*68 + (c>>1)] =
                bf2(fmaxf(acc1[i][nt][0] + bA, 0.f), fmaxf(acc1[i][nt][1] + bB, 0.f));
            ((uint32_t*)Hs)[(r+8)*68 + (c>>1)] =
                bf2(fmaxf(acc1[i][nt][2] + bA, 0.f), fmaxf(acc1[i][nt][3] + bB, 0.f));
        }
    __syncthreads();

    // ---- GEMM2: y = h @ W2, K=128, N=256, paired mu/lv per warp ----
    float acc2[4][4][4];
    #pragma unroll
    for (int mi = 0; mi < 4; mi++)
        #pragma unroll
        for (int j = 0; j < 4; j++)
            #pragma unroll
            for (int e = 0; e < 4; e++) acc2[mi][j][e] = 0.f;

    for (int ch = 0; ch < 2; ch++) {
        #pragma unroll
        for (int i = 0; i < 8; i++) {
            const int idx = tid + i*256;
            const int kp_l = idx >> 6, n4 = (idx & 63) << 2;
            *(uint4*)(Wp2 + kp_l*264 + n4) =
                __ldg((const uint4*)(g_pW2 + (size_t)(ch*32 + kp_l)*256 + n4));
        }
        __syncthreads();
        for (int s = 0; s < 4; s++) {
            const int koff = s << 3;
            const int kidx = ch*64 + (s << 4);
            uint32_t a[4][4];
            #pragma unroll
            for (int mi = 0; mi < 4; mi++) {
                const uint32_t addr = hsb + (mi*16 + (lane & 15)) * 272
                                    + ((kidx + ((lane >> 4) << 3)) << 1);
                ldsm_x4(a[mi][0], a[mi][1], a[mi][2], a[mi][3], addr);
            }
            #pragma unroll
            for (int j = 0; j < 4; j++) {
                const int cb = (j < 2) ? (w*16 + 8*j) : (FDIM + w*16 + 8*(j-2));
                const uint32_t b0 = Wp2[(koff + t)*264 + cb + g];
                const uint32_t bv = Wp2[(koff + 4 + t)*264 + cb + g];
                #pragma unroll
                for (int mi = 0; mi < 4; mi++)
                    mma_bf16(acc2[mi][j], a[mi], b0, bv);
            }
        }
        __syncthreads();
    }

    // ---- epilogue in registers: z = mu + exp(0.5*tanh(lv))*eps -> g_zh ----
    float klw = 0.f;
    #pragma unroll
    for (int j = 0; j < 2; j++) {
        const int c = w*16 + 8*j + 2*t;
        const float bmx = __ldg(b2 + c),        bmy = __ldg(b2 + c + 1);
        const float blx = __ldg(b2 + FDIM + c), bly = __ldg(b2 + FDIM + c + 1);
        #pragma unroll
        for (int mi = 0; mi < 4; mi++) {
            const float* fm = acc2[mi][j];
            const float* fl = acc2[mi][j+2];
            #pragma unroll
            for (int half = 0; half < 2; half++) {
                const int r = mi*16 + g + half*8;
                const int n = base + r;
                if (n < N_NODES) {
                    const float mux = fm[2*half]   + bmx;
                    const float muy = fm[2*half+1] + bmy;
                    const float lvx = tanhf(fl[2*half]   + blx);
                    const float lvy = tanhf(fl[2*half+1] + bly);
                    const float2 e = __ldg((const float2*)(eps + (size_t)n*FDIM + c));
                    const float zx = mux + expf(0.5f*lvx) * e.x;
                    const float zy = muy + expf(0.5f*lvy) * e.y;
                    ((uint32_t*)g_zh)[(size_t)n*64 + (c>>1)] = bf2(zx, zy);
                    klw += lvx + 1.f - expf(lvx) - mux*mux;
                    klw += lvy + 1.f - expf(lvy) - muy*muy;
                }
            }
        }
    }
    #pragma unroll
    for (int o = 16; o; o >>= 1) klw += __shfl_xor_sync(0xffffffffu, klw, o);
    if (lane == 0) skl[w] = klw;
    __syncthreads();
    if (tid == 0) {
        double s = 0.0;
        #pragma unroll
        for (int i = 0; i < 8; i++) s += (double)skl[i];
        atomicAdd(&g_kl_sum, s);
    }
}

// ----------------------------------------------------------------------------
// Kernel 2: edge scatter-add (bf16 z reads, f32 atomics)
// ----------------------------------------------------------------------------
__global__ void scatter_kernel(const int* __restrict__ esrc,
                               const int* __restrict__ edst)
{
    const int e    = (blockIdx.x * blockDim.x + threadIdx.x) >> 5;
    const int lane = threadIdx.x & 31;
    if (e >= N_EDGES) return;
    const int s = __ldg(esrc + e);
    const int d = __ldg(edst + e);
    const uint2 v = ((const uint2*)(g_zh + (size_t)s * FDIM))[lane];
    const float2 f0 = up_bf2(v.x);
    const float2 f1 = up_bf2(v.y);
    float* p = &g_agg[(size_t)d * FDIM + 4*lane];
    asm volatile("red.global.add.v4.f32 [%0], {%1, %2, %3, %4};"
                 :: "l"(p), "f"(f0.x), "f"(f0.y), "f"(f1.x), "f"(f1.y) : "memory");
}

// ----------------------------------------------------------------------------
// Kernel 3: decoder (bf16 mma) + heads mma + thread-parallel loss
//   smem: X bf16[64][264] (33792B) | Wp u32[32][136] (17408B)
//   after GEMM: Yd bf16[64][136] @0 | Whp u32[64][24] @17408 | Yh f32[64][20] @23552
// ----------------------------------------------------------------------------
extern "C" __global__ void __launch_bounds__(256, 4)
dec_kernel(const int*   __restrict__ op_id,
           const float* __restrict__ lat,
           const float* __restrict__ mub,
           const float* __restrict__ lvb,
           const float* __restrict__ opw,
           float* __restrict__ op_loss,
           float* __restrict__ op_cnt)
{
    extern __shared__ __align__(16) char smraw[];
    uint16_t* X   = (uint16_t*)smraw;               // [64][264]
    uint32_t* Wp  = (uint32_t*)(smraw + 33792);     // [32][136]
    uint16_t* Yd  = (uint16_t*)smraw;               // [64][136]
    uint32_t* Whp = (uint32_t*)(smraw + 17408);     // [64][24]
    float*    Yh  = (float*)(smraw + 23552);        // [64][20]
    __shared__ float sL[8];

    const int tid  = threadIdx.x;
    const int lane = tid & 31;
    const int w    = tid >> 5;
    const int base = blockIdx.x * TILE;
    const int g    = lane >> 2;
    const int t    = lane & 3;
    const uint32_t xb  = smem_u32(X);
    const uint32_t ydb = smem_u32(Yd);

    // ---- gather z (bf16 copy) / agg (f32->bf16) ----
    #pragma unroll
    for (int it = 0; it < 8; it++) {
        const int idx = tid + it*256;
        const int r = idx >> 5, c4 = (idx & 31) << 2;
        const int n = base + r;
        uint16_t* row = X + r * 264;
        if (n < N_NODES) {
            *(uint2*)(row + c4) =
                __ldg((const uint2*)((const uint32_t*)g_zh + (size_t)n*64 + (c4>>1)));
            const float4 va = __ldg((const float4*)(g_agg + (size_t)n*FDIM + c4));
            *(uint2*)(row + FDIM + c4) = make_uint2(bf2(va.x,va.y), bf2(va.z,va.w));
        } else {
            *(uint2*)(row + c4)        = make_uint2(0u, 0u);
            *(uint2*)(row + FDIM + c4) = make_uint2(0u, 0u);
        }
    }
    __syncthreads();

    // ---- GEMM: yd = relu([z|agg] @ [Wself;Wagg]), K=256 (4 chunks x k64) ----
    float acc[2][4][4];
    #pragma unroll
    for (int i = 0; i < 2; i++)
        #pragma unroll
        for (int nt = 0; nt < 4; nt++)
            #pragma unroll
            for (int e = 0; e < 4; e++) acc[i][nt][e] = 0.f;

    const int mp  = w & 1;
    const int nqd = w >> 1;

    for (int ch = 0; ch < 4; ch++) {
        #pragma unroll
        for (int i = 0; i < 4; i++) {
            const int idx = tid + i*256;
            const int kp_l = idx >> 5, n4 = (idx & 31) << 2;
            *(uint4*)(Wp + kp_l*136 + n4) =
                __ldg((const uint4*)(g_pWd + (size_t)(ch*32 + kp_l)*FDIM + n4));
        }
        __syncthreads();
        for (int s = 0; s < 4; s++) {
            const int koff = s << 3;
            const int kidx = ch*64 + (s << 4);
            uint32_t a0[4], a1[4];
            const uint32_t addr = xb + (mp*32 + (lane & 15)) * 528
                                + ((kidx + ((lane >> 4) << 3)) << 1);
            ldsm_x4(a0[0], a0[1], a0[2], a0[3], addr);
            ldsm_x4(a1[0], a1[1], a1[2], a1[3], addr + 16*528);
            #pragma unroll
            for (int nt = 0; nt < 4; nt++) {
                const int ncol = nqd*32 + nt*8 + g;
                const uint32_t b0 = Wp[(koff + t)*136 + ncol];
                const uint32_t bv = Wp[(koff + 4 + t)*136 + ncol];
                mma_bf16(acc[0][nt], a0, b0, bv);
                mma_bf16(acc[1][nt], a1, b0, bv);
            }
        }
        __syncthreads();
    }

    // ---- yd = relu -> Yd bf16 ; stage heads weights ----
    #pragma unroll
    for (int i = 0; i < 2; i++)
        #pragma unroll
        for (int nt = 0; nt < 4; nt++) {
            const int r = mp*32 + i*16 + g;
            const int c = nqd*32 + nt*8 + 2*t;
            ((uint32_t*)Yd)[r*68 + (c>>1)] =
                bf2(fmaxf(acc[i][nt][0], 0.f), fmaxf(acc[i][nt][1], 0.f));
            ((uint32_t*)Yd)[(r+8)*68 + (c>>1)] =
                bf2(fmaxf(acc[i][nt][2], 0.f), fmaxf(acc[i][nt][3], 0.f));
        }
    #pragma unroll
    for (int i = 0; i < 4; i++) {
        const int idx = tid + i*256;
        const int kp = idx >> 4, nn = idx & 15;
        Whp[kp*24 + nn] = g_pWh[kp*16 + nn];
    }
    __syncthreads();

    // ---- heads mma: Yh[64][16] = yd @ [muW|lvW] + bias ----
    {
        const int mt = w & 3;
        const int nh = (w >> 2) & 1;
        float ah[4] = {0.f, 0.f, 0.f, 0.f};
        for (int s = 0; s < 8; s++) {
            const int koff = s << 3;
            uint32_t a[4];
            const uint32_t addr = ydb + (mt*16 + (lane & 15)) * 272
                                + (((s << 4) + ((lane >> 4) << 3)) << 1);
            ldsm_x4(a[0], a[1], a[2], a[3], addr);
            const uint32_t b0 = Whp[(koff + t)*24 + nh*8 + g];
            const uint32_t bv = Whp[(koff + 4 + t)*24 + nh*8 + g];
            mma_bf16(ah, a, b0, bv);
        }
        const int r = mt*16 + g;
        const int c = nh*8 + 2*t;
        const float* bp = nh ? lvb : mub;
        const float bx = __ldg(bp + 2*t), by = __ldg(bp + 2*t + 1);
        Yh[r*20 + c]         = ah[0] + bx;
        Yh[r*20 + c + 1]     = ah[1] + by;
        Yh[(r+8)*20 + c]     = ah[2] + bx;
        Yh[(r+8)*20 + c + 1] = ah[3] + by;
    }
    __syncthreads();

    // ---- loss: thread = (node r = tid>>2, k-pair kg = tid&3) ----
    {
        const int r  = tid >> 2;
        const int kg = tid & 3;
        const int n  = base + r;
        const bool valid = (n < N_NODES);
        float part = 0.f;
        int op = 0;
        if (valid) {
            op = __ldg(op_id + n);
            const float4 muA = *(const float4*)(Yh + r*20);
            const float4 muB = *(const float4*)(Yh + r*20 + 4);
            const float4 lvA = *(const float4*)(Yh + r*20 + 8);
            const float4 lvB = *(const float4*)(Yh + r*20 + 12);
            const float muv[8] = { muA.x, muA.y, muA.z, muA.w, muB.x, muB.y, muB.z, muB.w };
            const float lvv[8] = { lvA.x, lvA.y, lvA.z, lvA.w, lvB.x, lvB.y, lvB.z, lvB.w };
            const float* wrow = opw + (size_t)op * (2 * LDIM * LDIM);
            float mpA = 0.f, mpB = 0.f, lpA = 0.f, lpB = 0.f;
            #pragma unroll
            for (int l = 0; l < LDIM; l++) {
                const float2 wm = __ldg((const float2*)(wrow + l*2*LDIM + 2*kg));
                const float2 wl = __ldg((const float2*)(wrow + l*2*LDIM + LDIM + 2*kg));
                mpA += muv[l] * wm.x; mpB += muv[l] * wm.y;
                lpA += lvv[l] * wl.x; lpB += lvv[l] * wl.y;
            }
            const float2 lab = __ldg((const float2*)(lat + (size_t)n*LDIM + 2*kg));
            const float dA = mpA - lab.x, dB = mpB - lab.y;
            part = dA*dA / (2.f*expf(lpA) + 1e-7f) + 0.5f*lpA
                 + dB*dB / (2.f*expf(lpB) + 1e-7f) + 0.5f*lpB;
        }
        part += __shfl_xor_sync(0xffffffffu, part, 1);
        part += __shfl_xor_sync(0xffffffffu, part, 2);
        const float lossn = part * (1.f / LDIM);
        if (valid && kg == 0) {
            atomicAdd(op_loss + op, lossn);
            atomicAdd(op_cnt  + op, 1.f);
        }
        float wval = (valid && kg == 0) ? lossn : 0.f;
        wval += __shfl_xor_sync(0xffffffffu, wval, 4);
        wval += __shfl_xor_sync(0xffffffffu, wval, 8);
        wval += __shfl_xor_sync(0xffffffffu, wval, 16);
        if (lane == 0) sL[w] = wval;
    }
    __syncthreads();
    if (tid == 0) {
        double s = 0.0;
        #pragma unroll
        for (int i = 0; i < 8; i++) s += (double)sL[i];
        atomicAdd(&g_lat_sum, s);
    }
}

// ----------------------------------------------------------------------------
// Kernel 4: finalize
// ----------------------------------------------------------------------------
__global__ void fin_kernel(float* __restrict__ out)
{
    if (threadIdx.x == 0) {
        const double lat_loss = g_lat_sum / (double)N_NODES;
        const double kl = -0.5 * (g_kl_sum / ((double)N_NODES * (double)FDIM));
        out[0] = (float)(lat_loss + kl);
    }
}

// ----------------------------------------------------------------------------
extern "C" void kernel_launch(void* const* d_in, const int* in_sizes, int n_in,
                              void* d_out, int out_size)
{
    const int*   op_id = (const int*)  d_in[0];
    const int*   sv_id = (const int*)  d_in[1];
    const int*   st_id = (const int*)  d_in[2];
    const float* lat   = (const float*)d_in[3];
    const int*   esrc  = (const int*)  d_in[4];
    const int*   edst  = (const int*)  d_in[5];
    const float* eps   = (const float*)d_in[6];
    const float* opE   = (const float*)d_in[7];
    const float* svE   = (const float*)d_in[8];
    const float* stE   = (const float*)d_in[9];
    const float* W1    = (const float*)d_in[10];
    const float* b1    = (const float*)d_in[11];
    const float* W2    = (const float*)d_in[12];
    const float* b2    = (const float*)d_in[13];
    const float* Wself = (const float*)d_in[14];
    const float* Wagg  = (const float*)d_in[15];
    const float* muW   = (const float*)d_in[16];
    const float* mub   = (const float*)d_in[17];
    const float* lvW   = (const float*)d_in[18];
    const float* lvb   = (const float*)d_in[19];
    const float* opw   = (const float*)d_in[20];

    float* out     = (float*)d_out;
    float* op_loss = out + 1;
    float* op_cnt  = out + 1 + OPC;

    const int ENC_SMEM = 62464;
    const int DEC_SMEM = 51200;
    static bool attr_done = false;
    if (!attr_done) {
        cudaFuncSetAttribute(enc_kernel, cudaFuncAttributeMaxDynamicSharedMemorySize, ENC_SMEM);
        cudaFuncSetAttribute(dec_kernel, cudaFuncAttributeMaxDynamicSharedMemorySize, DEC_SMEM);
        attr_done = true;
    }

    const int n_tiles = (N_NODES + TILE - 1) / TILE;   // 7813

    prep_kernel<<<1073, 256>>>(W1, W2, Wself, Wagg, muW, lvW, opE, svE, stE);

    zero_kernel<<<62500, 256>>>(out);

    enc_kernel<<<n_tiles, 256, ENC_SMEM>>>(op_id, sv_id, st_id, lat, eps, b1, b2);

    scatter_kernel<<<(N_EDGES + 7) / 8, 256>>>(esrc, edst);

    dec_kernel<<<n_tiles, 256, DEC_SMEM>>>(op_id, lat, mub, lvb, opw,
                                           op_loss, op_cnt);

    fin_kernel<<<1, 32>>>(out);
}

// round 7
// speedup vs baseline: 11.9907x; 1.0884x over previous
#include <cuda_runtime.h>
#include <cstdint>

#define N_NODES 500000
#define N_EDGES 1000000
#define EMB 64
#define FDIM 128
#define LDIM 8
#define OPC 5000

#define TILE 64

// ---- scratch (no allocations allowed) ----
__device__ uint16_t g_zh [(size_t)N_NODES * FDIM];   // z in bf16 (128 MB)
__device__ uint16_t g_agg[(size_t)N_NODES * FDIM];   // agg in bf16 (128 MB)
__device__ double   g_kl_sum;
__device__ double   g_lat_sum;

// ---- pre-packed weights/embeddings (bf16) ----
__device__ uint32_t g_pW1[128 * 128];    // [kpair][n] for W1 (k padded to 256)
__device__ uint32_t g_pW2[64 * 256];     // [kpair][n] for W2
__device__ uint32_t g_pWd[128 * 128];    // [kpair][n], kp<64 Wself, kp>=64 Wagg
__device__ uint32_t g_pWh[64 * 16];      // [kpair][mu0..7 | lv0..7]
__device__ uint16_t g_pOpE[OPC * EMB];
__device__ uint16_t g_pSvE[2000 * EMB];
__device__ uint16_t g_pStE[16 * EMB];

// ---- helpers ----
__device__ __forceinline__ uint32_t smem_u32(const void* p) {
    uint32_t a;
    asm("{ .reg .u64 t; cvta.to.shared.u64 t, %1; cvt.u32.u64 %0, t; }"
        : "=r"(a) : "l"(p));
    return a;
}
__device__ __forceinline__ void ldsm_x4(uint32_t& r0, uint32_t& r1,
                                        uint32_t& r2, uint32_t& r3,
                                        uint32_t addr) {
    asm volatile("ldmatrix.sync.aligned.m8n8.x4.shared.b16 {%0,%1,%2,%3}, [%4];"
                 : "=r"(r0), "=r"(r1), "=r"(r2), "=r"(r3) : "r"(addr));
}
__device__ __forceinline__ void mma_bf16(float* d, const uint32_t* a,
                                         uint32_t b0, uint32_t b1) {
    asm volatile("mma.sync.aligned.m16n8k16.row.col.f32.bf16.bf16.f32 "
                 "{%0,%1,%2,%3}, {%4,%5,%6,%7}, {%8,%9}, {%0,%1,%2,%3};"
                 : "+f"(d[0]), "+f"(d[1]), "+f"(d[2]), "+f"(d[3])
                 : "r"(a[0]), "r"(a[1]), "r"(a[2]), "r"(a[3]),
                   "r"(b0), "r"(b1));
}
__device__ __forceinline__ uint32_t bf2(float lo, float hi) {
    uint32_t d;
    asm("cvt.rn.satfinite.bf16x2.f32 %0, %1, %2;" : "=r"(d) : "f"(hi), "f"(lo));
    return d;
}

// ----------------------------------------------------------------------------
// Kernel P: pack weights + embeddings to bf16
// ----------------------------------------------------------------------------
__global__ void prep_kernel(const float* __restrict__ W1,
                            const float* __restrict__ W2,
                            const float* __restrict__ Wself,
                            const float* __restrict__ Wagg,
                            const float* __restrict__ muW,
                            const float* __restrict__ lvW,
                            const float* __restrict__ opE,
                            const float* __restrict__ svE,
                            const float* __restrict__ stE)
{
    const int i = blockIdx.x * blockDim.x + threadIdx.x;
    if (i < 16384) {                                     // pW1
        const int kp = i >> 7, n = i & 127;
        const int k0 = 2 * kp;
        const float lo = (k0 < 200)     ? __ldg(W1 + (size_t)k0 * FDIM + n)     : 0.f;
        const float hi = (k0 + 1 < 200) ? __ldg(W1 + (size_t)(k0+1) * FDIM + n) : 0.f;
        g_pW1[i] = bf2(lo, hi);
    } else if (i < 32768) {                              // pW2
        const int j = i - 16384;
        const int kp = j >> 8, n = j & 255;
        const int k0 = 2 * kp;
        g_pW2[j] = bf2(__ldg(W2 + (size_t)k0 * 256 + n),
                       __ldg(W2 + (size_t)(k0+1) * 256 + n));
    } else if (i < 49152) {                              // pWd
        const int j = i - 32768;
        const int kp = j >> 7, n = j & 127;
        const float* src = (kp < 64) ? Wself : Wagg;
        const int k0 = (kp < 64) ? 2*kp : 2*(kp - 64);
        g_pWd[j] = bf2(__ldg(src + (size_t)k0 * FDIM + n),
                       __ldg(src + (size_t)(k0+1) * FDIM + n));
    } else if (i < 50176) {                              // pWh
        const int j = i - 49152;
        const int kp = j >> 4, nn = j & 15;
        float lo, hi;
        if (nn < 8) {
            lo = __ldg(muW + (size_t)(2*kp) * LDIM + nn);
            hi = __ldg(muW + (size_t)(2*kp+1) * LDIM + nn);
        } else {
            lo = __ldg(lvW + (size_t)(2*kp) * LDIM + nn - 8);
            hi = __ldg(lvW + (size_t)(2*kp+1) * LDIM + nn - 8);
        }
        g_pWh[j] = bf2(lo, hi);
    } else if (i < 210176) {                             // pOpE (u32 pairs)
        const int j = i - 50176;
        const float2 v = __ldg((const float2*)(opE + 2*(size_t)j));
        ((uint32_t*)g_pOpE)[j] = bf2(v.x, v.y);
    } else if (i < 274176) {                             // pSvE
        const int j = i - 210176;
        const float2 v = __ldg((const float2*)(svE + 2*(size_t)j));
        ((uint32_t*)g_pSvE)[j] = bf2(v.x, v.y);
    } else if (i < 274688) {                             // pStE
        const int j = i - 274176;
        const float2 v = __ldg((const float2*)(stE + 2*(size_t)j));
        ((uint32_t*)g_pStE)[j] = bf2(v.x, v.y);
    }
}

// ----------------------------------------------------------------------------
// Kernel 0: zero agg scratch (bf16), output head, scalar accumulators
// ----------------------------------------------------------------------------
__global__ void zero_kernel(float* __restrict__ out)
{
    size_t i = (size_t)blockIdx.x * blockDim.x + threadIdx.x;
    const size_t tot8 = (size_t)N_NODES * FDIM / 8;   // 8M uint4
    if (i < tot8) ((uint4*)g_agg)[i] = make_uint4(0u, 0u, 0u, 0u);
    if (i < (size_t)(1 + 2*OPC)) out[i] = 0.f;
    if (i == 0) { g_kl_sum = 0.0; g_lat_sum = 0.0; }
}

// ----------------------------------------------------------------------------
// Kernel 1: encoder (bf16 mma), 64-node tile, 256 threads
// ----------------------------------------------------------------------------
extern "C" __global__ void __launch_bounds__(256, 2)
enc_kernel(const int*   __restrict__ op_id,
           const int*   __restrict__ sv_id,
           const int*   __restrict__ st_id,
           const float* __restrict__ lat,
           const float* __restrict__ eps,
           const float* __restrict__ b1,
           const float* __restrict__ b2)
{
    extern __shared__ __align__(16) char smraw[];
    uint16_t* X1  = (uint16_t*)smraw;               // [64][216]
    uint32_t* Wp1 = (uint32_t*)(smraw + 27648);     // [32][136]
    uint16_t* Hs  = (uint16_t*)(smraw + 45056);     // [64][136]
    uint32_t* Wp2 = (uint32_t*)smraw;               // [32][264] (aliases X1)
    __shared__ float skl[8];

    const int tid  = threadIdx.x;
    const int lane = tid & 31;
    const int w    = tid >> 5;
    const int base = blockIdx.x * TILE;
    const int g    = lane >> 2;
    const int t    = lane & 3;
    const uint32_t x1b = smem_u32(X1);
    const uint32_t hsb = smem_u32(Hs);

    // ---- gather feats (pre-packed bf16 copies) ----
    {
        const int r = tid >> 2, q = tid & 3;
        const int n = base + r;
        uint16_t* row = X1 + r * 216;
        if (n < N_NODES) {
            const int op = op_id[n], sv = sv_id[n], st = st_id[n];
            const uint4* so = (const uint4*)(g_pOpE + (size_t)op*EMB + q*16);
            const uint4* ss = (const uint4*)(g_pSvE + (size_t)sv*EMB + q*16);
            const uint4* st4 = (const uint4*)(g_pStE + (size_t)st*EMB + q*16);
            *(uint4*)(row + q*16)          = __ldg(so);
            *(uint4*)(row + q*16 + 8)      = __ldg(so + 1);
            *(uint4*)(row + 64 + q*16)     = __ldg(ss);
            *(uint4*)(row + 64 + q*16 + 8) = __ldg(ss + 1);
            *(uint4*)(row + 128 + q*16)    = __ldg(st4);
            *(uint4*)(row + 128 + q*16 + 8)= __ldg(st4 + 1);
            if (q == 0) {
                const float4 v0 = __ldg((const float4*)(lat + (size_t)n*LDIM));
                const float4 v1 = __ldg((const float4*)(lat + (size_t)n*LDIM + 4));
                *(uint4*)(row + 192) = make_uint4(bf2(v0.x,v0.y), bf2(v0.z,v0.w),
                                                  bf2(v1.x,v1.y), bf2(v1.z,v1.w));
            } else if (q == 1) {
                *(uint4*)(row + 200) = make_uint4(0u,0u,0u,0u);
            }
        } else {
            const uint4 z4 = make_uint4(0u,0u,0u,0u);
            *(uint4*)(row + q*16)           = z4;
            *(uint4*)(row + q*16 + 8)       = z4;
            *(uint4*)(row + 64 + q*16)      = z4;
            *(uint4*)(row + 64 + q*16 + 8)  = z4;
            *(uint4*)(row + 128 + q*16)     = z4;
            *(uint4*)(row + 128 + q*16 + 8) = z4;
            if (q == 0)      *(uint4*)(row + 192) = z4;
            else if (q == 1) *(uint4*)(row + 200) = z4;
        }
    }
    __syncthreads();

    // ---- GEMM1: h = relu(X1 @ W1 + b1), K=208 ----
    float acc1[2][4][4];
    #pragma unroll
    for (int i = 0; i < 2; i++)
        #pragma unroll
        for (int nt = 0; nt < 4; nt++)
            #pragma unroll
            for (int j = 0; j < 4; j++) acc1[i][nt][j] = 0.f;

    const int mp  = w & 1;
    const int nq1 = w >> 1;

    for (int ch = 0; ch < 4; ch++) {
        #pragma unroll
        for (int i = 0; i < 4; i++) {
            const int idx = tid + i*256;
            const int kp_l = idx >> 5, n4 = (idx & 31) << 2;
            *(uint4*)(Wp1 + kp_l*136 + n4) =
                __ldg((const uint4*)(g_pW1 + (size_t)(ch*32 + kp_l)*FDIM + n4));
        }
        __syncthreads();
        const int nsteps = (ch < 3) ? 4 : 1;
        for (int s = 0; s < nsteps; s++) {
            const int koff = s << 3;
            const int kidx = ch*64 + (s << 4);
            uint32_t a0[4], a1[4];
            const uint32_t addr = x1b + (mp*32 + (lane & 15)) * 432
                                + ((kidx + ((lane >> 4) << 3)) << 1);
            ldsm_x4(a0[0], a0[1], a0[2], a0[3], addr);
            ldsm_x4(a1[0], a1[1], a1[2], a1[3], addr + 16*432);
            #pragma unroll
            for (int nt = 0; nt < 4; nt++) {
                const int ncol = nq1*32 + nt*8 + g;
                const uint32_t b0 = Wp1[(koff + t)*136 + ncol];
                const uint32_t bv = Wp1[(koff + 4 + t)*136 + ncol];
                mma_bf16(acc1[0][nt], a0, b0, bv);
                mma_bf16(acc1[1][nt], a1, b0, bv);
            }
        }
        __syncthreads();
    }

    // ---- h = relu(+bias) -> Hs bf16 ----
    #pragma unroll
    for (int i = 0; i < 2; i++)
        #pragma unroll
        for (int nt = 0; nt < 4; nt++) {
            const int r = mp*32 + i*16 + g;
            const int c = nq1*32 + nt*8 + 2*t;
            const float bA = __ldg(b1 + c), bB = __ldg(b1 + c + 1);
            ((uint32_t*)Hs)[r*68 + (c>>1)] =
                bf2(fmaxf(acc1[i][nt][0] + bA, 0.f), fmaxf(acc1[i][nt][1] + bB, 0.f));
            ((uint32_t*)Hs)[(r+8)*68 + (c>>1)] =
                bf2(fmaxf(acc1[i][nt][2] + bA, 0.f), fmaxf(acc1[i][nt][3] + bB, 0.f));
        }
    __syncthreads();

    // ---- GEMM2: y = h @ W2, K=128, N=256, paired mu/lv per warp ----
    float acc2[4][4][4];
    #pragma unroll
    for (int mi = 0; mi < 4; mi++)
        #pragma unroll
        for (int j = 0; j < 4; j++)
            #pragma unroll
            for (int e = 0; e < 4; e++) acc2[mi][j][e] = 0.f;

    for (int ch = 0; ch < 2; ch++) {
        #pragma unroll
        for (int i = 0; i < 8; i++) {
            const int idx = tid + i*256;
            const int kp_l = idx >> 6, n4 = (idx & 63) << 2;
            *(uint4*)(Wp2 + kp_l*264 + n4) =
                __ldg((const uint4*)(g_pW2 + (size_t)(ch*32 + kp_l)*256 + n4));
        }
        __syncthreads();
        for (int s = 0; s < 4; s++) {
            const int koff = s << 3;
            const int kidx = ch*64 + (s << 4);
            uint32_t a[4][4];
            #pragma unroll
            for (int mi = 0; mi < 4; mi++) {
                const uint32_t addr = hsb + (mi*16 + (lane & 15)) * 272
                                    + ((kidx + ((lane >> 4) << 3)) << 1);
                ldsm_x4(a[mi][0], a[mi][1], a[mi][2], a[mi][3], addr);
            }
            #pragma unroll
            for (int j = 0; j < 4; j++) {
                const int cb = (j < 2) ? (w*16 + 8*j) : (FDIM + w*16 + 8*(j-2));
                const uint32_t b0 = Wp2[(koff + t)*264 + cb + g];
                const uint32_t bv = Wp2[(koff + 4 + t)*264 + cb + g];
                #pragma unroll
                for (int mi = 0; mi < 4; mi++)
                    mma_bf16(acc2[mi][j], a[mi], b0, bv);
            }
        }
        __syncthreads();
    }

    // ---- epilogue in registers: z = mu + exp(0.5*tanh(lv))*eps -> g_zh ----
    float klw = 0.f;
    #pragma unroll
    for (int j = 0; j < 2; j++) {
        const int c = w*16 + 8*j + 2*t;
        const float bmx = __ldg(b2 + c),        bmy = __ldg(b2 + c + 1);
        const float blx = __ldg(b2 + FDIM + c), bly = __ldg(b2 + FDIM + c + 1);
        #pragma unroll
        for (int mi = 0; mi < 4; mi++) {
            const float* fm = acc2[mi][j];
            const float* fl = acc2[mi][j+2];
            #pragma unroll
            for (int half = 0; half < 2; half++) {
                const int r = mi*16 + g + half*8;
                const int n = base + r;
                if (n < N_NODES) {
                    const float mux = fm[2*half]   + bmx;
                    const float muy = fm[2*half+1] + bmy;
                    const float lvx = tanhf(fl[2*half]   + blx);
                    const float lvy = tanhf(fl[2*half+1] + bly);
                    const float2 e = __ldg((const float2*)(eps + (size_t)n*FDIM + c));
                    const float zx = mux + expf(0.5f*lvx) * e.x;
                    const float zy = muy + expf(0.5f*lvy) * e.y;
                    ((uint32_t*)g_zh)[(size_t)n*64 + (c>>1)] = bf2(zx, zy);
                    klw += lvx + 1.f - expf(lvx) - mux*mux;
                    klw += lvy + 1.f - expf(lvy) - muy*muy;
                }
            }
        }
    }
    #pragma unroll
    for (int o = 16; o; o >>= 1) klw += __shfl_xor_sync(0xffffffffu, klw, o);
    if (lane == 0) skl[w] = klw;
    __syncthreads();
    if (tid == 0) {
        double s = 0.0;
        #pragma unroll
        for (int i = 0; i < 8; i++) s += (double)skl[i];
        atomicAdd(&g_kl_sum, s);
    }
}

// ----------------------------------------------------------------------------
// Kernel 2: edge scatter-add — bf16 reads, bf16x2 global reductions
// ----------------------------------------------------------------------------
__global__ void scatter_kernel(const int* __restrict__ esrc,
                               const int* __restrict__ edst)
{
    const int e    = (blockIdx.x * blockDim.x + threadIdx.x) >> 5;
    const int lane = threadIdx.x & 31;
    if (e >= N_EDGES) return;
    const int s = __ldg(esrc + e);
    const int d = __ldg(edst + e);
    const uint2 v = __ldg((const uint2*)(g_zh + (size_t)s * FDIM) + lane);
    uint32_t* p = (uint32_t*)(g_agg + (size_t)d * FDIM) + 2*lane;
    asm volatile("red.global.add.noftz.bf16x2 [%0], %1;" :: "l"(p),     "r"(v.x) : "memory");
    asm volatile("red.global.add.noftz.bf16x2 [%0], %1;" :: "l"(p + 1), "r"(v.y) : "memory");
}

// ----------------------------------------------------------------------------
// Kernel 3: decoder (bf16 mma) + heads mma + thread-parallel loss
// ----------------------------------------------------------------------------
extern "C" __global__ void __launch_bounds__(256, 4)
dec_kernel(const int*   __restrict__ op_id,
           const float* __restrict__ lat,
           const float* __restrict__ mub,
           const float* __restrict__ lvb,
           const float* __restrict__ opw,
           float* __restrict__ op_loss,
           float* __restrict__ op_cnt)
{
    extern __shared__ __align__(16) char smraw[];
    uint16_t* X   = (uint16_t*)smraw;               // [64][264]
    uint32_t* Wp  = (uint32_t*)(smraw + 33792);     // [32][136]
    uint16_t* Yd  = (uint16_t*)smraw;               // [64][136]
    uint32_t* Whp = (uint32_t*)(smraw + 17408);     // [64][24]
    float*    Yh  = (float*)(smraw + 23552);        // [64][20]
    __shared__ float sL[8];

    const int tid  = threadIdx.x;
    const int lane = tid & 31;
    const int w    = tid >> 5;
    const int base = blockIdx.x * TILE;
    const int g    = lane >> 2;
    const int t    = lane & 3;
    const uint32_t xb  = smem_u32(X);
    const uint32_t ydb = smem_u32(Yd);

    // ---- gather z / agg (both bf16 straight copies) ----
    #pragma unroll
    for (int it = 0; it < 8; it++) {
        const int idx = tid + it*256;
        const int r = idx >> 5, c4 = (idx & 31) << 2;
        const int n = base + r;
        uint16_t* row = X + r * 264;
        if (n < N_NODES) {
            *(uint2*)(row + c4) =
                __ldg((const uint2*)(g_zh + (size_t)n*FDIM + c4));
            *(uint2*)(row + FDIM + c4) =
                __ldg((const uint2*)(g_agg + (size_t)n*FDIM + c4));
        } else {
            *(uint2*)(row + c4)        = make_uint2(0u, 0u);
            *(uint2*)(row + FDIM + c4) = make_uint2(0u, 0u);
        }
    }
    __syncthreads();

    // ---- GEMM: yd = relu([z|agg] @ [Wself;Wagg]), K=256 (4 chunks x k64) ----
    float acc[2][4][4];
    #pragma unroll
    for (int i = 0; i < 2; i++)
        #pragma unroll
        for (int nt = 0; nt < 4; nt++)
            #pragma unroll
            for (int e = 0; e < 4; e++) acc[i][nt][e] = 0.f;

    const int mp  = w & 1;
    const int nqd = w >> 1;

    for (int ch = 0; ch < 4; ch++) {
        #pragma unroll
        for (int i = 0; i < 4; i++) {
            const int idx = tid + i*256;
            const int kp_l = idx >> 5, n4 = (idx & 31) << 2;
            *(uint4*)(Wp + kp_l*136 + n4) =
                __ldg((const uint4*)(g_pWd + (size_t)(ch*32 + kp_l)*FDIM + n4));
        }
        __syncthreads();
        for (int s = 0; s < 4; s++) {
            const int koff = s << 3;
            const int kidx = ch*64 + (s << 4);
            uint32_t a0[4], a1[4];
            const uint32_t addr = xb + (mp*32 + (lane & 15)) * 528
                                + ((kidx + ((lane >> 4) << 3)) << 1);
            ldsm_x4(a0[0], a0[1], a0[2], a0[3], addr);
            ldsm_x4(a1[0], a1[1], a1[2], a1[3], addr + 16*528);
            #pragma unroll
            for (int nt = 0; nt < 4; nt++) {
                const int ncol = nqd*32 + nt*8 + g;
                const uint32_t b0 = Wp[(koff + t)*136 + ncol];
                const uint32_t bv = Wp[(koff + 4 + t)*136 + ncol];
                mma_bf16(acc[0][nt], a0, b0, bv);
                mma_bf16(acc[1][nt], a1, b0, bv);
            }
        }
        __syncthreads();
    }

    // ---- yd = relu -> Yd bf16 ; stage heads weights ----
    #pragma unroll
    for (int i = 0; i < 2; i++)
        #pragma unroll
        for (int nt = 0; nt < 4; nt++) {
            const int r = mp*32 + i*16 + g;
            const int c = nqd*32 + nt*8 + 2*t;
            ((uint32_t*)Yd)[r*68 + (c>>1)] =
                bf2(fmaxf(acc[i][nt][0], 0.f), fmaxf(acc[i][nt][1], 0.f));
            ((uint32_t*)Yd)[(r+8)*68 + (c>>1)] =
                bf2(fmaxf(acc[i][nt][2], 0.f), fmaxf(acc[i][nt][3], 0.f));
        }
    #pragma unroll
    for (int i = 0; i < 4; i++) {
        const int idx = tid + i*256;
        const int kp = idx >> 4, nn = idx & 15;
        Whp[kp*24 + nn] = g_pWh[kp*16 + nn];
    }
    __syncthreads();

    // ---- heads mma: Yh[64][16] = yd @ [muW|lvW] + bias ----
    {
        const int mt = w & 3;
        const int nh = (w >> 2) & 1;
        float ah[4] = {0.f, 0.f, 0.f, 0.f};
        for (int s = 0; s < 8; s++) {
            const int koff = s << 3;
            uint32_t a[4];
            const uint32_t addr = ydb + (mt*16 + (lane & 15)) * 272
                                + (((s << 4) + ((lane >> 4) << 3)) << 1);
            ldsm_x4(a[0], a[1], a[2], a[3], addr);
            const uint32_t b0 = Whp[(koff + t)*24 + nh*8 + g];
            const uint32_t bv = Whp[(koff + 4 + t)*24 + nh*8 + g];
            mma_bf16(ah, a, b0, bv);
        }
        const int r = mt*16 + g;
        const int c = nh*8 + 2*t;
        const float* bp = nh ? lvb : mub;
        const float bx = __ldg(bp + 2*t), by = __ldg(bp + 2*t + 1);
        Yh[r*20 + c]         = ah[0] + bx;
        Yh[r*20 + c + 1]     = ah[1] + by;
        Yh[(r+8)*20 + c]     = ah[2] + bx;
        Yh[(r+8)*20 + c + 1] = ah[3] + by;
    }
    __syncthreads();

    // ---- loss: thread = (node r = tid>>2, k-pair kg = tid&3) ----
    {
        const int r  = tid >> 2;
        const int kg = tid & 3;
        const int n  = base + r;
        const bool valid = (n < N_NODES);
        float part = 0.f;
        int op = 0;
        if (valid) {
            op = __ldg(op_id + n);
            const float4 muA = *(const float4*)(Yh + r*20);
            const float4 muB = *(const float4*)(Yh + r*20 + 4);
            const float4 lvA = *(const float4*)(Yh + r*20 + 8);
            const float4 lvB = *(const float4*)(Yh + r*20 + 12);
            const float muv[8] = { muA.x, muA.y, muA.z, muA.w, muB.x, muB.y, muB.z, muB.w };
            const float lvv[8] = { lvA.x, lvA.y, lvA.z, lvA.w, lvB.x, lvB.y, lvB.z, lvB.w };
            const float* wrow = opw + (size_t)op * (2 * LDIM * LDIM);
            float mpA = 0.f, mpB = 0.f, lpA = 0.f, lpB = 0.f;
            #pragma unroll
            for (int l = 0; l < LDIM; l++) {
                const float2 wm = __ldg((const float2*)(wrow + l*2*LDIM + 2*kg));
                const float2 wl = __ldg((const float2*)(wrow + l*2*LDIM + LDIM + 2*kg));
                mpA += muv[l] * wm.x; mpB += muv[l] * wm.y;
                lpA += lvv[l] * wl.x; lpB += lvv[l] * wl.y;
            }
            const float2 lab = __ldg((const float2*)(lat + (size_t)n*LDIM + 2*kg));
            const float dA = mpA - lab.x, dB = mpB - lab.y;
            part = dA*dA / (2.f*expf(lpA) + 1e-7f) + 0.5f*lpA
                 + dB*dB / (2.f*expf(lpB) + 1e-7f) + 0.5f*lpB;
        }
        part += __shfl_xor_sync(0xffffffffu, part, 1);
        part += __shfl_xor_sync(0xffffffffu, part, 2);
        const float lossn = part * (1.f / LDIM);
        if (valid && kg == 0) {
            atomicAdd(op_loss + op, lossn);
            atomicAdd(op_cnt  + op, 1.f);
        }
        float wval = (valid && kg == 0) ? lossn : 0.f;
        wval += __shfl_xor_sync(0xffffffffu, wval, 4);
        wval += __shfl_xor_sync(0xffffffffu, wval, 8);
        wval += __shfl_xor_sync(0xffffffffu, wval, 16);
        if (lane == 0) sL[w] = wval;
    }
    __syncthreads();
    if (tid == 0) {
        double s = 0.0;
        #pragma unroll
        for (int i = 0; i < 8; i++) s += (double)sL[i];
        atomicAdd(&g_lat_sum, s);
    }
}

// ----------------------------------------------------------------------------
// Kernel 4: finalize
// ----------------------------------------------------------------------------
__global__ void fin_kernel(float* __restrict__ out)
{
    if (threadIdx.x == 0) {
        const double lat_loss = g_lat_sum / (double)N_NODES;
        const double kl = -0.5 * (g_kl_sum / ((double)N_NODES * (double)FDIM));
        out[0] = (float)(lat_loss + kl);
    }
}

// ----------------------------------------------------------------------------
extern "C" void kernel_launch(void* const* d_in, const int* in_sizes, int n_in,
                              void* d_out, int out_size)
{
    const int*   op_id = (const int*)  d_in[0];
    const int*   sv_id = (const int*)  d_in[1];
    const int*   st_id = (const int*)  d_in[2];
    const float* lat   = (const float*)d_in[3];
    const int*   esrc  = (const int*)  d_in[4];
    const int*   edst  = (const int*)  d_in[5];
    const float* eps   = (const float*)d_in[6];
    const float* opE   = (const float*)d_in[7];
    const float* svE   = (const float*)d_in[8];
    const float* stE   = (const float*)d_in[9];
    const float* W1    = (const float*)d_in[10];
    const float* b1    = (const float*)d_in[11];
    const float* W2    = (const float*)d_in[12];
    const float* b2    = (const float*)d_in[13];
    const float* Wself = (const float*)d_in[14];
    const float* Wagg  = (const float*)d_in[15];
    const float* muW   = (const float*)d_in[16];
    const float* mub   = (const float*)d_in[17];
    const float* lvW   = (const float*)d_in[18];
    const float* lvb   = (const float*)d_in[19];
    const float* opw   = (const float*)d_in[20];

    float* out     = (float*)d_out;
    float* op_loss = out + 1;
    float* op_cnt  = out + 1 + OPC;

    const int ENC_SMEM = 62464;
    const int DEC_SMEM = 51200;
    static bool attr_done = false;
    if (!attr_done) {
        cudaFuncSetAttribute(enc_kernel, cudaFuncAttributeMaxDynamicSharedMemorySize, ENC_SMEM);
        cudaFuncSetAttribute(dec_kernel, cudaFuncAttributeMaxDynamicSharedMemorySize, DEC_SMEM);
        attr_done = true;
    }

    const int n_tiles = (N_NODES + TILE - 1) / TILE;   // 7813

    prep_kernel<<<1073, 256>>>(W1, W2, Wself, Wagg, muW, lvW, opE, svE, stE);

    zero_kernel<<<31250, 256>>>(out);

    enc_kernel<<<n_tiles, 256, ENC_SMEM>>>(op_id, sv_id, st_id, lat, eps, b1, b2);

    scatter_kernel<<<(N_EDGES + 7) / 8, 256>>>(esrc, edst);

    dec_kernel<<<n_tiles, 256, DEC_SMEM>>>(op_id, lat, mub, lvb, opw,
                                           op_loss, op_cnt);

    fin_kernel<<<1, 32>>>(out);
}

// round 8
// speedup vs baseline: 12.9900x; 1.0833x over previous
#include <cuda_runtime.h>
#include <cstdint>

#define N_NODES 500000
#define N_EDGES 1000000
#define EMB 64
#define FDIM 128
#define LDIM 8
#define OPC 5000

#define TILE 64

// ---- scratch (no allocations allowed) ----
__device__ uint16_t g_zh [(size_t)N_NODES * FDIM];   // z in bf16 (128 MB)
__device__ uint16_t g_agg[(size_t)N_NODES * FDIM];   // agg in bf16 (128 MB)
__device__ double   g_kl_sum;
__device__ double   g_lat_sum;

// ---- pre-packed weights/embeddings (bf16) ----
__device__ uint32_t g_pW1[128 * 128];
__device__ uint32_t g_pW2[64 * 256];
__device__ uint32_t g_pWd[128 * 128];
__device__ uint32_t g_pWh[64 * 16];
__device__ uint16_t g_pOpE[OPC * EMB];
__device__ uint16_t g_pSvE[2000 * EMB];
__device__ uint16_t g_pStE[16 * EMB];

// ---- helpers ----
__device__ __forceinline__ uint32_t smem_u32(const void* p) {
    uint32_t a;
    asm("{ .reg .u64 t; cvta.to.shared.u64 t, %1; cvt.u32.u64 %0, t; }"
        : "=r"(a) : "l"(p));
    return a;
}
__device__ __forceinline__ void ldsm_x4(uint32_t& r0, uint32_t& r1,
                                        uint32_t& r2, uint32_t& r3,
                                        uint32_t addr) {
    asm volatile("ldmatrix.sync.aligned.m8n8.x4.shared.b16 {%0,%1,%2,%3}, [%4];"
                 : "=r"(r0), "=r"(r1), "=r"(r2), "=r"(r3) : "r"(addr));
}
__device__ __forceinline__ void mma_bf16(float* d, const uint32_t* a,
                                         uint32_t b0, uint32_t b1) {
    asm volatile("mma.sync.aligned.m16n8k16.row.col.f32.bf16.bf16.f32 "
                 "{%0,%1,%2,%3}, {%4,%5,%6,%7}, {%8,%9}, {%0,%1,%2,%3};"
                 : "+f"(d[0]), "+f"(d[1]), "+f"(d[2]), "+f"(d[3])
                 : "r"(a[0]), "r"(a[1]), "r"(a[2]), "r"(a[3]),
                   "r"(b0), "r"(b1));
}
__device__ __forceinline__ uint32_t bf2(float lo, float hi) {
    uint32_t d;
    asm("cvt.rn.satfinite.bf16x2.f32 %0, %1, %2;" : "=r"(d) : "f"(hi), "f"(lo));
    return d;
}

// ----------------------------------------------------------------------------
// Kernel P: pack weights + embeddings to bf16
// ----------------------------------------------------------------------------
__global__ void prep_kernel(const float* __restrict__ W1,
                            const float* __restrict__ W2,
                            const float* __restrict__ Wself,
                            const float* __restrict__ Wagg,
                            const float* __restrict__ muW,
                            const float* __restrict__ lvW,
                            const float* __restrict__ opE,
                            const float* __restrict__ svE,
                            const float* __restrict__ stE)
{
    const int i = blockIdx.x * blockDim.x + threadIdx.x;
    if (i < 16384) {
        const int kp = i >> 7, n = i & 127;
        const int k0 = 2 * kp;
        const float lo = (k0 < 200)     ? __ldg(W1 + (size_t)k0 * FDIM + n)     : 0.f;
        const float hi = (k0 + 1 < 200) ? __ldg(W1 + (size_t)(k0+1) * FDIM + n) : 0.f;
        g_pW1[i] = bf2(lo, hi);
    } else if (i < 32768) {
        const int j = i - 16384;
        const int kp = j >> 8, n = j & 255;
        const int k0 = 2 * kp;
        g_pW2[j] = bf2(__ldg(W2 + (size_t)k0 * 256 + n),
                       __ldg(W2 + (size_t)(k0+1) * 256 + n));
    } else if (i < 49152) {
        const int j = i - 32768;
        const int kp = j >> 7, n = j & 127;
        const float* src = (kp < 64) ? Wself : Wagg;
        const int k0 = (kp < 64) ? 2*kp : 2*(kp - 64);
        g_pWd[j] = bf2(__ldg(src + (size_t)k0 * FDIM + n),
                       __ldg(src + (size_t)(k0+1) * FDIM + n));
    } else if (i < 50176) {
        const int j = i - 49152;
        const int kp = j >> 4, nn = j & 15;
        float lo, hi;
        if (nn < 8) {
            lo = __ldg(muW + (size_t)(2*kp) * LDIM + nn);
            hi = __ldg(muW + (size_t)(2*kp+1) * LDIM + nn);
        } else {
            lo = __ldg(lvW + (size_t)(2*kp) * LDIM + nn - 8);
            hi = __ldg(lvW + (size_t)(2*kp+1) * LDIM + nn - 8);
        }
        g_pWh[j] = bf2(lo, hi);
    } else if (i < 210176) {
        const int j = i - 50176;
        const float2 v = __ldg((const float2*)(opE + 2*(size_t)j));
        ((uint32_t*)g_pOpE)[j] = bf2(v.x, v.y);
    } else if (i < 274176) {
        const int j = i - 210176;
        const float2 v = __ldg((const float2*)(svE + 2*(size_t)j));
        ((uint32_t*)g_pSvE)[j] = bf2(v.x, v.y);
    } else if (i < 274688) {
        const int j = i - 274176;
        const float2 v = __ldg((const float2*)(stE + 2*(size_t)j));
        ((uint32_t*)g_pStE)[j] = bf2(v.x, v.y);
    }
}

// ----------------------------------------------------------------------------
// Kernel 0: zero agg scratch (bf16), output head, scalar accumulators
// ----------------------------------------------------------------------------
__global__ void zero_kernel(float* __restrict__ out)
{
    size_t i = (size_t)blockIdx.x * blockDim.x + threadIdx.x;
    const size_t tot8 = (size_t)N_NODES * FDIM / 8;
    if (i < tot8) ((uint4*)g_agg)[i] = make_uint4(0u, 0u, 0u, 0u);
    if (i < (size_t)(1 + 2*OPC)) out[i] = 0.f;
    if (i == 0) { g_kl_sum = 0.0; g_lat_sum = 0.0; }
}

// ----------------------------------------------------------------------------
// Kernel 1: encoder (bf16 mma), 64-node tile, 256 threads
// ----------------------------------------------------------------------------
extern "C" __global__ void __launch_bounds__(256, 2)
enc_kernel(const int*   __restrict__ op_id,
           const int*   __restrict__ sv_id,
           const int*   __restrict__ st_id,
           const float* __restrict__ lat,
           const float* __restrict__ eps,
           const float* __restrict__ b1,
           const float* __restrict__ b2)
{
    extern __shared__ __align__(16) char smraw[];
    uint16_t* X1  = (uint16_t*)smraw;               // [64][216]
    uint32_t* Wp1 = (uint32_t*)(smraw + 27648);     // [32][136]
    uint16_t* Hs  = (uint16_t*)(smraw + 45056);     // [64][136]
    uint32_t* Wp2 = (uint32_t*)smraw;               // [32][264] (aliases X1)
    __shared__ float skl[8];

    const int tid  = threadIdx.x;
    const int lane = tid & 31;
    const int w    = tid >> 5;
    const int base = blockIdx.x * TILE;
    const int g    = lane >> 2;
    const int t    = lane & 3;
    const uint32_t x1b = smem_u32(X1);
    const uint32_t hsb = smem_u32(Hs);

    // ---- gather feats (pre-packed bf16 copies) ----
    {
        const int r = tid >> 2, q = tid & 3;
        const int n = base + r;
        uint16_t* row = X1 + r * 216;
        if (n < N_NODES) {
            const int op = op_id[n], sv = sv_id[n], st = st_id[n];
            const uint4* so = (const uint4*)(g_pOpE + (size_t)op*EMB + q*16);
            const uint4* ss = (const uint4*)(g_pSvE + (size_t)sv*EMB + q*16);
            const uint4* st4 = (const uint4*)(g_pStE + (size_t)st*EMB + q*16);
            *(uint4*)(row + q*16)          = __ldg(so);
            *(uint4*)(row + q*16 + 8)      = __ldg(so + 1);
            *(uint4*)(row + 64 + q*16)     = __ldg(ss);
            *(uint4*)(row + 64 + q*16 + 8) = __ldg(ss + 1);
            *(uint4*)(row + 128 + q*16)    = __ldg(st4);
            *(uint4*)(row + 128 + q*16 + 8)= __ldg(st4 + 1);
            if (q == 0) {
                const float4 v0 = __ldg((const float4*)(lat + (size_t)n*LDIM));
                const float4 v1 = __ldg((const float4*)(lat + (size_t)n*LDIM + 4));
                *(uint4*)(row + 192) = make_uint4(bf2(v0.x,v0.y), bf2(v0.z,v0.w),
                                                  bf2(v1.x,v1.y), bf2(v1.z,v1.w));
            } else if (q == 1) {
                *(uint4*)(row + 200) = make_uint4(0u,0u,0u,0u);
            }
        } else {
            const uint4 z4 = make_uint4(0u,0u,0u,0u);
            *(uint4*)(row + q*16)           = z4;
            *(uint4*)(row + q*16 + 8)       = z4;
            *(uint4*)(row + 64 + q*16)      = z4;
            *(uint4*)(row + 64 + q*16 + 8)  = z4;
            *(uint4*)(row + 128 + q*16)     = z4;
            *(uint4*)(row + 128 + q*16 + 8) = z4;
            if (q == 0)      *(uint4*)(row + 192) = z4;
            else if (q == 1) *(uint4*)(row + 200) = z4;
        }
    }
    __syncthreads();

    // ---- GEMM1: h = relu(X1 @ W1 + b1), K=208 ----
    float acc1[2][4][4];
    #pragma unroll
    for (int i = 0; i < 2; i++)
        #pragma unroll
        for (int nt = 0; nt < 4; nt++)
            #pragma unroll
            for (int j = 0; j < 4; j++) acc1[i][nt][j] = 0.f;

    const int mp  = w & 1;
    const int nq1 = w >> 1;

    for (int ch = 0; ch < 4; ch++) {
        #pragma unroll
        for (int i = 0; i < 4; i++) {
            const int idx = tid + i*256;
            const int kp_l = idx >> 5, n4 = (idx & 31) << 2;
            *(uint4*)(Wp1 + kp_l*136 + n4) =
                __ldg((const uint4*)(g_pW1 + (size_t)(ch*32 + kp_l)*FDIM + n4));
        }
        __syncthreads();
        const int nsteps = (ch < 3) ? 4 : 1;
        for (int s = 0; s < nsteps; s++) {
            const int koff = s << 3;
            const int kidx = ch*64 + (s << 4);
            uint32_t a0[4], a1[4];
            const uint32_t addr = x1b + (mp*32 + (lane & 15)) * 432
                                + ((kidx + ((lane >> 4) << 3)) << 1);
            ldsm_x4(a0[0], a0[1], a0[2], a0[3], addr);
            ldsm_x4(a1[0], a1[1], a1[2], a1[3], addr + 16*432);
            #pragma unroll
            for (int nt = 0; nt < 4; nt++) {
                const int ncol = nq1*32 + nt*8 + g;
                const uint32_t b0 = Wp1[(koff + t)*136 + ncol];
                const uint32_t bv = Wp1[(koff + 4 + t)*136 + ncol];
                mma_bf16(acc1[0][nt], a0, b0, bv);
                mma_bf16(acc1[1][nt], a1, b0, bv);
            }
        }
        __syncthreads();
    }

    // ---- h = relu(+bias) -> Hs bf16 ----
    #pragma unroll
    for (int i = 0; i < 2; i++)
        #pragma unroll
        for (int nt = 0; nt < 4; nt++) {
            const int r = mp*32 + i*16 + g;
            const int c = nq1*32 + nt*8 + 2*t;
            const float bA = __ldg(b1 + c), bB = __ldg(b1 + c + 1);
            ((uint32_t*)Hs)[r*68 + (c>>1)] =
                bf2(fmaxf(acc1[i][nt][0] + bA, 0.f), fmaxf(acc1[i][nt][1] + bB, 0.f));
            ((uint32_t*)Hs)[(r+8)*68 + (c>>1)] =
                bf2(fmaxf(acc1[i][nt][2] + bA, 0.f), fmaxf(acc1[i][nt][3] + bB, 0.f));
        }
    __syncthreads();

    // ---- GEMM2: y = h @ W2, K=128, N=256, paired mu/lv per warp ----
    float acc2[4][4][4];
    #pragma unroll
    for (int mi = 0; mi < 4; mi++)
        #pragma unroll
        for (int j = 0; j < 4; j++)
            #pragma unroll
            for (int e = 0; e < 4; e++) acc2[mi][j][e] = 0.f;

    for (int ch = 0; ch < 2; ch++) {
        #pragma unroll
        for (int i = 0; i < 8; i++) {
            const int idx = tid + i*256;
            const int kp_l = idx >> 6, n4 = (idx & 63) << 2;
            *(uint4*)(Wp2 + kp_l*264 + n4) =
                __ldg((const uint4*)(g_pW2 + (size_t)(ch*32 + kp_l)*256 + n4));
        }
        __syncthreads();
        for (int s = 0; s < 4; s++) {
            const int koff = s << 3;
            const int kidx = ch*64 + (s << 4);
            uint32_t a[4][4];
            #pragma unroll
            for (int mi = 0; mi < 4; mi++) {
                const uint32_t addr = hsb + (mi*16 + (lane & 15)) * 272
                                    + ((kidx + ((lane >> 4) << 3)) << 1);
                ldsm_x4(a[mi][0], a[mi][1], a[mi][2], a[mi][3], addr);
            }
            #pragma unroll
            for (int j = 0; j < 4; j++) {
                const int cb = (j < 2) ? (w*16 + 8*j) : (FDIM + w*16 + 8*(j-2));
                const uint32_t b0 = Wp2[(koff + t)*264 + cb + g];
                const uint32_t bv = Wp2[(koff + 4 + t)*264 + cb + g];
                #pragma unroll
                for (int mi = 0; mi < 4; mi++)
                    mma_bf16(acc2[mi][j], a[mi], b0, bv);
            }
        }
        __syncthreads();
    }

    // ---- epilogue in registers: z = mu + exp(0.5*tanh(lv))*eps -> g_zh ----
    float klw = 0.f;
    #pragma unroll
    for (int j = 0; j < 2; j++) {
        const int c = w*16 + 8*j + 2*t;
        const float bmx = __ldg(b2 + c),        bmy = __ldg(b2 + c + 1);
        const float blx = __ldg(b2 + FDIM + c), bly = __ldg(b2 + FDIM + c + 1);
        #pragma unroll
        for (int mi = 0; mi < 4; mi++) {
            const float* fm = acc2[mi][j];
            const float* fl = acc2[mi][j+2];
            #pragma unroll
            for (int half = 0; half < 2; half++) {
                const int r = mi*16 + g + half*8;
                const int n = base + r;
                if (n < N_NODES) {
                    const float mux = fm[2*half]   + bmx;
                    const float muy = fm[2*half+1] + bmy;
                    const float lvx = tanhf(fl[2*half]   + blx);
                    const float lvy = tanhf(fl[2*half+1] + bly);
                    const float2 e = __ldg((const float2*)(eps + (size_t)n*FDIM + c));
                    const float zx = mux + expf(0.5f*lvx) * e.x;
                    const float zy = muy + expf(0.5f*lvy) * e.y;
                    ((uint32_t*)g_zh)[(size_t)n*64 + (c>>1)] = bf2(zx, zy);
                    klw += lvx + 1.f - expf(lvx) - mux*mux;
                    klw += lvy + 1.f - expf(lvy) - muy*muy;
                }
            }
        }
    }
    #pragma unroll
    for (int o = 16; o; o >>= 1) klw += __shfl_xor_sync(0xffffffffu, klw, o);
    if (lane == 0) skl[w] = klw;
    __syncthreads();
    if (tid == 0) {
        double s = 0.0;
        #pragma unroll
        for (int i = 0; i < 8; i++) s += (double)skl[i];
        atomicAdd(&g_kl_sum, s);
    }
}

// ----------------------------------------------------------------------------
// Kernel 2: edge scatter-add — 8 edges/warp, 16B slices, MLP-4 unroll
// ----------------------------------------------------------------------------
__global__ void scatter_kernel(const int* __restrict__ esrc,
                               const int* __restrict__ edst)
{
    const int warp = (blockIdx.x * blockDim.x + threadIdx.x) >> 5;
    const int lane = threadIdx.x & 31;
    const int sub  = lane >> 4;          // edge within pair
    const int off  = lane & 15;          // 16B unit: 16 lanes x 16B = 256B row
    const int ebase = warp * 8 + sub;

    int   s[4], d[4];
    uint4 v[4];
    #pragma unroll
    for (int i = 0; i < 4; i++) {
        const int e = ebase + 2*i;
        s[i] = (e < N_EDGES) ? __ldg(esrc + e) : 0;
        d[i] = (e < N_EDGES) ? __ldg(edst + e) : 0;
    }
    #pragma unroll
    for (int i = 0; i < 4; i++)
        v[i] = __ldg((const uint4*)(g_zh + (size_t)s[i] * FDIM) + off);
    #pragma unroll
    for (int i = 0; i < 4; i++) {
        const int e = ebase + 2*i;
        if (e < N_EDGES) {
            uint32_t* p = (uint32_t*)(g_agg + (size_t)d[i] * FDIM) + 4*off;
            asm volatile("red.global.add.noftz.v4.bf16x2 [%0], {%1, %2, %3, %4};"
                         :: "l"(p), "r"(v[i].x), "r"(v[i].y), "r"(v[i].z), "r"(v[i].w)
                         : "memory");
        }
    }
}

// ----------------------------------------------------------------------------
// Kernel 3: decoder (bf16 mma) + heads mma + thread-parallel loss
// ----------------------------------------------------------------------------
extern "C" __global__ void __launch_bounds__(256, 4)
dec_kernel(const int*   __restrict__ op_id,
           const float* __restrict__ lat,
           const float* __restrict__ mub,
           const float* __restrict__ lvb,
           const float* __restrict__ opw,
           float* __restrict__ op_loss,
           float* __restrict__ op_cnt)
{
    extern __shared__ __align__(16) char smraw[];
    uint16_t* X   = (uint16_t*)smraw;               // [64][264]
    uint32_t* Wp  = (uint32_t*)(smraw + 33792);     // [32][136]
    uint16_t* Yd  = (uint16_t*)smraw;               // [64][136]
    uint32_t* Whp = (uint32_t*)(smraw + 17408);     // [64][24]
    float*    Yh  = (float*)(smraw + 23552);        // [64][20]
    __shared__ float sL[8];

    const int tid  = threadIdx.x;
    const int lane = tid & 31;
    const int w    = tid >> 5;
    const int base = blockIdx.x * TILE;
    const int g    = lane >> 2;
    const int t    = lane & 3;
    const uint32_t xb  = smem_u32(X);
    const uint32_t ydb = smem_u32(Yd);

    // ---- gather z / agg (both bf16 straight copies) ----
    #pragma unroll
    for (int it = 0; it < 8; it++) {
        const int idx = tid + it*256;
        const int r = idx >> 5, c4 = (idx & 31) << 2;
        const int n = base + r;
        uint16_t* row = X + r * 264;
        if (n < N_NODES) {
            *(uint2*)(row + c4) =
                __ldg((const uint2*)(g_zh + (size_t)n*FDIM + c4));
            *(uint2*)(row + FDIM + c4) =
                __ldg((const uint2*)(g_agg + (size_t)n*FDIM + c4));
        } else {
            *(uint2*)(row + c4)        = make_uint2(0u, 0u);
            *(uint2*)(row + FDIM + c4) = make_uint2(0u, 0u);
        }
    }
    __syncthreads();

    // ---- GEMM: yd = relu([z|agg] @ [Wself;Wagg]), K=256 (4 chunks x k64) ----
    float acc[2][4][4];
    #pragma unroll
    for (int i = 0; i < 2; i++)
        #pragma unroll
        for (int nt = 0; nt < 4; nt++)
            #pragma unroll
            for (int e = 0; e < 4; e++) acc[i][nt][e] = 0.f;

    const int mp  = w & 1;
    const int nqd = w >> 1;

    for (int ch = 0; ch < 4; ch++) {
        #pragma unroll
        for (int i = 0; i < 4; i++) {
            const int idx = tid + i*256;
            const int kp_l = idx >> 5, n4 = (idx & 31) << 2;
            *(uint4*)(Wp + kp_l*136 + n4) =
                __ldg((const uint4*)(g_pWd + (size_t)(ch*32 + kp_l)*FDIM + n4));
        }
        __syncthreads();
        for (int s = 0; s < 4; s++) {
            const int koff = s << 3;
            const int kidx = ch*64 + (s << 4);
            uint32_t a0[4], a1[4];
            const uint32_t addr = xb + (mp*32 + (lane & 15)) * 528
                                + ((kidx + ((lane >> 4) << 3)) << 1);
            ldsm_x4(a0[0], a0[1], a0[2], a0[3], addr);
            ldsm_x4(a1[0], a1[1], a1[2], a1[3], addr + 16*528);
            #pragma unroll
            for (int nt = 0; nt < 4; nt++) {
                const int ncol = nqd*32 + nt*8 + g;
                const uint32_t b0 = Wp[(koff + t)*136 + ncol];
                const uint32_t bv = Wp[(koff + 4 + t)*136 + ncol];
                mma_bf16(acc[0][nt], a0, b0, bv);
                mma_bf16(acc[1][nt], a1, b0, bv);
            }
        }
        __syncthreads();
    }

    // ---- yd = relu -> Yd bf16 ; stage heads weights ----
    #pragma unroll
    for (int i = 0; i < 2; i++)
        #pragma unroll
        for (int nt = 0; nt < 4; nt++) {
            const int r = mp*32 + i*16 + g;
            const int c = nqd*32 + nt*8 + 2*t;
            ((uint32_t*)Yd)[r*68 + (c>>1)] =
                bf2(fmaxf(acc[i][nt][0], 0.f), fmaxf(acc[i][nt][1], 0.f));
            ((uint32_t*)Yd)[(r+8)*68 + (c>>1)] =
                bf2(fmaxf(acc[i][nt][2], 0.f), fmaxf(acc[i][nt][3], 0.f));
        }
    #pragma unroll
    for (int i = 0; i < 4; i++) {
        const int idx = tid + i*256;
        const int kp = idx >> 4, nn = idx & 15;
        Whp[kp*24 + nn] = g_pWh[kp*16 + nn];
    }
    __syncthreads();

    // ---- heads mma: Yh[64][16] = yd @ [muW|lvW] + bias ----
    {
        const int mt = w & 3;
        const int nh = (w >> 2) & 1;
        float ah[4] = {0.f, 0.f, 0.f, 0.f};
        for (int s = 0; s < 8; s++) {
            const int koff = s << 3;
            uint32_t a[4];
            const uint32_t addr = ydb + (mt*16 + (lane & 15)) * 272
                                + (((s << 4) + ((lane >> 4) << 3)) << 1);
            ldsm_x4(a[0], a[1], a[2], a[3], addr);
            const uint32_t b0 = Whp[(koff + t)*24 + nh*8 + g];
            const uint32_t bv = Whp[(koff + 4 + t)*24 + nh*8 + g];
            mma_bf16(ah, a, b0, bv);
        }
        const int r = mt*16 + g;
        const int c = nh*8 + 2*t;
        const float* bp = nh ? lvb : mub;
        const float bx = __ldg(bp + 2*t), by = __ldg(bp + 2*t + 1);
        Yh[r*20 + c]         = ah[0] + bx;
        Yh[r*20 + c + 1]     = ah[1] + by;
        Yh[(r+8)*20 + c]     = ah[2] + bx;
        Yh[(r+8)*20 + c + 1] = ah[3] + by;
    }
    __syncthreads();

    // ---- loss: thread = (node r = tid>>2, k-pair kg = tid&3) ----
    {
        const int r  = tid >> 2;
        const int kg = tid & 3;
        const int n  = base + r;
        const bool valid = (n < N_NODES);
        float part = 0.f;
        int op = 0;
        if (valid) {
            op = __ldg(op_id + n);
            const float4 muA = *(const float4*)(Yh + r*20);
            const float4 muB = *(const float4*)(Yh + r*20 + 4);
            const float4 lvA = *(const float4*)(Yh + r*20 + 8);
            const float4 lvB = *(const float4*)(Yh + r*20 + 12);
            const float muv[8] = { muA.x, muA.y, muA.z, muA.w, muB.x, muB.y, muB.z, muB.w };
            const float lvv[8] = { lvA.x, lvA.y, lvA.z, lvA.w, lvB.x, lvB.y, lvB.z, lvB.w };
            const float* wrow = opw + (size_t)op * (2 * LDIM * LDIM);
            float mpA = 0.f, mpB = 0.f, lpA = 0.f, lpB = 0.f;
            #pragma unroll
            for (int l = 0; l < LDIM; l++) {
                const float2 wm = __ldg((const float2*)(wrow + l*2*LDIM + 2*kg));
                const float2 wl = __ldg((const float2*)(wrow + l*2*LDIM + LDIM + 2*kg));
                mpA += muv[l] * wm.x; mpB += muv[l] * wm.y;
                lpA += lvv[l] * wl.x; lpB += lvv[l] * wl.y;
            }
            const float2 lab = __ldg((const float2*)(lat + (size_t)n*LDIM + 2*kg));
            const float dA = mpA - lab.x, dB = mpB - lab.y;
            part = dA*dA / (2.f*expf(lpA) + 1e-7f) + 0.5f*lpA
                 + dB*dB / (2.f*expf(lpB) + 1e-7f) + 0.5f*lpB;
        }
        part += __shfl_xor_sync(0xffffffffu, part, 1);
        part += __shfl_xor_sync(0xffffffffu, part, 2);
        const float lossn = part * (1.f / LDIM);
        if (valid && kg == 0) {
            atomicAdd(op_loss + op, lossn);
            atomicAdd(op_cnt  + op, 1.f);
        }
        float wval = (valid && kg == 0) ? lossn : 0.f;
        wval += __shfl_xor_sync(0xffffffffu, wval, 4);
        wval += __shfl_xor_sync(0xffffffffu, wval, 8);
        wval += __shfl_xor_sync(0xffffffffu, wval, 16);
        if (lane == 0) sL[w] = wval;
    }
    __syncthreads();
    if (tid == 0) {
        double s = 0.0;
        #pragma unroll
        for (int i = 0; i < 8; i++) s += (double)sL[i];
        atomicAdd(&g_lat_sum, s);
    }
}

// ----------------------------------------------------------------------------
// Kernel 4: finalize
// ----------------------------------------------------------------------------
__global__ void fin_kernel(float* __restrict__ out)
{
    if (threadIdx.x == 0) {
        const double lat_loss = g_lat_sum / (double)N_NODES;
        const double kl = -0.5 * (g_kl_sum / ((double)N_NODES * (double)FDIM));
        out[0] = (float)(lat_loss + kl);
    }
}

// ----------------------------------------------------------------------------
extern "C" void kernel_launch(void* const* d_in, const int* in_sizes, int n_in,
                              void* d_out, int out_size)
{
    const int*   op_id = (const int*)  d_in[0];
    const int*   sv_id = (const int*)  d_in[1];
    const int*   st_id = (const int*)  d_in[2];
    const float* lat   = (const float*)d_in[3];
    const int*   esrc  = (const int*)  d_in[4];
    const int*   edst  = (const int*)  d_in[5];
    const float* eps   = (const float*)d_in[6];
    const float* opE   = (const float*)d_in[7];
    const float* svE   = (const float*)d_in[8];
    const float* stE   = (const float*)d_in[9];
    const float* W1    = (const float*)d_in[10];
    const float* b1    = (const float*)d_in[11];
    const float* W2    = (const float*)d_in[12];
    const float* b2    = (const float*)d_in[13];
    const float* Wself = (const float*)d_in[14];
    const float* Wagg  = (const float*)d_in[15];
    const float* muW   = (const float*)d_in[16];
    const float* mub   = (const float*)d_in[17];
    const float* lvW   = (const float*)d_in[18];
    const float* lvb   = (const float*)d_in[19];
    const float* opw   = (const float*)d_in[20];

    float* out     = (float*)d_out;
    float* op_loss = out + 1;
    float* op_cnt  = out + 1 + OPC;

    const int ENC_SMEM = 62464;
    const int DEC_SMEM = 51200;
    static bool attr_done = false;
    if (!attr_done) {
        cudaFuncSetAttribute(enc_kernel, cudaFuncAttributeMaxDynamicSharedMemorySize, ENC_SMEM);
        cudaFuncSetAttribute(dec_kernel, cudaFuncAttributeMaxDynamicSharedMemorySize, DEC_SMEM);
        attr_done = true;
    }

    const int n_tiles = (N_NODES + TILE - 1) / TILE;   // 7813

    prep_kernel<<<1073, 256>>>(W1, W2, Wself, Wagg, muW, lvW, opE, svE, stE);

    zero_kernel<<<31250, 256>>>(out);

    enc_kernel<<<n_tiles, 256, ENC_SMEM>>>(op_id, sv_id, st_id, lat, eps, b1, b2);

    // 1M edges, 8 per warp -> 125000 warps -> 15625 blocks of 256
    scatter_kernel<<<15625, 256>>>(esrc, edst);

    dec_kernel<<<n_tiles, 256, DEC_SMEM>>>(op_id, lat, mub, lvb, opw,
                                           op_loss, op_cnt);

    fin_kernel<<<1, 32>>>(out);
}

// round 9
// speedup vs baseline: 14.0874x; 1.0845x over previous
#include <cuda_runtime.h>
#include <cstdint>

#define N_NODES 500000
#define N_EDGES 1000000
#define EMB 64
#define FDIM 128
#define LDIM 8
#define OPC 5000

#define TILE 64

// ---- scratch (no allocations allowed) ----
__device__ uint16_t g_zh [(size_t)N_NODES * FDIM];   // z in bf16 (128 MB)
__device__ uint16_t g_agg[(size_t)N_NODES * FDIM];   // agg in bf16 (128 MB)
__device__ double   g_kl_sum;
__device__ double   g_lat_sum;

// ---- pre-packed weights/embeddings (bf16) ----
__device__ uint32_t g_pW1[128 * 128];
__device__ uint32_t g_pW2[64 * 256];
__device__ uint32_t g_pWd[128 * 128];
__device__ uint32_t g_pWh[64 * 16];
__device__ uint16_t g_pOpE[OPC * EMB];
__device__ uint16_t g_pSvE[2000 * EMB];
__device__ uint16_t g_pStE[16 * EMB];

// ---- helpers ----
__device__ __forceinline__ uint32_t smem_u32(const void* p) {
    uint32_t a;
    asm("{ .reg .u64 t; cvta.to.shared.u64 t, %1; cvt.u32.u64 %0, t; }"
        : "=r"(a) : "l"(p));
    return a;
}
__device__ __forceinline__ void ldsm_x4(uint32_t& r0, uint32_t& r1,
                                        uint32_t& r2, uint32_t& r3,
                                        uint32_t addr) {
    asm volatile("ldmatrix.sync.aligned.m8n8.x4.shared.b16 {%0,%1,%2,%3}, [%4];"
                 : "=r"(r0), "=r"(r1), "=r"(r2), "=r"(r3) : "r"(addr));
}
__device__ __forceinline__ void mma_bf16(float* d, const uint32_t* a,
                                         uint32_t b0, uint32_t b1) {
    asm volatile("mma.sync.aligned.m16n8k16.row.col.f32.bf16.bf16.f32 "
                 "{%0,%1,%2,%3}, {%4,%5,%6,%7}, {%8,%9}, {%0,%1,%2,%3};"
                 : "+f"(d[0]), "+f"(d[1]), "+f"(d[2]), "+f"(d[3])
                 : "r"(a[0]), "r"(a[1]), "r"(a[2]), "r"(a[3]),
                   "r"(b0), "r"(b1));
}
__device__ __forceinline__ uint32_t bf2(float lo, float hi) {
    uint32_t d;
    asm("cvt.rn.satfinite.bf16x2.f32 %0, %1, %2;" : "=r"(d) : "f"(hi), "f"(lo));
    return d;
}
__device__ __forceinline__ void cpa16(uint32_t dst, const void* src) {
    asm volatile("cp.async.cg.shared.global [%0], [%1], 16;"
                 :: "r"(dst), "l"(src) : "memory");
}
#define CP_COMMIT() asm volatile("cp.async.commit_group;" ::: "memory")
#define CP_WAIT(n)  asm volatile("cp.async.wait_group %0;" :: "n"(n) : "memory")

// ----------------------------------------------------------------------------
// Kernel P: pack weights + embeddings to bf16
// ----------------------------------------------------------------------------
__global__ void prep_kernel(const float* __restrict__ W1,
                            const float* __restrict__ W2,
                            const float* __restrict__ Wself,
                            const float* __restrict__ Wagg,
                            const float* __restrict__ muW,
                            const float* __restrict__ lvW,
                            const float* __restrict__ opE,
                            const float* __restrict__ svE,
                            const float* __restrict__ stE)
{
    const int i = blockIdx.x * blockDim.x + threadIdx.x;
    if (i < 16384) {
        const int kp = i >> 7, n = i & 127;
        const int k0 = 2 * kp;
        const float lo = (k0 < 200)     ? __ldg(W1 + (size_t)k0 * FDIM + n)     : 0.f;
        const float hi = (k0 + 1 < 200) ? __ldg(W1 + (size_t)(k0+1) * FDIM + n) : 0.f;
        g_pW1[i] = bf2(lo, hi);
    } else if (i < 32768) {
        const int j = i - 16384;
        const int kp = j >> 8, n = j & 255;
        const int k0 = 2 * kp;
        g_pW2[j] = bf2(__ldg(W2 + (size_t)k0 * 256 + n),
                       __ldg(W2 + (size_t)(k0+1) * 256 + n));
    } else if (i < 49152) {
        const int j = i - 32768;
        const int kp = j >> 7, n = j & 127;
        const float* src = (kp < 64) ? Wself : Wagg;
        const int k0 = (kp < 64) ? 2*kp : 2*(kp - 64);
        g_pWd[j] = bf2(__ldg(src + (size_t)k0 * FDIM + n),
                       __ldg(src + (size_t)(k0+1) * FDIM + n));
    } else if (i < 50176) {
        const int j = i - 49152;
        const int kp = j >> 4, nn = j & 15;
        float lo, hi;
        if (nn < 8) {
            lo = __ldg(muW + (size_t)(2*kp) * LDIM + nn);
            hi = __ldg(muW + (size_t)(2*kp+1) * LDIM + nn);
        } else {
            lo = __ldg(lvW + (size_t)(2*kp) * LDIM + nn - 8);
            hi = __ldg(lvW + (size_t)(2*kp+1) * LDIM + nn - 8);
        }
        g_pWh[j] = bf2(lo, hi);
    } else if (i < 210176) {
        const int j = i - 50176;
        const float2 v = __ldg((const float2*)(opE + 2*(size_t)j));
        ((uint32_t*)g_pOpE)[j] = bf2(v.x, v.y);
    } else if (i < 274176) {
        const int j = i - 210176;
        const float2 v = __ldg((const float2*)(svE + 2*(size_t)j));
        ((uint32_t*)g_pSvE)[j] = bf2(v.x, v.y);
    } else if (i < 274688) {
        const int j = i - 274176;
        const float2 v = __ldg((const float2*)(stE + 2*(size_t)j));
        ((uint32_t*)g_pStE)[j] = bf2(v.x, v.y);
    }
}

// ----------------------------------------------------------------------------
// Kernel 0: zero agg scratch (bf16), output head, scalar accumulators
// ----------------------------------------------------------------------------
__global__ void zero_kernel(float* __restrict__ out)
{
    size_t i = (size_t)blockIdx.x * blockDim.x + threadIdx.x;
    const size_t tot8 = (size_t)N_NODES * FDIM / 8;
    if (i < tot8) ((uint4*)g_agg)[i] = make_uint4(0u, 0u, 0u, 0u);
    if (i < (size_t)(1 + 2*OPC)) out[i] = 0.f;
    if (i == 0) { g_kl_sum = 0.0; g_lat_sum = 0.0; }
}

// ----------------------------------------------------------------------------
// Kernel 1: encoder (bf16 mma), 64-node tile, 256 threads
//   smem (83 KB): X1 bf16[64][216] @0 | Wp1A u32[32][136] @27648 |
//                 Wp1B @45056 | Hs bf16[64][136] @67584
//   phase2: Wp2 u32[64][264] @0 (aliases X1 + Wp1A/B)
// ----------------------------------------------------------------------------
extern "C" __global__ void __launch_bounds__(256, 2)
enc_kernel(const int*   __restrict__ op_id,
           const int*   __restrict__ sv_id,
           const int*   __restrict__ st_id,
           const float* __restrict__ lat,
           const float* __restrict__ eps,
           const float* __restrict__ b1,
           const float* __restrict__ b2)
{
    extern __shared__ __align__(16) char smraw[];
    uint16_t* X1  = (uint16_t*)smraw;               // [64][216]
    uint16_t* Hs  = (uint16_t*)(smraw + 67584);     // [64][136]
    uint32_t* Wp2 = (uint32_t*)smraw;               // [64][264]
    __shared__ float skl[8];

    const int tid  = threadIdx.x;
    const int lane = tid & 31;
    const int w    = tid >> 5;
    const int base = blockIdx.x * TILE;
    const int g    = lane >> 2;
    const int t    = lane & 3;
    const uint32_t x1b  = smem_u32(X1);
    const uint32_t hsb  = smem_u32(Hs);
    const uint32_t wb[2] = { smem_u32(smraw + 27648), smem_u32(smraw + 45056) };

    // stage GEMM1 chunk into buffer (32 kpairs x 128 u32, padded stride 136)
    auto stage1 = [&](int ch, uint32_t wbuf) {
        #pragma unroll
        for (int i = 0; i < 4; i++) {
            const int idx = tid + i*256;            // 1024 = 32 kp x 32 u4
            const int kp_l = idx >> 5, n4 = (idx & 31) << 2;
            cpa16(wbuf + (kp_l*136 + n4)*4,
                  g_pW1 + (size_t)(ch*32 + kp_l)*FDIM + n4);
        }
    };

    // ---- prologue: prefetch chunk 0, gather feats, prefetch chunk 1 ----
    stage1(0, wb[0]);
    CP_COMMIT();
    {
        const int r = tid >> 2, q = tid & 3;
        const int n = base + r;
        uint16_t* row = X1 + r * 216;
        if (n < N_NODES) {
            const int op = op_id[n], sv = sv_id[n], st = st_id[n];
            const uint4* so = (const uint4*)(g_pOpE + (size_t)op*EMB + q*16);
            const uint4* ss = (const uint4*)(g_pSvE + (size_t)sv*EMB + q*16);
            const uint4* st4 = (const uint4*)(g_pStE + (size_t)st*EMB + q*16);
            *(uint4*)(row + q*16)          = __ldg(so);
            *(uint4*)(row + q*16 + 8)      = __ldg(so + 1);
            *(uint4*)(row + 64 + q*16)     = __ldg(ss);
            *(uint4*)(row + 64 + q*16 + 8) = __ldg(ss + 1);
            *(uint4*)(row + 128 + q*16)    = __ldg(st4);
            *(uint4*)(row + 128 + q*16 + 8)= __ldg(st4 + 1);
            if (q == 0) {
                const float4 v0 = __ldg((const float4*)(lat + (size_t)n*LDIM));
                const float4 v1 = __ldg((const float4*)(lat + (size_t)n*LDIM + 4));
                *(uint4*)(row + 192) = make_uint4(bf2(v0.x,v0.y), bf2(v0.z,v0.w),
                                                  bf2(v1.x,v1.y), bf2(v1.z,v1.w));
            } else if (q == 1) {
                *(uint4*)(row + 200) = make_uint4(0u,0u,0u,0u);
            }
        } else {
            const uint4 z4 = make_uint4(0u,0u,0u,0u);
            *(uint4*)(row + q*16)           = z4;
            *(uint4*)(row + q*16 + 8)       = z4;
            *(uint4*)(row + 64 + q*16)      = z4;
            *(uint4*)(row + 64 + q*16 + 8)  = z4;
            *(uint4*)(row + 128 + q*16)     = z4;
            *(uint4*)(row + 128 + q*16 + 8) = z4;
            if (q == 0)      *(uint4*)(row + 192) = z4;
            else if (q == 1) *(uint4*)(row + 200) = z4;
        }
    }
    stage1(1, wb[1]);
    CP_COMMIT();
    CP_WAIT(1);            // chunk 0 resident (chunk 1 still in flight)
    __syncthreads();       // feats + chunk0 visible to all

    // ---- GEMM1: h = relu(X1 @ W1 + b1), K=208, double-buffered chunks ----
    float acc1[2][4][4];
    #pragma unroll
    for (int i = 0; i < 2; i++)
        #pragma unroll
        for (int nt = 0; nt < 4; nt++)
            #pragma unroll
            for (int j = 0; j < 4; j++) acc1[i][nt][j] = 0.f;

    const int mp  = w & 1;
    const int nq1 = w >> 1;

    for (int ch = 0; ch < 4; ch++) {
        const uint32_t* Wc = (const uint32_t*)(smraw + ((ch & 1) ? 45056 : 27648));
        const int nsteps = (ch < 3) ? 4 : 1;
        for (int s = 0; s < nsteps; s++) {
            const int koff = s << 3;
            const int kidx = ch*64 + (s << 4);
            uint32_t a0[4], a1[4];
            const uint32_t addr = x1b + (mp*32 + (lane & 15)) * 432
                                + ((kidx + ((lane >> 4) << 3)) << 1);
            ldsm_x4(a0[0], a0[1], a0[2], a0[3], addr);
            ldsm_x4(a1[0], a1[1], a1[2], a1[3], addr + 16*432);
            #pragma unroll
            for (int nt = 0; nt < 4; nt++) {
                const int ncol = nq1*32 + nt*8 + g;
                const uint32_t b0 = Wc[(koff + t)*136 + ncol];
                const uint32_t bv = Wc[(koff + 4 + t)*136 + ncol];
                mma_bf16(acc1[0][nt], a0, b0, bv);
                mma_bf16(acc1[1][nt], a1, b0, bv);
            }
        }
        if (ch < 3) {
            __syncthreads();                 // buffer free for overwrite
            if (ch + 2 < 4) {
                stage1(ch + 2, wb[ch & 1]);
                CP_COMMIT();
                CP_WAIT(1);                  // chunk ch+1 resident
            } else {
                CP_WAIT(0);                  // last chunk resident
            }
            __syncthreads();
        }
    }
    __syncthreads();   // all warps done reading X1/Wp1 before Wp2 overwrites

    // ---- prefetch ALL of W2 (64 kpairs, aliases X1 region) ----
    #pragma unroll
    for (int i = 0; i < 16; i++) {
        const int idx = tid + i*256;                // 4096 = 64 kp x 64 u4
        const int kp_l = idx >> 6, n4 = (idx & 63) << 2;
        cpa16(smem_u32(Wp2 + kp_l*264 + n4),
              g_pW2 + (size_t)kp_l*256 + n4);
    }
    CP_COMMIT();

    // ---- h = relu(+bias) -> Hs bf16 (overlaps W2 prefetch) ----
    #pragma unroll
    for (int i = 0; i < 2; i++)
        #pragma unroll
        for (int nt = 0; nt < 4; nt++) {
            const int r = mp*32 + i*16 + g;
            const int c = nq1*32 + nt*8 + 2*t;
            const float bA = __ldg(b1 + c), bB = __ldg(b1 + c + 1);
            ((uint32_t*)Hs)[r*68 + (c>>1)] =
                bf2(fmaxf(acc1[0 + (i==1)*0][nt][0], 0.f), 0.f);  // placeholder (overwritten below)
            // NOTE: proper stores below
        }
    // (correct Hs stores — keep exact mapping from prior rounds)
    #pragma unroll
    for (int i = 0; i < 2; i++)
        #pragma unroll
        for (int nt = 0; nt < 4; nt++) {
            const int r = mp*32 + i*16 + g;
            const int c = nq1*32 + nt*8 + 2*t;
            const float bA = __ldg(b1 + c), bB = __ldg(b1 + c + 1);
            ((uint32_t*)Hs)[r*68 + (c>>1)] =
                bf2(fmaxf(acc1[i][nt][0] + bA, 0.f), fmaxf(acc1[i][nt][1] + bB, 0.f));
            ((uint32_t*)Hs)[(r+8)*68 + (c>>1)] =
                bf2(fmaxf(acc1[i][nt][2] + bA, 0.f), fmaxf(acc1[i][nt][3] + bB, 0.f));
        }
    CP_WAIT(0);
    __syncthreads();

    // ---- GEMM2: y = h @ W2, K=128 (8 sync-free k-steps), paired mu/lv ----
    float acc2[4][4][4];
    #pragma unroll
    for (int mi = 0; mi < 4; mi++)
        #pragma unroll
        for (int j = 0; j < 4; j++)
            #pragma unroll
            for (int e = 0; e < 4; e++) acc2[mi][j][e] = 0.f;

    for (int s = 0; s < 8; s++) {
        const int koff = s << 3;
        const int kidx = s << 4;
        uint32_t a[4][4];
        #pragma unroll
        for (int mi = 0; mi < 4; mi++) {
            const uint32_t addr = hsb + (mi*16 + (lane & 15)) * 272
                                + ((kidx + ((lane >> 4) << 3)) << 1);
            ldsm_x4(a[mi][0], a[mi][1], a[mi][2], a[mi][3], addr);
        }
        #pragma unroll
        for (int j = 0; j < 4; j++) {
            const int cb = (j < 2) ? (w*16 + 8*j) : (FDIM + w*16 + 8*(j-2));
            const uint32_t b0 = Wp2[(koff + t)*264 + cb + g];
            const uint32_t bv = Wp2[(koff + 4 + t)*264 + cb + g];
            #pragma unroll
            for (int mi = 0; mi < 4; mi++)
                mma_bf16(acc2[mi][j], a[mi], b0, bv);
        }
    }

    // ---- epilogue in registers: z = mu + exp(0.5*tanh(lv))*eps -> g_zh ----
    float klw = 0.f;
    #pragma unroll
    for (int j = 0; j < 2; j++) {
        const int c = w*16 + 8*j + 2*t;
        const float bmx = __ldg(b2 + c),        bmy = __ldg(b2 + c + 1);
        const float blx = __ldg(b2 + FDIM + c), bly = __ldg(b2 + FDIM + c + 1);
        #pragma unroll
        for (int mi = 0; mi < 4; mi++) {
            const float* fm = acc2[mi][j];
            const float* fl = acc2[mi][j+2];
            #pragma unroll
            for (int half = 0; half < 2; half++) {
                const int r = mi*16 + g + half*8;
                const int n = base + r;
                if (n < N_NODES) {
                    const float mux = fm[2*half]   + bmx;
                    const float muy = fm[2*half+1] + bmy;
                    const float lvx = tanhf(fl[2*half]   + blx);
                    const float lvy = tanhf(fl[2*half+1] + bly);
                    const float2 e = __ldg((const float2*)(eps + (size_t)n*FDIM + c));
                    const float zx = mux + expf(0.5f*lvx) * e.x;
                    const float zy = muy + expf(0.5f*lvy) * e.y;
                    ((uint32_t*)g_zh)[(size_t)n*64 + (c>>1)] = bf2(zx, zy);
                    klw += lvx + 1.f - expf(lvx) - mux*mux;
                    klw += lvy + 1.f - expf(lvy) - muy*muy;
                }
            }
        }
    }
    #pragma unroll
    for (int o = 16; o; o >>= 1) klw += __shfl_xor_sync(0xffffffffu, klw, o);
    if (lane == 0) skl[w] = klw;
    __syncthreads();
    if (tid == 0) {
        double s = 0.0;
        #pragma unroll
        for (int i = 0; i < 8; i++) s += (double)skl[i];
        atomicAdd(&g_kl_sum, s);
    }
}

// ----------------------------------------------------------------------------
// Kernel 2: edge scatter-add — 8 edges/warp, 16B slices, MLP-4 unroll
// ----------------------------------------------------------------------------
__global__ void scatter_kernel(const int* __restrict__ esrc,
                               const int* __restrict__ edst)
{
    const int warp = (blockIdx.x * blockDim.x + threadIdx.x) >> 5;
    const int lane = threadIdx.x & 31;
    const int sub  = lane >> 4;
    const int off  = lane & 15;
    const int ebase = warp * 8 + sub;

    int   s[4], d[4];
    uint4 v[4];
    #pragma unroll
    for (int i = 0; i < 4; i++) {
        const int e = ebase + 2*i;
        s[i] = (e < N_EDGES) ? __ldg(esrc + e) : 0;
        d[i] = (e < N_EDGES) ? __ldg(edst + e) : 0;
    }
    #pragma unroll
    for (int i = 0; i < 4; i++)
        v[i] = __ldg((const uint4*)(g_zh + (size_t)s[i] * FDIM) + off);
    #pragma unroll
    for (int i = 0; i < 4; i++) {
        const int e = ebase + 2*i;
        if (e < N_EDGES) {
            uint32_t* p = (uint32_t*)(g_agg + (size_t)d[i] * FDIM) + 4*off;
            asm volatile("red.global.add.noftz.v4.bf16x2 [%0], {%1, %2, %3, %4};"
                         :: "l"(p), "r"(v[i].x), "r"(v[i].y), "r"(v[i].z), "r"(v[i].w)
                         : "memory");
        }
    }
}

// ----------------------------------------------------------------------------
// Kernel 3: decoder (bf16 mma) + heads mma + thread-parallel loss
// ----------------------------------------------------------------------------
extern "C" __global__ void __launch_bounds__(256, 4)
dec_kernel(const int*   __restrict__ op_id,
           const float* __restrict__ lat,
           const float* __restrict__ mub,
           const float* __restrict__ lvb,
           const float* __restrict__ opw,
           float* __restrict__ op_loss,
           float* __restrict__ op_cnt)
{
    extern __shared__ __align__(16) char smraw[];
    uint16_t* X   = (uint16_t*)smraw;               // [64][264]
    uint32_t* Wp  = (uint32_t*)(smraw + 33792);     // [32][136]
    uint16_t* Yd  = (uint16_t*)smraw;               // [64][136]
    uint32_t* Whp = (uint32_t*)(smraw + 17408);     // [64][24]
    float*    Yh  = (float*)(smraw + 23552);        // [64][20]
    __shared__ float sL[8];

    const int tid  = threadIdx.x;
    const int lane = tid & 31;
    const int w    = tid >> 5;
    const int base = blockIdx.x * TILE;
    const int g    = lane >> 2;
    const int t    = lane & 3;
    const uint32_t xb  = smem_u32(X);
    const uint32_t ydb = smem_u32(Yd);

    // ---- gather z / agg (both bf16 straight copies) ----
    #pragma unroll
    for (int it = 0; it < 8; it++) {
        const int idx = tid + it*256;
        const int r = idx >> 5, c4 = (idx & 31) << 2;
        const int n = base + r;
        uint16_t* row = X + r * 264;
        if (n < N_NODES) {
            *(uint2*)(row + c4) =
                __ldg((const uint2*)(g_zh + (size_t)n*FDIM + c4));
            *(uint2*)(row + FDIM + c4) =
                __ldg((const uint2*)(g_agg + (size_t)n*FDIM + c4));
        } else {
            *(uint2*)(row + c4)        = make_uint2(0u, 0u);
            *(uint2*)(row + FDIM + c4) = make_uint2(0u, 0u);
        }
    }
    __syncthreads();

    // ---- GEMM: yd = relu([z|agg] @ [Wself;Wagg]), K=256 (4 chunks x k64) ----
    float acc[2][4][4];
    #pragma unroll
    for (int i = 0; i < 2; i++)
        #pragma unroll
        for (int nt = 0; nt < 4; nt++)
            #pragma unroll
            for (int e = 0; e < 4; e++) acc[i][nt][e] = 0.f;

    const int mp  = w & 1;
    const int nqd = w >> 1;

    for (int ch = 0; ch < 4; ch++) {
        #pragma unroll
        for (int i = 0; i < 4; i++) {
            const int idx = tid + i*256;
            const int kp_l = idx >> 5, n4 = (idx & 31) << 2;
            *(uint4*)(Wp + kp_l*136 + n4) =
                __ldg((const uint4*)(g_pWd + (size_t)(ch*32 + kp_l)*FDIM + n4));
        }
        __syncthreads();
        for (int s = 0; s < 4; s++) {
            const int koff = s << 3;
            const int kidx = ch*64 + (s << 4);
            uint32_t a0[4], a1[4];
            const uint32_t addr = xb + (mp*32 + (lane & 15)) * 528
                                + ((kidx + ((lane >> 4) << 3)) << 1);
            ldsm_x4(a0[0], a0[1], a0[2], a0[3], addr);
            ldsm_x4(a1[0], a1[1], a1[2], a1[3], addr + 16*528);
            #pragma unroll
            for (int nt = 0; nt < 4; nt++) {
                const int ncol = nqd*32 + nt*8 + g;
                const uint32_t b0 = Wp[(koff + t)*136 + ncol];
                const uint32_t bv = Wp[(koff + 4 + t)*136 + ncol];
                mma_bf16(acc[0][nt], a0, b0, bv);
                mma_bf16(acc[1][nt], a1, b0, bv);
            }
        }
        __syncthreads();
    }

    // ---- yd = relu -> Yd bf16 ; stage heads weights ----
    #pragma unroll
    for (int i = 0; i < 2; i++)
        #pragma unroll
        for (int nt = 0; nt < 4; nt++) {
            const int r = mp*32 + i*16 + g;
            const int c = nqd*32 + nt*8 + 2*t;
            ((uint32_t*)Yd)[r*68 + (c>>1)] =
                bf2(fmaxf(acc[i][nt][0], 0.f), fmaxf(acc[i][nt][1], 0.f));
            ((uint32_t*)Yd)[(r+8)*68 + (c>>1)] =
                bf2(fmaxf(acc[i][nt][2], 0.f), fmaxf(acc[i][nt][3], 0.f));
        }
    #pragma unroll
    for (int i = 0; i < 4; i++) {
        const int idx = tid + i*256;
        const int kp = idx >> 4, nn = idx & 15;
        Whp[kp*24 + nn] = g_pWh[kp*16 + nn];
    }
    __syncthreads();

    // ---- heads mma: Yh[64][16] = yd @ [muW|lvW] + bias ----
    {
        const int mt = w & 3;
        const int nh = (w >> 2) & 1;
        float ah[4] = {0.f, 0.f, 0.f, 0.f};
        for (int s = 0; s < 8; s++) {
            const int koff = s << 3;
            uint32_t a[4];
            const uint32_t addr = ydb + (mt*16 + (lane & 15)) * 272
                                + (((s << 4) + ((lane >> 4) << 3)) << 1);
            ldsm_x4(a[0], a[1], a[2], a[3], addr);
            const uint32_t b0 = Whp[(koff + t)*24 + nh*8 + g];
            const uint32_t bv = Whp[(koff + 4 + t)*24 + nh*8 + g];
            mma_bf16(ah, a, b0, bv);
        }
        const int r = mt*16 + g;
        const int c = nh*8 + 2*t;
        const float* bp = nh ? lvb : mub;
        const float bx = __ldg(bp + 2*t), by = __ldg(bp + 2*t + 1);
        Yh[r*20 + c]         = ah[0] + bx;
        Yh[r*20 + c + 1]     = ah[1] + by;
        Yh[(r+8)*20 + c]     = ah[2] + bx;
        Yh[(r+8)*20 + c + 1] = ah[3] + by;
    }
    __syncthreads();

    // ---- loss: thread = (node r = tid>>2, k-pair kg = tid&3) ----
    {
        const int r  = tid >> 2;
        const int kg = tid & 3;
        const int n  = base + r;
        const bool valid = (n < N_NODES);
        float part = 0.f;
        int op = 0;
        if (valid) {
            op = __ldg(op_id + n);
            const float4 muA = *(const float4*)(Yh + r*20);
            const float4 muB = *(const float4*)(Yh + r*20 + 4);
            const float4 lvA = *(const float4*)(Yh + r*20 + 8);
            const float4 lvB = *(const float4*)(Yh + r*20 + 12);
            const float muv[8] = { muA.x, muA.y, muA.z, muA.w, muB.x, muB.y, muB.z, muB.w };
            const float lvv[8] = { lvA.x, lvA.y, lvA.z, lvA.w, lvB.x, lvB.y, lvB.z, lvB.w };
            const float* wrow = opw + (size_t)op * (2 * LDIM * LDIM);
            float mpA = 0.f, mpB = 0.f, lpA = 0.f, lpB = 0.f;
            #pragma unroll
            for (int l = 0; l < LDIM; l++) {
                const float2 wm = __ldg((const float2*)(wrow + l*2*LDIM + 2*kg));
                const float2 wl = __ldg((const float2*)(wrow + l*2*LDIM + LDIM + 2*kg));
                mpA += muv[l] * wm.x; mpB += muv[l] * wm.y;
                lpA += lvv[l] * wl.x; lpB += lvv[l] * wl.y;
            }
            const float2 lab = __ldg((const float2*)(lat + (size_t)n*LDIM + 2*kg));
            const float dA = mpA - lab.x, dB = mpB - lab.y;
            part = dA*dA / (2.f*expf(lpA) + 1e-7f) + 0.5f*lpA
                 + dB*dB / (2.f*expf(lpB) + 1e-7f) + 0.5f*lpB;
        }
        part += __shfl_xor_sync(0xffffffffu, part, 1);
        part += __shfl_xor_sync(0xffffffffu, part, 2);
        const float lossn = part * (1.f / LDIM);
        if (valid && kg == 0) {
            atomicAdd(op_loss + op, lossn);
            atomicAdd(op_cnt  + op, 1.f);
        }
        float wval = (valid && kg == 0) ? lossn : 0.f;
        wval += __shfl_xor_sync(0xffffffffu, wval, 4);
        wval += __shfl_xor_sync(0xffffffffu, wval, 8);
        wval += __shfl_xor_sync(0xffffffffu, wval, 16);
        if (lane == 0) sL[w] = wval;
    }
    __syncthreads();
    if (tid == 0) {
        double s = 0.0;
        #pragma unroll
        for (int i = 0; i < 8; i++) s += (double)sL[i];
        atomicAdd(&g_lat_sum, s);
    }
}

// ----------------------------------------------------------------------------
// Kernel 4: finalize
// ----------------------------------------------------------------------------
__global__ void fin_kernel(float* __restrict__ out)
{
    if (threadIdx.x == 0) {
        const double lat_loss = g_lat_sum / (double)N_NODES;
        const double kl = -0.5 * (g_kl_sum / ((double)N_NODES * (double)FDIM));
        out[0] = (float)(lat_loss + kl);
    }
}

// ----------------------------------------------------------------------------
extern "C" void kernel_launch(void* const* d_in, const int* in_sizes, int n_in,
                              void* d_out, int out_size)
{
    const int*   op_id = (const int*)  d_in[0];
    const int*   sv_id = (const int*)  d_in[1];
    const int*   st_id = (const int*)  d_in[2];
    const float* lat   = (const float*)d_in[3];
    const int*   esrc  = (const int*)  d_in[4];
    const int*   edst  = (const int*)  d_in[5];
    const float* eps   = (const float*)d_in[6];
    const float* opE   = (const float*)d_in[7];
    const float* svE   = (const float*)d_in[8];
    const float* stE   = (const float*)d_in[9];
    const float* W1    = (const float*)d_in[10];
    const float* b1    = (const float*)d_in[11];
    const float* W2    = (const float*)d_in[12];
    const float* b2    = (const float*)d_in[13];
    const float* Wself = (const float*)d_in[14];
    const float* Wagg  = (const float*)d_in[15];
    const float* muW   = (const float*)d_in[16];
    const float* mub   = (const float*)d_in[17];
    const float* lvW   = (const float*)d_in[18];
    const float* lvb   = (const float*)d_in[19];
    const float* opw   = (const float*)d_in[20];

    float* out     = (float*)d_out;
    float* op_loss = out + 1;
    float* op_cnt  = out + 1 + OPC;

    const int ENC_SMEM = 84992;
    const int DEC_SMEM = 51200;
    static bool attr_done = false;
    if (!attr_done) {
        cudaFuncSetAttribute(enc_kernel, cudaFuncAttributeMaxDynamicSharedMemorySize, ENC_SMEM);
        cudaFuncSetAttribute(dec_kernel, cudaFuncAttributeMaxDynamicSharedMemorySize, DEC_SMEM);
        attr_done = true;
    }

    const int n_tiles = (N_NODES + TILE - 1) / TILE;   // 7813

    prep_kernel<<<1073, 256>>>(W1, W2, Wself, Wagg, muW, lvW, opE, svE, stE);

    zero_kernel<<<31250, 256>>>(out);

    enc_kernel<<<n_tiles, 256, ENC_SMEM>>>(op_id, sv_id, st_id, lat, eps, b1, b2);

    scatter_kernel<<<15625, 256>>>(esrc, edst);

    dec_kernel<<<n_tiles, 256, DEC_SMEM>>>(op_id, lat, mub, lvb, opw,
                                           op_loss, op_cnt);

    fin_kernel<<<1, 32>>>(out);
}

// round 10
// speedup vs baseline: 14.7441x; 1.0466x over previous
#include <cuda_runtime.h>
#include <cstdint>

#define N_NODES 500000
#define N_EDGES 1000000
#define EMB 64
#define FDIM 128
#define LDIM 8
#define OPC 5000

#define TILE 64

// ---- scratch (no allocations allowed) ----
__device__ uint16_t g_zh [(size_t)N_NODES * FDIM];   // z in bf16 (128 MB)
__device__ uint16_t g_agg[(size_t)N_NODES * FDIM];   // agg in bf16 (128 MB)
__device__ double   g_kl_sum;
__device__ double   g_lat_sum;

// ---- pre-packed weights/embeddings (bf16) ----
__device__ uint32_t g_pW1[128 * 128];
__device__ uint32_t g_pW2[64 * 256];
__device__ uint32_t g_pWd[128 * 128];
__device__ uint32_t g_pWh[64 * 16];
__device__ uint16_t g_pOpE[OPC * EMB];
__device__ uint16_t g_pSvE[2000 * EMB];
__device__ uint16_t g_pStE[16 * EMB];

// ---- helpers ----
__device__ __forceinline__ uint32_t smem_u32(const void* p) {
    uint32_t a;
    asm("{ .reg .u64 t; cvta.to.shared.u64 t, %1; cvt.u32.u64 %0, t; }"
        : "=r"(a) : "l"(p));
    return a;
}
__device__ __forceinline__ void ldsm_x4(uint32_t& r0, uint32_t& r1,
                                        uint32_t& r2, uint32_t& r3,
                                        uint32_t addr) {
    asm volatile("ldmatrix.sync.aligned.m8n8.x4.shared.b16 {%0,%1,%2,%3}, [%4];"
                 : "=r"(r0), "=r"(r1), "=r"(r2), "=r"(r3) : "r"(addr));
}
__device__ __forceinline__ void mma_bf16(float* d, const uint32_t* a,
                                         uint32_t b0, uint32_t b1) {
    asm volatile("mma.sync.aligned.m16n8k16.row.col.f32.bf16.bf16.f32 "
                 "{%0,%1,%2,%3}, {%4,%5,%6,%7}, {%8,%9}, {%0,%1,%2,%3};"
                 : "+f"(d[0]), "+f"(d[1]), "+f"(d[2]), "+f"(d[3])
                 : "r"(a[0]), "r"(a[1]), "r"(a[2]), "r"(a[3]),
                   "r"(b0), "r"(b1));
}
__device__ __forceinline__ uint32_t bf2(float lo, float hi) {
    uint32_t d;
    asm("cvt.rn.satfinite.bf16x2.f32 %0, %1, %2;" : "=r"(d) : "f"(hi), "f"(lo));
    return d;
}
__device__ __forceinline__ void cpa16(uint32_t dst, const void* src) {
    asm volatile("cp.async.cg.shared.global [%0], [%1], 16;"
                 :: "r"(dst), "l"(src) : "memory");
}
#define CP_COMMIT() asm volatile("cp.async.commit_group;" ::: "memory")
#define CP_WAIT(n)  asm volatile("cp.async.wait_group %0;" :: "n"(n) : "memory")

// ----------------------------------------------------------------------------
// Kernel 0: zero agg + out + scalars, AND pack weights/embeddings (fused prep)
// ----------------------------------------------------------------------------
__global__ void zero_prep_kernel(float* __restrict__ out,
                                 const float* __restrict__ W1,
                                 const float* __restrict__ W2,
                                 const float* __restrict__ Wself,
                                 const float* __restrict__ Wagg,
                                 const float* __restrict__ muW,
                                 const float* __restrict__ lvW,
                                 const float* __restrict__ opE,
                                 const float* __restrict__ svE,
                                 const float* __restrict__ stE)
{
    const size_t i = (size_t)blockIdx.x * blockDim.x + threadIdx.x;
    const size_t tot8 = (size_t)N_NODES * FDIM / 8;
    if (i < tot8) ((uint4*)g_agg)[i] = make_uint4(0u, 0u, 0u, 0u);
    if (i < (size_t)(1 + 2*OPC)) out[i] = 0.f;
    if (i == 0) { g_kl_sum = 0.0; g_lat_sum = 0.0; }

    // ---- prep (first 274688 threads) ----
    if (i < 16384) {
        const int kp = (int)i >> 7, n = (int)i & 127;
        const int k0 = 2 * kp;
        const float lo = (k0 < 200)     ? __ldg(W1 + (size_t)k0 * FDIM + n)     : 0.f;
        const float hi = (k0 + 1 < 200) ? __ldg(W1 + (size_t)(k0+1) * FDIM + n) : 0.f;
        g_pW1[i] = bf2(lo, hi);
    } else if (i < 32768) {
        const int j = (int)i - 16384;
        const int kp = j >> 8, n = j & 255;
        const int k0 = 2 * kp;
        g_pW2[j] = bf2(__ldg(W2 + (size_t)k0 * 256 + n),
                       __ldg(W2 + (size_t)(k0+1) * 256 + n));
    } else if (i < 49152) {
        const int j = (int)i - 32768;
        const int kp = j >> 7, n = j & 127;
        const float* src = (kp < 64) ? Wself : Wagg;
        const int k0 = (kp < 64) ? 2*kp : 2*(kp - 64);
        g_pWd[j] = bf2(__ldg(src + (size_t)k0 * FDIM + n),
                       __ldg(src + (size_t)(k0+1) * FDIM + n));
    } else if (i < 50176) {
        const int j = (int)i - 49152;
        const int kp = j >> 4, nn = j & 15;
        float lo, hi;
        if (nn < 8) {
            lo = __ldg(muW + (size_t)(2*kp) * LDIM + nn);
            hi = __ldg(muW + (size_t)(2*kp+1) * LDIM + nn);
        } else {
            lo = __ldg(lvW + (size_t)(2*kp) * LDIM + nn - 8);
            hi = __ldg(lvW + (size_t)(2*kp+1) * LDIM + nn - 8);
        }
        g_pWh[j] = bf2(lo, hi);
    } else if (i < 210176) {
        const int j = (int)i - 50176;
        const float2 v = __ldg((const float2*)(opE + 2*(size_t)j));
        ((uint32_t*)g_pOpE)[j] = bf2(v.x, v.y);
    } else if (i < 274176) {
        const int j = (int)i - 210176;
        const float2 v = __ldg((const float2*)(svE + 2*(size_t)j));
        ((uint32_t*)g_pSvE)[j] = bf2(v.x, v.y);
    } else if (i < 274688) {
        const int j = (int)i - 274176;
        const float2 v = __ldg((const float2*)(stE + 2*(size_t)j));
        ((uint32_t*)g_pStE)[j] = bf2(v.x, v.y);
    }
}

// ----------------------------------------------------------------------------
// Kernel 1: encoder (bf16 mma), 64-node tile, 256 threads, cp.async pipeline
// ----------------------------------------------------------------------------
extern "C" __global__ void __launch_bounds__(256, 2)
enc_kernel(const int*   __restrict__ op_id,
           const int*   __restrict__ sv_id,
           const int*   __restrict__ st_id,
           const float* __restrict__ lat,
           const float* __restrict__ eps,
           const float* __restrict__ b1,
           const float* __restrict__ b2)
{
    extern __shared__ __align__(16) char smraw[];
    uint16_t* X1  = (uint16_t*)smraw;               // [64][216]
    uint16_t* Hs  = (uint16_t*)(smraw + 67584);     // [64][136]
    uint32_t* Wp2 = (uint32_t*)smraw;               // [64][264]
    __shared__ float skl[8];

    const int tid  = threadIdx.x;
    const int lane = tid & 31;
    const int w    = tid >> 5;
    const int base = blockIdx.x * TILE;
    const int g    = lane >> 2;
    const int t    = lane & 3;
    const uint32_t x1b  = smem_u32(X1);
    const uint32_t hsb  = smem_u32(Hs);
    const uint32_t wb[2] = { smem_u32(smraw + 27648), smem_u32(smraw + 45056) };

    auto stage1 = [&](int ch, uint32_t wbuf) {
        #pragma unroll
        for (int i = 0; i < 4; i++) {
            const int idx = tid + i*256;
            const int kp_l = idx >> 5, n4 = (idx & 31) << 2;
            cpa16(wbuf + (kp_l*136 + n4)*4,
                  g_pW1 + (size_t)(ch*32 + kp_l)*FDIM + n4);
        }
    };

    // ---- prologue: prefetch chunk 0, gather feats, prefetch chunk 1 ----
    stage1(0, wb[0]);
    CP_COMMIT();
    {
        const int r = tid >> 2, q = tid & 3;
        const int n = base + r;
        uint16_t* row = X1 + r * 216;
        if (n < N_NODES) {
            const int op = op_id[n], sv = sv_id[n], st = st_id[n];
            const uint4* so = (const uint4*)(g_pOpE + (size_t)op*EMB + q*16);
            const uint4* ss = (const uint4*)(g_pSvE + (size_t)sv*EMB + q*16);
            const uint4* st4 = (const uint4*)(g_pStE + (size_t)st*EMB + q*16);
            *(uint4*)(row + q*16)          = __ldg(so);
            *(uint4*)(row + q*16 + 8)      = __ldg(so + 1);
            *(uint4*)(row + 64 + q*16)     = __ldg(ss);
            *(uint4*)(row + 64 + q*16 + 8) = __ldg(ss + 1);
            *(uint4*)(row + 128 + q*16)    = __ldg(st4);
            *(uint4*)(row + 128 + q*16 + 8)= __ldg(st4 + 1);
            if (q == 0) {
                const float4 v0 = __ldg((const float4*)(lat + (size_t)n*LDIM));
                const float4 v1 = __ldg((const float4*)(lat + (size_t)n*LDIM + 4));
                *(uint4*)(row + 192) = make_uint4(bf2(v0.x,v0.y), bf2(v0.z,v0.w),
                                                  bf2(v1.x,v1.y), bf2(v1.z,v1.w));
            } else if (q == 1) {
                *(uint4*)(row + 200) = make_uint4(0u,0u,0u,0u);
            }
        } else {
            const uint4 z4 = make_uint4(0u,0u,0u,0u);
            *(uint4*)(row + q*16)           = z4;
            *(uint4*)(row + q*16 + 8)       = z4;
            *(uint4*)(row + 64 + q*16)      = z4;
            *(uint4*)(row + 64 + q*16 + 8)  = z4;
            *(uint4*)(row + 128 + q*16)     = z4;
            *(uint4*)(row + 128 + q*16 + 8) = z4;
            if (q == 0)      *(uint4*)(row + 192) = z4;
            else if (q == 1) *(uint4*)(row + 200) = z4;
        }
    }
    stage1(1, wb[1]);
    CP_COMMIT();
    CP_WAIT(1);
    __syncthreads();

    // ---- GEMM1: h = relu(X1 @ W1 + b1), K=208, double-buffered ----
    float acc1[2][4][4];
    #pragma unroll
    for (int i = 0; i < 2; i++)
        #pragma unroll
        for (int nt = 0; nt < 4; nt++)
            #pragma unroll
            for (int j = 0; j < 4; j++) acc1[i][nt][j] = 0.f;

    const int mp  = w & 1;
    const int nq1 = w >> 1;

    for (int ch = 0; ch < 4; ch++) {
        const uint32_t* Wc = (const uint32_t*)(smraw + ((ch & 1) ? 45056 : 27648));
        const int nsteps = (ch < 3) ? 4 : 1;
        for (int s = 0; s < nsteps; s++) {
            const int koff = s << 3;
            const int kidx = ch*64 + (s << 4);
            uint32_t a0[4], a1[4];
            const uint32_t addr = x1b + (mp*32 + (lane & 15)) * 432
                                + ((kidx + ((lane >> 4) << 3)) << 1);
            ldsm_x4(a0[0], a0[1], a0[2], a0[3], addr);
            ldsm_x4(a1[0], a1[1], a1[2], a1[3], addr + 16*432);
            #pragma unroll
            for (int nt = 0; nt < 4; nt++) {
                const int ncol = nq1*32 + nt*8 + g;
                const uint32_t b0 = Wc[(koff + t)*136 + ncol];
                const uint32_t bv = Wc[(koff + 4 + t)*136 + ncol];
                mma_bf16(acc1[0][nt], a0, b0, bv);
                mma_bf16(acc1[1][nt], a1, b0, bv);
            }
        }
        if (ch < 3) {
            __syncthreads();
            if (ch + 2 < 4) {
                stage1(ch + 2, wb[ch & 1]);
                CP_COMMIT();
                CP_WAIT(1);
            } else {
                CP_WAIT(0);
            }
            __syncthreads();
        }
    }
    __syncthreads();

    // ---- prefetch ALL of W2 (aliases X1 region) ----
    #pragma unroll
    for (int i = 0; i < 16; i++) {
        const int idx = tid + i*256;
        const int kp_l = idx >> 6, n4 = (idx & 63) << 2;
        cpa16(smem_u32(Wp2 + kp_l*264 + n4),
              g_pW2 + (size_t)kp_l*256 + n4);
    }
    CP_COMMIT();

    // ---- h = relu(+bias) -> Hs bf16 (overlaps W2 prefetch) ----
    #pragma unroll
    for (int i = 0; i < 2; i++)
        #pragma unroll
        for (int nt = 0; nt < 4; nt++) {
            const int r = mp*32 + i*16 + g;
            const int c = nq1*32 + nt*8 + 2*t;
            const float bA = __ldg(b1 + c), bB = __ldg(b1 + c + 1);
            ((uint32_t*)Hs)[r*68 + (c>>1)] =
                bf2(fmaxf(acc1[i][nt][0] + bA, 0.f), fmaxf(acc1[i][nt][1] + bB, 0.f));
            ((uint32_t*)Hs)[(r+8)*68 + (c>>1)] =
                bf2(fmaxf(acc1[i][nt][2] + bA, 0.f), fmaxf(acc1[i][nt][3] + bB, 0.f));
        }
    CP_WAIT(0);
    __syncthreads();

    // ---- GEMM2: y = h @ W2, K=128 (sync-free), paired mu/lv per warp ----
    float acc2[4][4][4];
    #pragma unroll
    for (int mi = 0; mi < 4; mi++)
        #pragma unroll
        for (int j = 0; j < 4; j++)
            #pragma unroll
            for (int e = 0; e < 4; e++) acc2[mi][j][e] = 0.f;

    for (int s = 0; s < 8; s++) {
        const int koff = s << 3;
        const int kidx = s << 4;
        uint32_t a[4][4];
        #pragma unroll
        for (int mi = 0; mi < 4; mi++) {
            const uint32_t addr = hsb + (mi*16 + (lane & 15)) * 272
                                + ((kidx + ((lane >> 4) << 3)) << 1);
            ldsm_x4(a[mi][0], a[mi][1], a[mi][2], a[mi][3], addr);
        }
        #pragma unroll
        for (int j = 0; j < 4; j++) {
            const int cb = (j < 2) ? (w*16 + 8*j) : (FDIM + w*16 + 8*(j-2));
            const uint32_t b0 = Wp2[(koff + t)*264 + cb + g];
            const uint32_t bv = Wp2[(koff + 4 + t)*264 + cb + g];
            #pragma unroll
            for (int mi = 0; mi < 4; mi++)
                mma_bf16(acc2[mi][j], a[mi], b0, bv);
        }
    }

    // ---- epilogue: z = mu + exp(0.5*tanh(lv))*eps -> g_zh, KL ----
    float klw = 0.f;
    #pragma unroll
    for (int j = 0; j < 2; j++) {
        const int c = w*16 + 8*j + 2*t;
        const float bmx = __ldg(b2 + c),        bmy = __ldg(b2 + c + 1);
        const float blx = __ldg(b2 + FDIM + c), bly = __ldg(b2 + FDIM + c + 1);
        #pragma unroll
        for (int mi = 0; mi < 4; mi++) {
            const float* fm = acc2[mi][j];
            const float* fl = acc2[mi][j+2];
            #pragma unroll
            for (int half = 0; half < 2; half++) {
                const int r = mi*16 + g + half*8;
                const int n = base + r;
                if (n < N_NODES) {
                    const float mux = fm[2*half]   + bmx;
                    const float muy = fm[2*half+1] + bmy;
                    const float lvx = tanhf(fl[2*half]   + blx);
                    const float lvy = tanhf(fl[2*half+1] + bly);
                    const float2 e = __ldg((const float2*)(eps + (size_t)n*FDIM + c));
                    const float zx = mux + expf(0.5f*lvx) * e.x;
                    const float zy = muy + expf(0.5f*lvy) * e.y;
                    ((uint32_t*)g_zh)[(size_t)n*64 + (c>>1)] = bf2(zx, zy);
                    klw += lvx + 1.f - expf(lvx) - mux*mux;
                    klw += lvy + 1.f - expf(lvy) - muy*muy;
                }
            }
        }
    }
    #pragma unroll
    for (int o = 16; o; o >>= 1) klw += __shfl_xor_sync(0xffffffffu, klw, o);
    if (lane == 0) skl[w] = klw;
    __syncthreads();
    if (tid == 0) {
        double s = 0.0;
        #pragma unroll
        for (int i = 0; i < 8; i++) s += (double)skl[i];
        atomicAdd(&g_kl_sum, s);
    }
}

// ----------------------------------------------------------------------------
// Kernel 2: edge scatter-add — 8 edges/warp, 16B slices, MLP-4 unroll
// ----------------------------------------------------------------------------
__global__ void scatter_kernel(const int* __restrict__ esrc,
                               const int* __restrict__ edst)
{
    const int warp = (blockIdx.x * blockDim.x + threadIdx.x) >> 5;
    const int lane = threadIdx.x & 31;
    const int sub  = lane >> 4;
    const int off  = lane & 15;
    const int ebase = warp * 8 + sub;

    int   s[4], d[4];
    uint4 v[4];
    #pragma unroll
    for (int i = 0; i < 4; i++) {
        const int e = ebase + 2*i;
        s[i] = (e < N_EDGES) ? __ldg(esrc + e) : 0;
        d[i] = (e < N_EDGES) ? __ldg(edst + e) : 0;
    }
    #pragma unroll
    for (int i = 0; i < 4; i++)
        v[i] = __ldg((const uint4*)(g_zh + (size_t)s[i] * FDIM) + off);
    #pragma unroll
    for (int i = 0; i < 4; i++) {
        const int e = ebase + 2*i;
        if (e < N_EDGES) {
            uint32_t* p = (uint32_t*)(g_agg + (size_t)d[i] * FDIM) + 4*off;
            asm volatile("red.global.add.noftz.v4.bf16x2 [%0], {%1, %2, %3, %4};"
                         :: "l"(p), "r"(v[i].x), "r"(v[i].y), "r"(v[i].z), "r"(v[i].w)
                         : "memory");
        }
    }
}

// ----------------------------------------------------------------------------
// Kernel 3: decoder (bf16 mma, cp.async pipelined) + heads mma + loss
//   smem (68.6 KB): X bf16[64][264] @0 | WpA u32[32][136] @33792 | WpB @51200
//   post-GEMM: Yd bf16[64][136] @0 | Whp u32[64][24] @17408 | Yh f32[64][20] @23552
// ----------------------------------------------------------------------------
extern "C" __global__ void __launch_bounds__(256, 3)
dec_kernel(const int*   __restrict__ op_id,
           const float* __restrict__ lat,
           const float* __restrict__ mub,
           const float* __restrict__ lvb,
           const float* __restrict__ opw,
           float* __restrict__ op_loss,
           float* __restrict__ op_cnt)
{
    extern __shared__ __align__(16) char smraw[];
    uint16_t* X   = (uint16_t*)smraw;               // [64][264]
    uint16_t* Yd  = (uint16_t*)smraw;               // [64][136] (post-GEMM)
    uint32_t* Whp = (uint32_t*)(smraw + 17408);     // [64][24]
    float*    Yh  = (float*)(smraw + 23552);        // [64][20]
    __shared__ float sL[8];

    const int tid  = threadIdx.x;
    const int lane = tid & 31;
    const int w    = tid >> 5;
    const int base = blockIdx.x * TILE;
    const int g    = lane >> 2;
    const int t    = lane & 3;
    const uint32_t xb  = smem_u32(X);
    const uint32_t ydb = smem_u32(Yd);
    const uint32_t wb[2] = { smem_u32(smraw + 33792), smem_u32(smraw + 51200) };

    auto staged = [&](int ch, uint32_t wbuf) {
        #pragma unroll
        for (int i = 0; i < 4; i++) {
            const int idx = tid + i*256;
            const int kp_l = idx >> 5, n4 = (idx & 31) << 2;
            cpa16(wbuf + (kp_l*136 + n4)*4,
                  g_pWd + (size_t)(ch*32 + kp_l)*FDIM + n4);
        }
    };

    // ---- prologue: chunk0 || X gather (cp.async, rows contiguous) || chunk1 ----
    staged(0, wb[0]);
    CP_COMMIT();
    #pragma unroll
    for (int it = 0; it < 8; it++) {
        const int u = tid + it*256;               // 2048 = 64 rows x 32 units
        const int r = u >> 5, half = (u >> 4) & 1, seg = u & 15;
        const int n = base + r;
        const uint32_t dst = xb + (r*264 + half*128 + seg*8) * 2;
        if (n < N_NODES) {
            const uint16_t* src = (half ? g_agg : g_zh) + (size_t)n*FDIM + seg*8;
            cpa16(dst, src);
        } else {
            *(uint4*)((char*)X + (dst - xb)) = make_uint4(0u,0u,0u,0u);
        }
    }
    CP_COMMIT();
    staged(1, wb[1]);
    CP_COMMIT();
    CP_WAIT(1);            // chunk0 + X resident (chunk1 in flight)
    __syncthreads();

    // ---- GEMM: yd = relu([z|agg] @ [Wself;Wagg]), K=256, double-buffered ----
    float acc[2][4][4];
    #pragma unroll
    for (int i = 0; i < 2; i++)
        #pragma unroll
        for (int nt = 0; nt < 4; nt++)
            #pragma unroll
            for (int e = 0; e < 4; e++) acc[i][nt][e] = 0.f;

    const int mp  = w & 1;
    const int nqd = w >> 1;

    for (int ch = 0; ch < 4; ch++) {
        const uint32_t* Wc = (const uint32_t*)(smraw + ((ch & 1) ? 51200 : 33792));
        for (int s = 0; s < 4; s++) {
            const int koff = s << 3;
            const int kidx = ch*64 + (s << 4);
            uint32_t a0[4], a1[4];
            const uint32_t addr = xb + (mp*32 + (lane & 15)) * 528
                                + ((kidx + ((lane >> 4) << 3)) << 1);
            ldsm_x4(a0[0], a0[1], a0[2], a0[3], addr);
            ldsm_x4(a1[0], a1[1], a1[2], a1[3], addr + 16*528);
            #pragma unroll
            for (int nt = 0; nt < 4; nt++) {
                const int ncol = nqd*32 + nt*8 + g;
                const uint32_t b0 = Wc[(koff + t)*136 + ncol];
                const uint32_t bv = Wc[(koff + 4 + t)*136 + ncol];
                mma_bf16(acc[0][nt], a0, b0, bv);
                mma_bf16(acc[1][nt], a1, b0, bv);
            }
        }
        if (ch < 3) {
            __syncthreads();
            if (ch + 2 < 4) {
                staged(ch + 2, wb[ch & 1]);
                CP_COMMIT();
                CP_WAIT(1);
            } else {
                CP_WAIT(0);
            }
            __syncthreads();
        }
    }
    __syncthreads();   // done reading X before Yd overwrites it

    // ---- yd = relu -> Yd bf16 ; stage heads weights ----
    #pragma unroll
    for (int i = 0; i < 2; i++)
        #pragma unroll
        for (int nt = 0; nt < 4; nt++) {
            const int r = mp*32 + i*16 + g;
            const int c = nqd*32 + nt*8 + 2*t;
            ((uint32_t*)Yd)[r*68 + (c>>1)] =
                bf2(fmaxf(acc[i][nt][0], 0.f), fmaxf(acc[i][nt][1], 0.f));
            ((uint32_t*)Yd)[(r+8)*68 + (c>>1)] =
                bf2(fmaxf(acc[i][nt][2], 0.f), fmaxf(acc[i][nt][3], 0.f));
        }
    #pragma unroll
    for (int i = 0; i < 4; i++) {
        const int idx = tid + i*256;
        const int kp = idx >> 4, nn = idx & 15;
        Whp[kp*24 + nn] = g_pWh[kp*16 + nn];
    }
    __syncthreads();

    // ---- heads mma: Yh[64][16] = yd @ [muW|lvW] + bias ----
    {
        const int mt = w & 3;
        const int nh = (w >> 2) & 1;
        float ah[4] = {0.f, 0.f, 0.f, 0.f};
        for (int s = 0; s < 8; s++) {
            const int koff = s << 3;
            uint32_t a[4];
            const uint32_t addr = ydb + (mt*16 + (lane & 15)) * 272
                                + (((s << 4) + ((lane >> 4) << 3)) << 1);
            ldsm_x4(a[0], a[1], a[2], a[3], addr);
            const uint32_t b0 = Whp[(koff + t)*24 + nh*8 + g];
            const uint32_t bv = Whp[(koff + 4 + t)*24 + nh*8 + g];
            mma_bf16(ah, a, b0, bv);
        }
        const int r = mt*16 + g;
        const int c = nh*8 + 2*t;
        const float* bp = nh ? lvb : mub;
        const float bx = __ldg(bp + 2*t), by = __ldg(bp + 2*t + 1);
        Yh[r*20 + c]         = ah[0] + bx;
        Yh[r*20 + c + 1]     = ah[1] + by;
        Yh[(r+8)*20 + c]     = ah[2] + bx;
        Yh[(r+8)*20 + c + 1] = ah[3] + by;
    }
    __syncthreads();

    // ---- loss: thread = (node r = tid>>2, k-pair kg = tid&3) ----
    {
        const int r  = tid >> 2;
        const int kg = tid & 3;
        const int n  = base + r;
        const bool valid = (n < N_NODES);
        float part = 0.f;
        int op = 0;
        if (valid) {
            op = __ldg(op_id + n);
            const float4 muA = *(const float4*)(Yh + r*20);
            const float4 muB = *(const float4*)(Yh + r*20 + 4);
            const float4 lvA = *(const float4*)(Yh + r*20 + 8);
            const float4 lvB = *(const float4*)(Yh + r*20 + 12);
            const float muv[8] = { muA.x, muA.y, muA.z, muA.w, muB.x, muB.y, muB.z, muB.w };
            const float lvv[8] = { lvA.x, lvA.y, lvA.z, lvA.w, lvB.x, lvB.y, lvB.z, lvB.w };
            const float* wrow = opw + (size_t)op * (2 * LDIM * LDIM);
            float mpA = 0.f, mpB = 0.f, lpA = 0.f, lpB = 0.f;
            #pragma unroll
            for (int l = 0; l < LDIM; l++) {
                const float2 wm = __ldg((const float2*)(wrow + l*2*LDIM + 2*kg));
                const float2 wl = __ldg((const float2*)(wrow + l*2*LDIM + LDIM + 2*kg));
                mpA += muv[l] * wm.x; mpB += muv[l] * wm.y;
                lpA += lvv[l] * wl.x; lpB += lvv[l] * wl.y;
            }
            const float2 lab = __ldg((const float2*)(lat + (size_t)n*LDIM + 2*kg));
            const float dA = mpA - lab.x, dB = mpB - lab.y;
            part = dA*dA / (2.f*expf(lpA) + 1e-7f) + 0.5f*lpA
                 + dB*dB / (2.f*expf(lpB) + 1e-7f) + 0.5f*lpB;
        }
        part += __shfl_xor_sync(0xffffffffu, part, 1);
        part += __shfl_xor_sync(0xffffffffu, part, 2);
        const float lossn = part * (1.f / LDIM);
        if (valid && kg == 0) {
            atomicAdd(op_loss + op, lossn);
            atomicAdd(op_cnt  + op, 1.f);
        }
        float wval = (valid && kg == 0) ? lossn : 0.f;
        wval += __shfl_xor_sync(0xffffffffu, wval, 4);
        wval += __shfl_xor_sync(0xffffffffu, wval, 8);
        wval += __shfl_xor_sync(0xffffffffu, wval, 16);
        if (lane == 0) sL[w] = wval;
    }
    __syncthreads();
    if (tid == 0) {
        double s = 0.0;
        #pragma unroll
        for (int i = 0; i < 8; i++) s += (double)sL[i];
        atomicAdd(&g_lat_sum, s);
    }
}

// ----------------------------------------------------------------------------
// Kernel 4: finalize
// ----------------------------------------------------------------------------
__global__ void fin_kernel(float* __restrict__ out)
{
    if (threadIdx.x == 0) {
        const double lat_loss = g_lat_sum / (double)N_NODES;
        const double kl = -0.5 * (g_kl_sum / ((double)N_NODES * (double)FDIM));
        out[0] = (float)(lat_loss + kl);
    }
}

// ----------------------------------------------------------------------------
extern "C" void kernel_launch(void* const* d_in, const int* in_sizes, int n_in,
                              void* d_out, int out_size)
{
    const int*   op_id = (const int*)  d_in[0];
    const int*   sv_id = (const int*)  d_in[1];
    const int*   st_id = (const int*)  d_in[2];
    const float* lat   = (const float*)d_in[3];
    const int*   esrc  = (const int*)  d_in[4];
    const int*   edst  = (const int*)  d_in[5];
    const float* eps   = (const float*)d_in[6];
    const float* opE   = (const float*)d_in[7];
    const float* svE   = (const float*)d_in[8];
    const float* stE   = (const float*)d_in[9];
    const float* W1    = (const float*)d_in[10];
    const float* b1    = (const float*)d_in[11];
    const float* W2    = (const float*)d_in[12];
    const float* b2    = (const float*)d_in[13];
    const float* Wself = (const float*)d_in[14];
    const float* Wagg  = (const float*)d_in[15];
    const float* muW   = (const float*)d_in[16];
    const float* mub   = (const float*)d_in[17];
    const float* lvW   = (const float*)d_in[18];
    const float* lvb   = (const float*)d_in[19];
    const float* opw   = (const float*)d_in[20];

    float* out     = (float*)d_out;
    float* op_loss = out + 1;
    float* op_cnt  = out + 1 + OPC;

    const int ENC_SMEM = 84992;
    const int DEC_SMEM = 68608;
    static bool attr_done = false;
    if (!attr_done) {
        cudaFuncSetAttribute(enc_kernel, cudaFuncAttributeMaxDynamicSharedMemorySize, ENC_SMEM);
        cudaFuncSetAttribute(dec_kernel, cudaFuncAttributeMaxDynamicSharedMemorySize, DEC_SMEM);
        attr_done = true;
    }

    const int n_tiles = (N_NODES + TILE - 1) / TILE;   // 7813

    zero_prep_kernel<<<31250, 256>>>(out, W1, W2, Wself, Wagg, muW, lvW,
                                     opE, svE, stE);

    enc_kernel<<<n_tiles, 256, ENC_SMEM>>>(op_id, sv_id, st_id, lat, eps, b1, b2);

    scatter_kernel<<<15625, 256>>>(esrc, edst);

    dec_kernel<<<n_tiles, 256, DEC_SMEM>>>(op_id, lat, mub, lvb, opw,
                                           op_loss, op_cnt);

    fin_kernel<<<1, 32>>>(out);
}